// round 1
// baseline (speedup 1.0000x reference)
#include <cuda_runtime.h>
#include <math.h>

#define BATCH 4
#define CCH 256
#define HH 128
#define WW 128
#define HWP 16384
#define CHW 4194304
#define TOKB 4194304

// ---------------- scratch (static device allocations) ----------------
__device__ float g_qt[BATCH * TOKB];
__device__ float g_kt[BATCH * TOKB];
__device__ float g_vt[BATCH * TOKB];
__device__ float g_S[67108864];        // scores / probs, [b][split][n][m]
__device__ float g_attn[BATCH * TOKB]; // attention output, image layout
__device__ float g_mean[CCH];
__device__ float g_rstd[CCH];

// ---------------- projection: C = W(256x256) @ in(256xHW) + bias, scatter to token layout ----------------
__global__ void k_proj(const float* __restrict__ Wt, const float* __restrict__ bias,
                       const float* __restrict__ inp, float* __restrict__ tok)
{
    __shared__ float As[16][65];
    __shared__ float Bs[16][68];
    int b = blockIdx.z;
    int o0 = blockIdx.y * 64, p0 = blockIdx.x * 64;
    const float* Bm = inp + (size_t)b * CHW;
    int tid = threadIdx.x;
    int lr = tid >> 2, lc = (tid & 3) << 2;     // A loader: row, k-col4
    int kr = tid >> 4, cc = (tid & 15) << 2;    // B loader: k-row, col4
    int ty = tid >> 4, tx = tid & 15;
    float acc[4][4] = {};
    for (int k0 = 0; k0 < 256; k0 += 16) {
        float4 a  = *(const float4*)(Wt + (o0 + lr) * 256 + k0 + lc);
        float4 bv = *(const float4*)(Bm + (size_t)(k0 + kr) * HWP + p0 + cc);
        __syncthreads();
        As[lc + 0][lr] = a.x; As[lc + 1][lr] = a.y; As[lc + 2][lr] = a.z; As[lc + 3][lr] = a.w;
        *(float4*)&Bs[kr][cc] = bv;
        __syncthreads();
#pragma unroll
        for (int k = 0; k < 16; k++) {
            float av[4], bb[4];
#pragma unroll
            for (int i = 0; i < 4; i++) av[i] = As[k][ty * 4 + i];
#pragma unroll
            for (int j = 0; j < 4; j++) bb[j] = Bs[k][tx * 4 + j];
#pragma unroll
            for (int i = 0; i < 4; i++)
#pragma unroll
                for (int j = 0; j < 4; j++)
                    acc[i][j] += av[i] * bb[j];
        }
    }
    size_t bbase = (size_t)b * TOKB;
#pragma unroll
    for (int i = 0; i < 4; i++) {
        int o = o0 + ty * 4 + i;
        float bia = __ldg(&bias[o]);
        int scale = o >> 6, cl = o & 63, l = scale + 1;
        int soff = scale << 20;
        int dsz = 64 << (2 * l);
#pragma unroll
        for (int j = 0; j < 4; j++) {
            int p = p0 + tx * 4 + j;
            int yy = p >> 7, xx = p & 127;
            int wy = yy >> l, py = yy & ((1 << l) - 1);
            int wx = xx >> l, px = xx & ((1 << l) - 1);
            int n = (wy << (7 - l)) | wx;
            int d = (cl << (2 * l)) | (py << l) | px;
            tok[bbase + soff + (size_t)n * dsz + d] = acc[i][j] + bia;
        }
    }
}

// ---------------- scores: S[z][n][m] = Q[n,:] . K[m,:] over k-chunk (split-K) ----------------
__global__ void k_scores(const float* __restrict__ Qt, const float* __restrict__ Kt,
                         float* __restrict__ S, int nTok, int d, int split, int kper, int soff)
{
    __shared__ float As[16][65];
    __shared__ float Bs[16][65];
    int z = blockIdx.z;
    int b = z / split, sp = z - b * split;
    const float* A  = Qt + (size_t)b * TOKB + soff;
    const float* Bm = Kt + (size_t)b * TOKB + soff;
    int m0 = blockIdx.x * 64, n0 = blockIdx.y * 64;
    int k0base = sp * kper;
    int tid = threadIdx.x;
    int lr = tid >> 2, lc = (tid & 3) << 2;
    int ty = tid >> 4, tx = tid & 15;
    float acc[4][4] = {};
    const float* Ap = A  + (size_t)(n0 + lr) * d + k0base + lc;
    const float* Bp = Bm + (size_t)(m0 + lr) * d + k0base + lc;
    for (int kk = 0; kk < kper; kk += 16) {
        float4 a  = *(const float4*)(Ap + kk);
        float4 bv = *(const float4*)(Bp + kk);
        __syncthreads();
        As[lc + 0][lr] = a.x;  As[lc + 1][lr] = a.y;  As[lc + 2][lr] = a.z;  As[lc + 3][lr] = a.w;
        Bs[lc + 0][lr] = bv.x; Bs[lc + 1][lr] = bv.y; Bs[lc + 2][lr] = bv.z; Bs[lc + 3][lr] = bv.w;
        __syncthreads();
#pragma unroll
        for (int k = 0; k < 16; k++) {
            float av[4], bb[4];
#pragma unroll
            for (int i = 0; i < 4; i++) av[i] = As[k][ty * 4 + i];
#pragma unroll
            for (int j = 0; j < 4; j++) bb[j] = Bs[k][tx * 4 + j];
#pragma unroll
            for (int i = 0; i < 4; i++)
#pragma unroll
                for (int j = 0; j < 4; j++)
                    acc[i][j] += av[i] * bb[j];
        }
    }
    size_t cb = (size_t)z * nTok * nTok;
#pragma unroll
    for (int i = 0; i < 4; i++)
#pragma unroll
        for (int j = 0; j < 4; j++)
            S[cb + (size_t)(n0 + ty * 4 + i) * nTok + m0 + tx * 4 + j] = acc[i][j];
}

// ---------------- softmax over rows, fusing split-K reduction, writes P at split 0 region ----------------
__global__ void k_softmax(float* __restrict__ S, int nTok, int split, float alpha)
{
    __shared__ float rowb[4096];
    __shared__ float red[256];
    int row = blockIdx.x;
    size_t bb = (size_t)blockIdx.y * split * nTok * nTok;
    int tid = threadIdx.x;
    float mx = -1e30f;
    for (int j = tid; j < nTok; j += 256) {
        float s = 0.f;
        for (int sp = 0; sp < split; sp++)
            s += S[bb + ((size_t)sp * nTok + row) * nTok + j];
        s *= alpha;
        rowb[j] = s;
        mx = fmaxf(mx, s);
    }
    red[tid] = mx; __syncthreads();
    for (int st = 128; st; st >>= 1) { if (tid < st) red[tid] = fmaxf(red[tid], red[tid + st]); __syncthreads(); }
    mx = red[0]; __syncthreads();
    float sum = 0.f;
    for (int j = tid; j < nTok; j += 256) {
        float e = __expf(rowb[j] - mx);
        rowb[j] = e; sum += e;
    }
    red[tid] = sum; __syncthreads();
    for (int st = 128; st; st >>= 1) { if (tid < st) red[tid] += red[tid + st]; __syncthreads(); }
    float inv = 1.0f / red[0];
    size_t ob = bb + (size_t)row * nTok;
    for (int j = tid; j < nTok; j += 256)
        S[ob + j] = rowb[j] * inv;
}

// ---------------- out: O = P(n x n) @ V(n x d), scatter to image layout ----------------
__global__ void k_out(const float* __restrict__ P, const float* __restrict__ Vt,
                      float* __restrict__ Oimg, int nTok, int d, int split, int scale, int l, int soff)
{
    __shared__ float As[16][65];
    __shared__ float Bs[16][68];
    int b = blockIdx.z;
    const float* A  = P  + (size_t)b * split * nTok * nTok;
    const float* Bm = Vt + (size_t)b * TOKB + soff;
    int d0 = blockIdx.x * 64, n0 = blockIdx.y * 64;
    int tid = threadIdx.x;
    int lr = tid >> 2, lc = (tid & 3) << 2;
    int kr = tid >> 4, cc = (tid & 15) << 2;
    int ty = tid >> 4, tx = tid & 15;
    float acc[4][4] = {};
    for (int k0 = 0; k0 < nTok; k0 += 16) {
        float4 a  = *(const float4*)(A  + (size_t)(n0 + lr) * nTok + k0 + lc);
        float4 bv = *(const float4*)(Bm + (size_t)(k0 + kr) * d + d0 + cc);
        __syncthreads();
        As[lc + 0][lr] = a.x; As[lc + 1][lr] = a.y; As[lc + 2][lr] = a.z; As[lc + 3][lr] = a.w;
        *(float4*)&Bs[kr][cc] = bv;
        __syncthreads();
#pragma unroll
        for (int k = 0; k < 16; k++) {
            float av[4], bb[4];
#pragma unroll
            for (int i = 0; i < 4; i++) av[i] = As[k][ty * 4 + i];
#pragma unroll
            for (int j = 0; j < 4; j++) bb[j] = Bs[k][tx * 4 + j];
#pragma unroll
            for (int i = 0; i < 4; i++)
#pragma unroll
                for (int j = 0; j < 4; j++)
                    acc[i][j] += av[i] * bb[j];
        }
    }
    int owlog = 7 - l;
#pragma unroll
    for (int i = 0; i < 4; i++) {
        int row = n0 + ty * 4 + i;
        int wy = row >> owlog, wx = row & ((1 << owlog) - 1);
#pragma unroll
        for (int j = 0; j < 4; j++) {
            int col = d0 + tx * 4 + j;
            int cl = col >> (2 * l);
            int r = col & ((1 << (2 * l)) - 1);
            int py = r >> l, px = r & ((1 << l) - 1);
            int y = (wy << l) | py, x = (wx << l) | px;
            int c = (scale << 6) | cl;
            Oimg[(((size_t)b * 256 + c) << 14) + (y << 7) + x] = acc[i][j];
        }
    }
}

// ---------------- conv3x3 SAME: 16x16 pixel tile, 16 output channels / block ----------------
__global__ void k_conv(const float* __restrict__ img, const float* __restrict__ Wo,
                       const float* __restrict__ bo, float* __restrict__ z)
{
    __shared__ float sIn[18 * 18];
    __shared__ __align__(16) float sW[9][16];
    int b = blockIdx.z;
    int o0 = blockIdx.y * 16;
    int t = blockIdx.x;
    int gy0 = (t >> 3) * 16, gx0 = (t & 7) * 16;
    int tid = threadIdx.x;
    int py = tid >> 4, px = tid & 15;
    float acc[16];
#pragma unroll
    for (int o = 0; o < 16; o++) acc[o] = __ldg(&bo[o0 + o]);
    const float* imgb = img + (size_t)b * CHW;
    for (int c = 0; c < 256; c++) {
        __syncthreads();
        for (int i = tid; i < 324; i += 256) {
            int iy = i / 18, ix = i - iy * 18;
            int gy = gy0 + iy - 1, gx = gx0 + ix - 1;
            float v = 0.f;
            if ((unsigned)gy < 128u && (unsigned)gx < 128u)
                v = imgb[(size_t)c * HWP + gy * 128 + gx];
            sIn[i] = v;
        }
        if (tid < 144) {
            int o = tid / 9, tap = tid - o * 9;
            sW[tap][o] = Wo[((size_t)(o0 + o) * 256 + c) * 9 + tap];
        }
        __syncthreads();
#pragma unroll
        for (int tap = 0; tap < 9; tap++) {
            int dy = tap / 3, dx = tap - dy * 3;
            float iv = sIn[(py + dy) * 18 + px + dx];
            const float4* w4 = (const float4*)sW[tap];
#pragma unroll
            for (int og = 0; og < 4; og++) {
                float4 w = w4[og];
                acc[og * 4 + 0] += w.x * iv;
                acc[og * 4 + 1] += w.y * iv;
                acc[og * 4 + 2] += w.z * iv;
                acc[og * 4 + 3] += w.w * iv;
            }
        }
    }
    size_t base = (((size_t)b * 256 + o0) << 14) + (gy0 + py) * 128 + gx0 + px;
#pragma unroll
    for (int o = 0; o < 16; o++)
        z[base + (size_t)o * HWP] = acc[o];
}

// ---------------- batchnorm stats per channel over (b,h,w) ----------------
__global__ void k_stats(const float* __restrict__ z, float* __restrict__ meanv, float* __restrict__ rstdv)
{
    __shared__ float rs[256], rs2[256];
    int c = blockIdx.x;
    int tid = threadIdx.x;
    float s = 0.f, s2 = 0.f;
    for (int i = tid; i < 65536; i += 256) {
        int b = i >> 14, p = i & 16383;
        float v = z[(((size_t)b * 256 + c) << 14) + p];
        s += v; s2 += v * v;
    }
    rs[tid] = s; rs2[tid] = s2; __syncthreads();
    for (int st = 128; st; st >>= 1) {
        if (tid < st) { rs[tid] += rs[tid + st]; rs2[tid] += rs2[tid + st]; }
        __syncthreads();
    }
    if (tid == 0) {
        float m = rs[0] * (1.0f / 65536.0f);
        float var = rs2[0] * (1.0f / 65536.0f) - m * m;
        meanv[c] = m;
        rstdv[c] = rsqrtf(var + 1e-5f);
    }
}

// ---------------- normalize + affine + LeakyReLU (in-place on d_out) ----------------
__global__ void k_final(float* __restrict__ z, const float* __restrict__ meanv, const float* __restrict__ rstdv,
                        const float* __restrict__ gamma, const float* __restrict__ beta)
{
    size_t idx = (size_t)blockIdx.x * 1024 + threadIdx.x;
    int c = (int)((idx >> 14) & 255);
    float v = z[idx];
    v = (v - __ldg(&meanv[c])) * __ldg(&rstdv[c]) * __ldg(&gamma[c]) + __ldg(&beta[c]);
    z[idx] = v >= 0.f ? v : 0.2f * v;
}

// ---------------- host launch ----------------
extern "C" void kernel_launch(void* const* d_in, const int* in_sizes, int n_in,
                              void* d_out, int out_size)
{
    (void)in_sizes; (void)n_in; (void)out_size;
    const float* x     = (const float*)d_in[0];
    const float* y     = (const float*)d_in[1];
    const float* Wq    = (const float*)d_in[2];
    const float* bq    = (const float*)d_in[3];
    const float* Wk    = (const float*)d_in[4];
    const float* bk    = (const float*)d_in[5];
    const float* Wv    = (const float*)d_in[6];
    const float* bv    = (const float*)d_in[7];
    const float* Wo    = (const float*)d_in[8];
    const float* bo    = (const float*)d_in[9];
    const float* gamma = (const float*)d_in[10];
    const float* beta  = (const float*)d_in[11];
    float* out = (float*)d_out;

    float *qt, *kt, *vt, *S, *attn, *meanv, *rstdv;
    cudaGetSymbolAddress((void**)&qt,    g_qt);
    cudaGetSymbolAddress((void**)&kt,    g_kt);
    cudaGetSymbolAddress((void**)&vt,    g_vt);
    cudaGetSymbolAddress((void**)&S,     g_S);
    cudaGetSymbolAddress((void**)&attn,  g_attn);
    cudaGetSymbolAddress((void**)&meanv, g_mean);
    cudaGetSymbolAddress((void**)&rstdv, g_rstd);

    dim3 pg(256, 4, 4);
    k_proj<<<pg, 256>>>(Wq, bq, x, qt);
    k_proj<<<pg, 256>>>(Wk, bk, y, kt);
    k_proj<<<pg, 256>>>(Wv, bv, y, vt);

    const int splits[4] = {1, 1, 8, 64};
    for (int s = 0; s < 4; s++) {
        int l = s + 1;
        int n = 16384 >> (2 * l);
        int d = 64 << (2 * l);
        int sp = splits[s];
        int kper = d / sp;
        int soff = s << 20;
        float alpha = 1.0f / sqrtf((float)d);
        k_scores<<<dim3(n / 64, n / 64, 4 * sp), 256>>>(qt, kt, S, n, d, sp, kper, soff);
        k_softmax<<<dim3(n, 4), 256>>>(S, n, sp, alpha);
        k_out<<<dim3(d / 64, n / 64, 4), 256>>>(S, vt, attn, n, d, sp, s, l, soff);
    }

    k_conv<<<dim3(64, 16, 4), 256>>>(attn, Wo, bo, out);
    k_stats<<<256, 256>>>(out, meanv, rstdv);
    k_final<<<16384, 1024>>>(out, meanv, rstdv, gamma, beta);
}

// round 2
// speedup vs baseline: 2.3845x; 2.3845x over previous
#include <cuda_runtime.h>
#include <math.h>
#include <stdint.h>

#define BATCH 4
#define HWP 16384
#define CHW 4194304
#define TOKB 4194304
#define KC 16
#define RP 20

// ---------------- scratch ----------------
__device__ float g_qt[BATCH * TOKB];
__device__ float g_kt[BATCH * TOKB];
__device__ float g_vt[BATCH * TOKB];
__device__ float g_S[67108864];
__device__ float g_attn[BATCH * TOKB];
__device__ float g_mean[256];
__device__ float g_rstd[256];

// ---------------- helpers ----------------
__device__ __forceinline__ float rtf32(float x) {
    uint32_t u; asm("cvt.rna.tf32.f32 %0, %1;" : "=r"(u) : "f"(x));
    return __uint_as_float(u);
}
__device__ __forceinline__ void ldsm4(uint32_t a, uint32_t& r0, uint32_t& r1, uint32_t& r2, uint32_t& r3) {
    asm volatile("ldmatrix.sync.aligned.m8n8.x4.shared.b16 {%0,%1,%2,%3}, [%4];"
                 : "=r"(r0), "=r"(r1), "=r"(r2), "=r"(r3) : "r"(a));
}
__device__ __forceinline__ void mma_tf32(float* c, const uint32_t* a, const uint32_t* b) {
    asm volatile("mma.sync.aligned.m16n8k8.row.col.f32.tf32.tf32.f32 "
                 "{%0,%1,%2,%3}, {%4,%5,%6,%7}, {%8,%9}, {%0,%1,%2,%3};"
                 : "+f"(c[0]), "+f"(c[1]), "+f"(c[2]), "+f"(c[3])
                 : "r"(a[0]), "r"(a[1]), "r"(a[2]), "r"(a[3]), "r"(b[0]), "r"(b[1]));
}
__device__ __forceinline__ void scatterTok(float* tok, int o, int p, float v) {
    int scl = o >> 6, cl = o & 63, l = scl + 1;
    int msk = (1 << l) - 1;
    int yy = p >> 7, xx = p & 127;
    int wy = yy >> l, py = yy & msk, wx = xx >> l, px = xx & msk;
    int n = (wy << (7 - l)) | wx;
    int d = (cl << (2 * l)) | (py << l) | px;
    tok[(scl << 20) + (size_t)n * (64 << (2 * l)) + d] = v;
}
__device__ __forceinline__ void scatterImg(float* img, int b, int scale, int row, int col, float v) {
    int l = scale + 1;
    int owlog = 7 - l;
    int wy = row >> owlog, wx = row & ((1 << owlog) - 1);
    int cl = col >> (2 * l);
    int r = col & ((1 << (2 * l)) - 1);
    int py = r >> l, px = r & ((1 << l) - 1);
    int y = (wy << l) | py, x = (wx << l) | px;
    int c = (scale << 6) | cl;
    img[(((size_t)b * 256 + c) << 14) + (y << 7) + x] = v;
}

// ---------------- unified tf32 tensor-core GEMM ----------------
// MODE 0: proj  C=W@inp + bias -> token layout (rounded tf32)
// MODE 1: scores (split-K partials) -> S
// MODE 2: out  P@V -> image layout
// MODE 3: conv3x3 implicit GEMM -> z image (+bias)
// LOADB 0: B global row-major [n][ldb] (no transpose)
// LOADB 1: B global k-major [k][ldb] (transpose on smem store)
// LOADB 2: conv shifted-image loader (BN must be 128 = one image row)
template<int BM, int BN, int LOADB, int MODE>
__global__ __launch_bounds__(256) void gemm_tc(
    const float* __restrict__ A, const float* __restrict__ B,
    const float* __restrict__ bias, float* __restrict__ C,
    int Kloop, int lda, int ldb,
    int split, int kper, int soff, int nTok, int scale)
{
    constexpr int WM = BM / 2, WN = BN / 4;
    constexpr int MT = WM / 16, NT = WN / 8, NTP = WN / 16;
    __shared__ float As[2][BM * RP];
    __shared__ float Bs[2][BN * RP];

    int tid = threadIdx.x;
    int lane = tid & 31, wid = tid >> 5;
    int wm = wid >> 2, wn = wid & 3;
    int m0 = blockIdx.y * BM, n0 = blockIdx.x * BN;

    const float* Ab; const float* Bb;
    int bidx = 0, z = 0;
    if constexpr (MODE == 1) {
        z = blockIdx.z; bidx = z / split; int sp = z - bidx * split;
        Ab = A + (size_t)bidx * TOKB + soff + (size_t)sp * kper;
        Bb = B + (size_t)bidx * TOKB + soff + (size_t)sp * kper;
    } else if constexpr (MODE == 2) {
        bidx = blockIdx.z;
        Ab = A + (size_t)bidx * split * nTok * nTok;
        Bb = B + (size_t)bidx * TOKB + soff;
    } else {
        bidx = blockIdx.z;
        Ab = A;
        Bb = B + (size_t)bidx * CHW;
    }

    constexpr int APER = (BM * 4) / 256;
    constexpr int BPER = (LOADB == 0) ? (BN * 4) / 256 : (LOADB == 1 ? (KC * BN) / 1024 : 1);
    float4 ra[APER];
    float4 rb[BPER];
    float rbs[8];

    auto ldA = [&](int k0) {
#pragma unroll
        for (int j = 0; j < APER; j++) {
            int i = tid + j * 256;
            int row = i >> 2, seg = (i & 3) << 2;
            ra[j] = *(const float4*)(Ab + (size_t)(m0 + row) * lda + k0 + seg);
        }
    };
    auto stA = [&](int buf) {
#pragma unroll
        for (int j = 0; j < APER; j++) {
            int i = tid + j * 256;
            int row = i >> 2, seg = (i & 3) << 2;
            float4 v = ra[j];
            v.x = rtf32(v.x); v.y = rtf32(v.y); v.z = rtf32(v.z); v.w = rtf32(v.w);
            *(float4*)&As[buf][row * RP + seg] = v;
        }
    };
    auto ldB = [&](int k0) {
        if constexpr (LOADB == 0) {
#pragma unroll
            for (int j = 0; j < BPER; j++) {
                int i = tid + j * 256;
                int row = i >> 2, seg = (i & 3) << 2;
                rb[j] = *(const float4*)(Bb + (size_t)(n0 + row) * ldb + k0 + seg);
            }
        } else if constexpr (LOADB == 1) {
#pragma unroll
            for (int j = 0; j < BPER; j++) {
                int p = tid + j * 256;
                int kr = p / (BN / 4), nseg = (p - kr * (BN / 4)) << 2;
                rb[j] = *(const float4*)(Bb + (size_t)(k0 + kr) * ldb + n0 + nseg);
            }
        } else {
            int kl = tid >> 4, x0 = (tid & 15) << 3;
            int k = k0 + kl;
            int c = k / 9, tap = k - c * 9;
            int dy = tap / 3, dx = tap - dy * 3;
            int yy = blockIdx.x;
            int gy = yy + dy - 1;
            const float* src = Bb + (size_t)c * HWP + gy * 128;
            bool okY = (unsigned)gy < 128u;
#pragma unroll
            for (int i = 0; i < 8; i++) {
                int gx = x0 + i + dx - 1;
                rbs[i] = (okY && (unsigned)gx < 128u) ? src[gx] : 0.f;
            }
        }
    };
    auto stB = [&](int buf) {
        if constexpr (LOADB == 0) {
#pragma unroll
            for (int j = 0; j < BPER; j++) {
                int i = tid + j * 256;
                int row = i >> 2, seg = (i & 3) << 2;
                float4 v = rb[j];
                v.x = rtf32(v.x); v.y = rtf32(v.y); v.z = rtf32(v.z); v.w = rtf32(v.w);
                *(float4*)&Bs[buf][row * RP + seg] = v;
            }
        } else if constexpr (LOADB == 1) {
#pragma unroll
            for (int j = 0; j < BPER; j++) {
                int p = tid + j * 256;
                int kr = p / (BN / 4), nseg = (p - kr * (BN / 4)) << 2;
                float4 v = rb[j];
                Bs[buf][(nseg + 0) * RP + kr] = rtf32(v.x);
                Bs[buf][(nseg + 1) * RP + kr] = rtf32(v.y);
                Bs[buf][(nseg + 2) * RP + kr] = rtf32(v.z);
                Bs[buf][(nseg + 3) * RP + kr] = rtf32(v.w);
            }
        } else {
            int kl = tid >> 4, x0 = (tid & 15) << 3;
#pragma unroll
            for (int i = 0; i < 8; i++)
                Bs[buf][(x0 + i) * RP + kl] = rtf32(rbs[i]);
        }
    };

    float acc[MT][NT][4];
#pragma unroll
    for (int i = 0; i < MT; i++)
#pragma unroll
        for (int j = 0; j < NT; j++)
#pragma unroll
            for (int e = 0; e < 4; e++) acc[i][j][e] = 0.f;

    uint32_t sA0 = (uint32_t)__cvta_generic_to_shared(&As[0][0]);
    uint32_t sA1 = (uint32_t)__cvta_generic_to_shared(&As[1][0]);
    uint32_t sB0 = (uint32_t)__cvta_generic_to_shared(&Bs[0][0]);
    uint32_t sB1 = (uint32_t)__cvta_generic_to_shared(&Bs[1][0]);
    int r8 = lane & 7, hi8 = (lane >> 3) & 1, hi16 = (lane >> 4) & 1;
    uint32_t aOff = (uint32_t)((wm * WM + r8 + hi8 * 8) * RP * 4 + hi16 * 16);
    uint32_t bOff = (uint32_t)((wn * WN + r8 + hi8 * 8) * RP * 4 + hi16 * 16);

    auto compute = [&](int buf) {
        uint32_t sa = buf ? sA1 : sA0;
        uint32_t sb = buf ? sB1 : sB0;
#pragma unroll
        for (int ks = 0; ks < KC / 8; ks++) {
            uint32_t af[MT][4], bf[NTP][4];
#pragma unroll
            for (int mt = 0; mt < MT; mt++)
                ldsm4(sa + aOff + mt * 16 * RP * 4 + ks * 32, af[mt][0], af[mt][1], af[mt][2], af[mt][3]);
#pragma unroll
            for (int np = 0; np < NTP; np++)
                ldsm4(sb + bOff + np * 16 * RP * 4 + ks * 32, bf[np][0], bf[np][1], bf[np][2], bf[np][3]);
#pragma unroll
            for (int mt = 0; mt < MT; mt++)
#pragma unroll
                for (int np = 0; np < NTP; np++) {
                    uint32_t b0[2] = { bf[np][0], bf[np][2] };
                    uint32_t b1[2] = { bf[np][1], bf[np][3] };
                    mma_tf32(acc[mt][np * 2 + 0], af[mt], b0);
                    mma_tf32(acc[mt][np * 2 + 1], af[mt], b1);
                }
        }
    };

    int nc = Kloop / KC;
    ldA(0); ldB(0);
    stA(0); stB(0);
    __syncthreads();
    for (int c = 0; c < nc; c++) {
        int cur = c & 1;
        if (c + 1 < nc) { ldA((c + 1) * KC); ldB((c + 1) * KC); }
        compute(cur);
        if (c + 1 < nc) { stA(cur ^ 1); stB(cur ^ 1); }
        __syncthreads();
    }

    // epilogue
    int g = lane >> 2, q2 = (lane & 3) << 1;
#pragma unroll
    for (int mt = 0; mt < MT; mt++) {
        int row0 = m0 + wm * WM + mt * 16 + g;
#pragma unroll
        for (int e2 = 0; e2 < 2; e2++) {
            int row = row0 + e2 * 8;
            float bia = 0.f;
            if constexpr (MODE == 0 || MODE == 3) bia = __ldg(&bias[row]);
#pragma unroll
            for (int nt = 0; nt < NT; nt++) {
                int col = n0 + wn * WN + nt * 8 + q2;
                float v0 = acc[mt][nt][e2 * 2 + 0] + bia;
                float v1 = acc[mt][nt][e2 * 2 + 1] + bia;
                if constexpr (MODE == 1) {
                    *(float2*)&C[(size_t)z * nTok * nTok + (size_t)row * nTok + col] = make_float2(v0, v1);
                } else if constexpr (MODE == 0) {
                    float* tok = C + (size_t)bidx * TOKB;
                    scatterTok(tok, row, col, rtf32(v0));
                    scatterTok(tok, row, col + 1, rtf32(v1));
                } else if constexpr (MODE == 2) {
                    scatterImg(C, bidx, scale, row, col, v0);
                    scatterImg(C, bidx, scale, row, col + 1, v1);
                } else {
                    size_t adr = (((size_t)bidx * 256 + row) << 14) + col;
                    *(float2*)&C[adr] = make_float2(v0, v1);
                }
            }
        }
    }
}

// ---------------- softmax over rows, fusing split-K reduction ----------------
__global__ void k_softmax(float* __restrict__ S, int nTok, int split, float alpha)
{
    __shared__ float rowb[4096];
    __shared__ float red[256];
    int row = blockIdx.x;
    size_t bb = (size_t)blockIdx.y * split * nTok * nTok;
    int tid = threadIdx.x;
    float mx = -1e30f;
    for (int j = tid; j < nTok; j += 256) {
        float s = 0.f;
        for (int sp = 0; sp < split; sp++)
            s += S[bb + ((size_t)sp * nTok + row) * nTok + j];
        s *= alpha;
        rowb[j] = s;
        mx = fmaxf(mx, s);
    }
    red[tid] = mx; __syncthreads();
    for (int st = 128; st; st >>= 1) { if (tid < st) red[tid] = fmaxf(red[tid], red[tid + st]); __syncthreads(); }
    mx = red[0]; __syncthreads();
    float sum = 0.f;
    for (int j = tid; j < nTok; j += 256) {
        float e = __expf(rowb[j] - mx);
        rowb[j] = e; sum += e;
    }
    red[tid] = sum; __syncthreads();
    for (int st = 128; st; st >>= 1) { if (tid < st) red[tid] += red[tid + st]; __syncthreads(); }
    float inv = 1.0f / red[0];
    size_t ob = bb + (size_t)row * nTok;
    for (int j = tid; j < nTok; j += 256)
        S[ob + j] = rowb[j] * inv;
}

// ---------------- batchnorm stats ----------------
__global__ void k_stats(const float* __restrict__ z, float* __restrict__ meanv, float* __restrict__ rstdv)
{
    __shared__ float rs[256], rs2[256];
    int c = blockIdx.x;
    int tid = threadIdx.x;
    float s = 0.f, s2 = 0.f;
    for (int i = tid; i < 65536; i += 256) {
        int b = i >> 14, p = i & 16383;
        float v = z[(((size_t)b * 256 + c) << 14) + p];
        s += v; s2 += v * v;
    }
    rs[tid] = s; rs2[tid] = s2; __syncthreads();
    for (int st = 128; st; st >>= 1) {
        if (tid < st) { rs[tid] += rs[tid + st]; rs2[tid] += rs2[tid + st]; }
        __syncthreads();
    }
    if (tid == 0) {
        float m = rs[0] * (1.0f / 65536.0f);
        float var = rs2[0] * (1.0f / 65536.0f) - m * m;
        meanv[c] = m;
        rstdv[c] = rsqrtf(var + 1e-5f);
    }
}

// ---------------- normalize + affine + LeakyReLU ----------------
__global__ void k_final(float* __restrict__ z, const float* __restrict__ meanv, const float* __restrict__ rstdv,
                        const float* __restrict__ gamma, const float* __restrict__ beta)
{
    size_t idx = (size_t)blockIdx.x * 1024 + threadIdx.x;
    int c = (int)((idx >> 14) & 255);
    float v = z[idx];
    v = (v - __ldg(&meanv[c])) * __ldg(&rstdv[c]) * __ldg(&gamma[c]) + __ldg(&beta[c]);
    z[idx] = v >= 0.f ? v : 0.2f * v;
}

// ---------------- host launch ----------------
extern "C" void kernel_launch(void* const* d_in, const int* in_sizes, int n_in,
                              void* d_out, int out_size)
{
    (void)in_sizes; (void)n_in; (void)out_size;
    const float* x     = (const float*)d_in[0];
    const float* y     = (const float*)d_in[1];
    const float* Wq    = (const float*)d_in[2];
    const float* bq    = (const float*)d_in[3];
    const float* Wk    = (const float*)d_in[4];
    const float* bk    = (const float*)d_in[5];
    const float* Wv    = (const float*)d_in[6];
    const float* bv    = (const float*)d_in[7];
    const float* Wo    = (const float*)d_in[8];
    const float* bo    = (const float*)d_in[9];
    const float* gamma = (const float*)d_in[10];
    const float* beta  = (const float*)d_in[11];
    float* out = (float*)d_out;

    float *qt, *kt, *vt, *S, *attn, *meanv, *rstdv;
    cudaGetSymbolAddress((void**)&qt,    g_qt);
    cudaGetSymbolAddress((void**)&kt,    g_kt);
    cudaGetSymbolAddress((void**)&vt,    g_vt);
    cudaGetSymbolAddress((void**)&S,     g_S);
    cudaGetSymbolAddress((void**)&attn,  g_attn);
    cudaGetSymbolAddress((void**)&meanv, g_mean);
    cudaGetSymbolAddress((void**)&rstdv, g_rstd);

    // projections: C = W @ inp + b -> token layout (tf32-rounded)
    gemm_tc<128, 128, 1, 0><<<dim3(128, 2, 4), 256>>>(Wq, x, bq, qt, 256, 256, HWP, 0, 0, 0, 0, 0);
    gemm_tc<128, 128, 1, 0><<<dim3(128, 2, 4), 256>>>(Wk, y, bk, kt, 256, 256, HWP, 0, 0, 0, 0, 0);
    gemm_tc<128, 128, 1, 0><<<dim3(128, 2, 4), 256>>>(Wv, y, bv, vt, 256, 256, HWP, 0, 0, 0, 0, 0);

    const int splits[4] = {1, 1, 8, 64};
    for (int s = 0; s < 4; s++) {
        int l = s + 1;
        int n = 16384 >> (2 * l);
        int d = 64 << (2 * l);
        int sp = splits[s];
        int kper = d / sp;
        int soff = s << 20;
        float alpha = 1.0f / sqrtf((float)d);
        if (s < 3) {
            gemm_tc<128, 128, 0, 1><<<dim3(n / 128, n / 128, 4 * sp), 256>>>(
                qt, kt, nullptr, S, kper, d, d, sp, kper, soff, n, s);
        } else {
            gemm_tc<64, 64, 0, 1><<<dim3(1, 1, 4 * sp), 256>>>(
                qt, kt, nullptr, S, kper, d, d, sp, kper, soff, n, s);
        }
        k_softmax<<<dim3(n, 4), 256>>>(S, n, sp, alpha);
        if (s < 3) {
            gemm_tc<128, 128, 1, 2><<<dim3(d / 128, n / 128, 4), 256>>>(
                S, vt, nullptr, attn, n, n, d, sp, 0, soff, n, s);
        } else {
            gemm_tc<64, 64, 1, 2><<<dim3(d / 64, n / 64, 4), 256>>>(
                S, vt, nullptr, attn, n, n, d, sp, 0, soff, n, s);
        }
    }

    // conv3x3 implicit GEMM -> d_out
    gemm_tc<128, 128, 2, 3><<<dim3(128, 2, 4), 256>>>(Wo, attn, bo, out, 2304, 2304, 0, 0, 0, 0, 0, 0);

    k_stats<<<256, 256>>>(out, meanv, rstdv);
    k_final<<<16384, 1024>>>(out, meanv, rstdv, gamma, beta);
}

// round 3
// speedup vs baseline: 2.5299x; 1.0610x over previous
#include <cuda_runtime.h>
#include <math.h>
#include <stdint.h>

#define BATCH 4
#define HWP 16384
#define CHW 4194304
#define TOKB 4194304
#define KC 16
#define RP 20

// ---------------- scratch ----------------
__device__ float g_qt[BATCH * TOKB];
__device__ float g_kt[BATCH * TOKB];
__device__ float g_vt[BATCH * TOKB];   // V in TRANSPOSED token layout [scale][d][n]
__device__ float g_S[67108864];
__device__ float g_attn[BATCH * TOKB];
__device__ float g_mean[256];
__device__ float g_rstd[256];

// ---------------- helpers ----------------
__device__ __forceinline__ float rtf32(float x) {
    uint32_t u; asm("cvt.rna.tf32.f32 %0, %1;" : "=r"(u) : "f"(x));
    return __uint_as_float(u);
}
__device__ __forceinline__ void cpasync16(uint32_t dst, const float* src) {
    asm volatile("cp.async.cg.shared.global [%0], [%1], 16;" :: "r"(dst), "l"(src));
}
__device__ __forceinline__ void ldsm4(uint32_t a, uint32_t& r0, uint32_t& r1, uint32_t& r2, uint32_t& r3) {
    asm volatile("ldmatrix.sync.aligned.m8n8.x4.shared.b16 {%0,%1,%2,%3}, [%4];"
                 : "=r"(r0), "=r"(r1), "=r"(r2), "=r"(r3) : "r"(a));
}
__device__ __forceinline__ void mma_tf32(float* c, const uint32_t* a, const uint32_t* b) {
    asm volatile("mma.sync.aligned.m16n8k8.row.col.f32.tf32.tf32.f32 "
                 "{%0,%1,%2,%3}, {%4,%5,%6,%7}, {%8,%9}, {%0,%1,%2,%3};"
                 : "+f"(c[0]), "+f"(c[1]), "+f"(c[2]), "+f"(c[3])
                 : "r"(a[0]), "r"(a[1]), "r"(a[2]), "r"(a[3]), "r"(b[0]), "r"(b[1]));
}
__device__ __forceinline__ void scatterTok(float* tok, int o, int p, float v) {
    int scl = o >> 6, cl = o & 63, l = scl + 1;
    int msk = (1 << l) - 1;
    int yy = p >> 7, xx = p & 127;
    int wy = yy >> l, py = yy & msk, wx = xx >> l, px = xx & msk;
    int n = (wy << (7 - l)) | wx;
    int d = (cl << (2 * l)) | (py << l) | px;
    tok[(scl << 20) + (size_t)n * (64 << (2 * l)) + d] = v;
}
__device__ __forceinline__ void scatterTokT(float* tok, int o, int p, float v) {
    int scl = o >> 6, cl = o & 63, l = scl + 1;
    int msk = (1 << l) - 1;
    int yy = p >> 7, xx = p & 127;
    int wy = yy >> l, py = yy & msk, wx = xx >> l, px = xx & msk;
    int n = (wy << (7 - l)) | wx;
    int d = (cl << (2 * l)) | (py << l) | px;
    int nTokS = 16384 >> (2 * l);
    tok[(scl << 20) + (size_t)d * nTokS + n] = v;
}
__device__ __forceinline__ void scatterImg(float* img, int b, int scale, int row, int col, float v) {
    int l = scale + 1;
    int owlog = 7 - l;
    int wy = row >> owlog, wx = row & ((1 << owlog) - 1);
    int cl = col >> (2 * l);
    int r = col & ((1 << (2 * l)) - 1);
    int py = r >> l, px = r & ((1 << l) - 1);
    int y = (wy << l) | py, x = (wx << l) | px;
    int c = (scale << 6) | cl;
    img[(((size_t)b * 256 + c) << 14) + (y << 7) + x] = v;
}

// ================= async tf32 GEMM (operands pre-rounded in gmem) =================
// MODE 1: scores Q@K^T (split-K partials) -> S
// MODE 2: out P@V -> image layout (rounded)
template<int BM, int BN, int MODE>
__global__ __launch_bounds__(256) void gemm_async(
    const float* __restrict__ A, const float* __restrict__ B, float* __restrict__ C,
    int Kloop, int lda, int ldb,
    int split, int kper, int soff, int nTok, int scale)
{
    constexpr int WM = BM / 2, WN = BN / 4;
    constexpr int MT = WM / 16, NT = WN / 8, NTP = WN / 16;
    constexpr int ST = 3;
    extern __shared__ float dynsmem[];
    float* Asm = dynsmem;
    float* Bsm = dynsmem + ST * BM * RP;

    int tid = threadIdx.x;
    int lane = tid & 31, wid = tid >> 5;
    int wm = wid >> 2, wn = wid & 3;
    int m0 = blockIdx.y * BM, n0 = blockIdx.x * BN;

    const float* Ab; const float* Bb;
    int bidx, z = 0;
    if constexpr (MODE == 1) {
        z = blockIdx.z; bidx = z / split; int sp = z - bidx * split;
        Ab = A + (size_t)bidx * TOKB + soff + (size_t)sp * kper;
        Bb = B + (size_t)bidx * TOKB + soff + (size_t)sp * kper;
    } else {
        bidx = blockIdx.z;
        Ab = A + (size_t)bidx * split * nTok * nTok;
        Bb = B + (size_t)bidx * TOKB + soff;
    }

    constexpr int APER = (BM * KC / 4) / 256;
    constexpr int BPER = (BN * KC / 4) / 256;
    uint32_t sA = (uint32_t)__cvta_generic_to_shared(Asm);
    uint32_t sB = (uint32_t)__cvta_generic_to_shared(Bsm);
    constexpr uint32_t ASTR = BM * RP * 4, BSTR = BN * RP * 4;
    int nc = Kloop / KC;

    auto issue = [&](int c) {
        int st = c % ST;
        int k0 = c * KC;
#pragma unroll
        for (int j = 0; j < APER; j++) {
            int i = tid + j * 256;
            int row = i >> 2, seg = (i & 3) << 2;
            cpasync16(sA + st * ASTR + (uint32_t)(row * RP + seg) * 4,
                      Ab + (size_t)(m0 + row) * lda + k0 + seg);
        }
#pragma unroll
        for (int j = 0; j < BPER; j++) {
            int i = tid + j * 256;
            int row = i >> 2, seg = (i & 3) << 2;
            cpasync16(sB + st * BSTR + (uint32_t)(row * RP + seg) * 4,
                      Bb + (size_t)(n0 + row) * ldb + k0 + seg);
        }
    };

    float acc[MT][NT][4];
#pragma unroll
    for (int i = 0; i < MT; i++)
#pragma unroll
        for (int j = 0; j < NT; j++)
#pragma unroll
            for (int e = 0; e < 4; e++) acc[i][j][e] = 0.f;

    int r8 = lane & 7, hi8 = (lane >> 3) & 1, hi16 = (lane >> 4) & 1;
    uint32_t aOff = (uint32_t)((wm * WM + r8 + hi8 * 8) * RP * 4 + hi16 * 16);
    uint32_t bOff = (uint32_t)((wn * WN + r8 + hi8 * 8) * RP * 4 + hi16 * 16);

    if (0 < nc) issue(0);
    asm volatile("cp.async.commit_group;");
    if (1 < nc) issue(1);
    asm volatile("cp.async.commit_group;");

    for (int c = 0; c < nc; c++) {
        asm volatile("cp.async.wait_group 1;");
        __syncthreads();
        {
            int st = c % ST;
            uint32_t sa = sA + st * ASTR, sb = sB + st * BSTR;
#pragma unroll
            for (int ks = 0; ks < KC / 8; ks++) {
                uint32_t af[MT][4], bf[NTP][4];
#pragma unroll
                for (int mt = 0; mt < MT; mt++)
                    ldsm4(sa + aOff + mt * 16 * RP * 4 + ks * 32, af[mt][0], af[mt][1], af[mt][2], af[mt][3]);
#pragma unroll
                for (int np = 0; np < NTP; np++)
                    ldsm4(sb + bOff + np * 16 * RP * 4 + ks * 32, bf[np][0], bf[np][1], bf[np][2], bf[np][3]);
#pragma unroll
                for (int mt = 0; mt < MT; mt++)
#pragma unroll
                    for (int np = 0; np < NTP; np++) {
                        uint32_t b0[2] = { bf[np][0], bf[np][2] };
                        uint32_t b1[2] = { bf[np][1], bf[np][3] };
                        mma_tf32(acc[mt][np * 2 + 0], af[mt], b0);
                        mma_tf32(acc[mt][np * 2 + 1], af[mt], b1);
                    }
            }
        }
        if (c + 2 < nc) issue(c + 2);
        asm volatile("cp.async.commit_group;");
    }

    // epilogue
    int g = lane >> 2, q2 = (lane & 3) << 1;
#pragma unroll
    for (int mt = 0; mt < MT; mt++) {
        int row0 = m0 + wm * WM + mt * 16 + g;
#pragma unroll
        for (int e2 = 0; e2 < 2; e2++) {
            int row = row0 + e2 * 8;
#pragma unroll
            for (int nt = 0; nt < NT; nt++) {
                int col = n0 + wn * WN + nt * 8 + q2;
                float v0 = acc[mt][nt][e2 * 2 + 0];
                float v1 = acc[mt][nt][e2 * 2 + 1];
                if constexpr (MODE == 1) {
                    *(float2*)&C[(size_t)z * nTok * nTok + (size_t)row * nTok + col] = make_float2(v0, v1);
                } else {
                    scatterImg(C, bidx, scale, row, col, rtf32(v0));
                    scatterImg(C, bidx, scale, row, col + 1, rtf32(v1));
                }
            }
        }
    }
}

// ================= sync tf32 GEMM (raw fp32 operands, needs rounding) =================
// MODE 0: proj -> token layout; MODE 4: proj -> TRANSPOSED token layout (V)
// MODE 3: conv3x3 implicit GEMM -> image (+bias)
// LOADB 1: B global k-major [k][ldb]; LOADB 2: conv shifted-image loader
template<int BM, int BN, int LOADB, int MODE>
__global__ __launch_bounds__(256) void gemm_sync(
    const float* __restrict__ A, const float* __restrict__ B,
    const float* __restrict__ bias, float* __restrict__ C,
    int Kloop, int lda, int ldb)
{
    constexpr int WM = BM / 2, WN = BN / 4;
    constexpr int MT = WM / 16, NT = WN / 8, NTP = WN / 16;
    __shared__ float As[2][BM * RP];
    __shared__ float Bs[2][BN * RP];

    int tid = threadIdx.x;
    int lane = tid & 31, wid = tid >> 5;
    int wm = wid >> 2, wn = wid & 3;
    int m0 = blockIdx.y * BM, n0 = blockIdx.x * BN;
    int bidx = blockIdx.z;
    const float* Ab = A;
    const float* Bb = B + (size_t)bidx * CHW;

    constexpr int APER = (BM * 4) / 256;
    constexpr int BPER = (LOADB == 1) ? (KC * BN) / 1024 : 1;
    float4 ra[APER];
    float4 rb[BPER];
    float rbs[8];

    auto ldA = [&](int k0) {
#pragma unroll
        for (int j = 0; j < APER; j++) {
            int i = tid + j * 256;
            int row = i >> 2, seg = (i & 3) << 2;
            ra[j] = *(const float4*)(Ab + (size_t)(m0 + row) * lda + k0 + seg);
        }
    };
    auto stA = [&](int buf) {
#pragma unroll
        for (int j = 0; j < APER; j++) {
            int i = tid + j * 256;
            int row = i >> 2, seg = (i & 3) << 2;
            float4 v = ra[j];
            v.x = rtf32(v.x); v.y = rtf32(v.y); v.z = rtf32(v.z); v.w = rtf32(v.w);
            *(float4*)&As[buf][row * RP + seg] = v;
        }
    };
    auto ldB = [&](int k0) {
        if constexpr (LOADB == 1) {
#pragma unroll
            for (int j = 0; j < BPER; j++) {
                int p = tid + j * 256;
                int kr = p / (BN / 4), nseg = (p - kr * (BN / 4)) << 2;
                rb[j] = *(const float4*)(Bb + (size_t)(k0 + kr) * ldb + n0 + nseg);
            }
        } else {
            int kl = tid >> 4, x0 = (tid & 15) << 3;
            int k = k0 + kl;
            int c = k / 9, tap = k - c * 9;
            int dy = tap / 3, dx = tap - dy * 3;
            int yy = blockIdx.x;
            int gy = yy + dy - 1;
            const float* src = Bb + (size_t)c * HWP + gy * 128;
            bool okY = (unsigned)gy < 128u;
#pragma unroll
            for (int i = 0; i < 8; i++) {
                int gx = x0 + i + dx - 1;
                rbs[i] = (okY && (unsigned)gx < 128u) ? src[gx] : 0.f;
            }
        }
    };
    auto stB = [&](int buf) {
        if constexpr (LOADB == 1) {
#pragma unroll
            for (int j = 0; j < BPER; j++) {
                int p = tid + j * 256;
                int kr = p / (BN / 4), nseg = (p - kr * (BN / 4)) << 2;
                float4 v = rb[j];
                Bs[buf][(nseg + 0) * RP + kr] = rtf32(v.x);
                Bs[buf][(nseg + 1) * RP + kr] = rtf32(v.y);
                Bs[buf][(nseg + 2) * RP + kr] = rtf32(v.z);
                Bs[buf][(nseg + 3) * RP + kr] = rtf32(v.w);
            }
        } else {
            int kl = tid >> 4, x0 = (tid & 15) << 3;
#pragma unroll
            for (int i = 0; i < 8; i++)
                Bs[buf][(x0 + i) * RP + kl] = rbs[i];   // attn already tf32
        }
    };

    float acc[MT][NT][4];
#pragma unroll
    for (int i = 0; i < MT; i++)
#pragma unroll
        for (int j = 0; j < NT; j++)
#pragma unroll
            for (int e = 0; e < 4; e++) acc[i][j][e] = 0.f;

    uint32_t sA0 = (uint32_t)__cvta_generic_to_shared(&As[0][0]);
    uint32_t sB0 = (uint32_t)__cvta_generic_to_shared(&Bs[0][0]);
    int r8 = lane & 7, hi8 = (lane >> 3) & 1, hi16 = (lane >> 4) & 1;
    uint32_t aOff = (uint32_t)((wm * WM + r8 + hi8 * 8) * RP * 4 + hi16 * 16);
    uint32_t bOff = (uint32_t)((wn * WN + r8 + hi8 * 8) * RP * 4 + hi16 * 16);

    auto compute = [&](int buf) {
        uint32_t sa = sA0 + (uint32_t)buf * BM * RP * 4;
        uint32_t sb = sB0 + (uint32_t)buf * BN * RP * 4;
#pragma unroll
        for (int ks = 0; ks < KC / 8; ks++) {
            uint32_t af[MT][4], bf[NTP][4];
#pragma unroll
            for (int mt = 0; mt < MT; mt++)
                ldsm4(sa + aOff + mt * 16 * RP * 4 + ks * 32, af[mt][0], af[mt][1], af[mt][2], af[mt][3]);
#pragma unroll
            for (int np = 0; np < NTP; np++)
                ldsm4(sb + bOff + np * 16 * RP * 4 + ks * 32, bf[np][0], bf[np][1], bf[np][2], bf[np][3]);
#pragma unroll
            for (int mt = 0; mt < MT; mt++)
#pragma unroll
                for (int np = 0; np < NTP; np++) {
                    uint32_t b0[2] = { bf[np][0], bf[np][2] };
                    uint32_t b1[2] = { bf[np][1], bf[np][3] };
                    mma_tf32(acc[mt][np * 2 + 0], af[mt], b0);
                    mma_tf32(acc[mt][np * 2 + 1], af[mt], b1);
                }
        }
    };

    int nc = Kloop / KC;
    ldA(0); ldB(0);
    stA(0); stB(0);
    __syncthreads();
    for (int c = 0; c < nc; c++) {
        int cur = c & 1;
        if (c + 1 < nc) { ldA((c + 1) * KC); ldB((c + 1) * KC); }
        compute(cur);
        if (c + 1 < nc) { stA(cur ^ 1); stB(cur ^ 1); }
        __syncthreads();
    }

    int g = lane >> 2, q2 = (lane & 3) << 1;
#pragma unroll
    for (int mt = 0; mt < MT; mt++) {
        int row0 = m0 + wm * WM + mt * 16 + g;
#pragma unroll
        for (int e2 = 0; e2 < 2; e2++) {
            int row = row0 + e2 * 8;
            float bia = __ldg(&bias[row]);
#pragma unroll
            for (int nt = 0; nt < NT; nt++) {
                int col = n0 + wn * WN + nt * 8 + q2;
                float v0 = acc[mt][nt][e2 * 2 + 0] + bia;
                float v1 = acc[mt][nt][e2 * 2 + 1] + bia;
                if constexpr (MODE == 0) {
                    float* tok = C + (size_t)bidx * TOKB;
                    scatterTok(tok, row, col, rtf32(v0));
                    scatterTok(tok, row, col + 1, rtf32(v1));
                } else if constexpr (MODE == 4) {
                    float* tok = C + (size_t)bidx * TOKB;
                    scatterTokT(tok, row, col, rtf32(v0));
                    scatterTokT(tok, row, col + 1, rtf32(v1));
                } else {
                    size_t adr = (((size_t)bidx * 256 + row) << 14) + col;
                    *(float2*)&C[adr] = make_float2(v0, v1);
                }
            }
        }
    }
}

// ---------------- softmax (fuses split-K reduction, rounds P to tf32) ----------------
__global__ void k_softmax(float* __restrict__ S, int nTok, int split, float alpha)
{
    __shared__ float rowb[4096];
    __shared__ float red[256];
    int row = blockIdx.x;
    size_t bb = (size_t)blockIdx.y * split * nTok * nTok;
    int tid = threadIdx.x;
    float mx = -1e30f;
    for (int j = tid; j < nTok; j += 256) {
        float s = 0.f;
        for (int sp = 0; sp < split; sp++)
            s += S[bb + ((size_t)sp * nTok + row) * nTok + j];
        s *= alpha;
        rowb[j] = s;
        mx = fmaxf(mx, s);
    }
    red[tid] = mx; __syncthreads();
    for (int st = 128; st; st >>= 1) { if (tid < st) red[tid] = fmaxf(red[tid], red[tid + st]); __syncthreads(); }
    mx = red[0]; __syncthreads();
    float sum = 0.f;
    for (int j = tid; j < nTok; j += 256) {
        float e = __expf(rowb[j] - mx);
        rowb[j] = e; sum += e;
    }
    red[tid] = sum; __syncthreads();
    for (int st = 128; st; st >>= 1) { if (tid < st) red[tid] += red[tid + st]; __syncthreads(); }
    float inv = 1.0f / red[0];
    size_t ob = bb + (size_t)row * nTok;
    for (int j = tid; j < nTok; j += 256)
        S[ob + j] = rtf32(rowb[j] * inv);
}

// ---------------- batchnorm stats ----------------
__global__ void k_stats(const float* __restrict__ z, float* __restrict__ meanv, float* __restrict__ rstdv)
{
    __shared__ float rs[256], rs2[256];
    int c = blockIdx.x;
    int tid = threadIdx.x;
    float s = 0.f, s2 = 0.f;
    for (int i = tid; i < 65536; i += 256) {
        int b = i >> 14, p = i & 16383;
        float v = z[(((size_t)b * 256 + c) << 14) + p];
        s += v; s2 += v * v;
    }
    rs[tid] = s; rs2[tid] = s2; __syncthreads();
    for (int st = 128; st; st >>= 1) {
        if (tid < st) { rs[tid] += rs[tid + st]; rs2[tid] += rs2[tid + st]; }
        __syncthreads();
    }
    if (tid == 0) {
        float m = rs[0] * (1.0f / 65536.0f);
        float var = rs2[0] * (1.0f / 65536.0f) - m * m;
        meanv[c] = m;
        rstdv[c] = rsqrtf(var + 1e-5f);
    }
}

// ---------------- normalize + affine + LeakyReLU ----------------
__global__ void k_final(float* __restrict__ z, const float* __restrict__ meanv, const float* __restrict__ rstdv,
                        const float* __restrict__ gamma, const float* __restrict__ beta)
{
    size_t idx = (size_t)blockIdx.x * 1024 + threadIdx.x;
    int c = (int)((idx >> 14) & 255);
    float v = z[idx];
    v = (v - __ldg(&meanv[c])) * __ldg(&rstdv[c]) * __ldg(&gamma[c]) + __ldg(&beta[c]);
    z[idx] = v >= 0.f ? v : 0.2f * v;
}

// ---------------- host launch ----------------
extern "C" void kernel_launch(void* const* d_in, const int* in_sizes, int n_in,
                              void* d_out, int out_size)
{
    (void)in_sizes; (void)n_in; (void)out_size;
    const float* x     = (const float*)d_in[0];
    const float* y     = (const float*)d_in[1];
    const float* Wq    = (const float*)d_in[2];
    const float* bq    = (const float*)d_in[3];
    const float* Wk    = (const float*)d_in[4];
    const float* bk    = (const float*)d_in[5];
    const float* Wv    = (const float*)d_in[6];
    const float* bv    = (const float*)d_in[7];
    const float* Wo    = (const float*)d_in[8];
    const float* bo    = (const float*)d_in[9];
    const float* gamma = (const float*)d_in[10];
    const float* beta  = (const float*)d_in[11];
    float* out = (float*)d_out;

    float *qt, *kt, *vt, *S, *attn, *meanv, *rstdv;
    cudaGetSymbolAddress((void**)&qt,    g_qt);
    cudaGetSymbolAddress((void**)&kt,    g_kt);
    cudaGetSymbolAddress((void**)&vt,    g_vt);
    cudaGetSymbolAddress((void**)&S,     g_S);
    cudaGetSymbolAddress((void**)&attn,  g_attn);
    cudaGetSymbolAddress((void**)&meanv, g_mean);
    cudaGetSymbolAddress((void**)&rstdv, g_rstd);

    const int shm128 = 3 * (128 + 128) * RP * 4;   // 61440
    const int shm64  = 3 * (64 + 64) * RP * 4;     // 30720
    cudaFuncSetAttribute(gemm_async<128, 128, 1>, cudaFuncAttributeMaxDynamicSharedMemorySize, shm128);
    cudaFuncSetAttribute(gemm_async<128, 128, 2>, cudaFuncAttributeMaxDynamicSharedMemorySize, shm128);
    cudaFuncSetAttribute(gemm_async<64, 64, 1>,   cudaFuncAttributeMaxDynamicSharedMemorySize, shm64);
    cudaFuncSetAttribute(gemm_async<64, 64, 2>,   cudaFuncAttributeMaxDynamicSharedMemorySize, shm64);

    // projections (sync path, fp32 inputs -> rounded tf32 tokens)
    gemm_sync<128, 128, 1, 0><<<dim3(128, 2, 4), 256>>>(Wq, x, bq, qt, 256, 256, HWP);
    gemm_sync<128, 128, 1, 0><<<dim3(128, 2, 4), 256>>>(Wk, y, bk, kt, 256, 256, HWP);
    gemm_sync<128, 128, 1, 4><<<dim3(128, 2, 4), 256>>>(Wv, y, bv, vt, 256, 256, HWP);

    const int splits[4] = {1, 1, 8, 64};
    for (int s = 0; s < 4; s++) {
        int l = s + 1;
        int n = 16384 >> (2 * l);
        int d = 64 << (2 * l);
        int sp = splits[s];
        int kper = d / sp;
        int soff = s << 20;
        float alpha = 1.0f / sqrtf((float)d);
        if (s < 3) {
            gemm_async<128, 128, 1><<<dim3(n / 128, n / 128, 4 * sp), 256, shm128>>>(
                qt, kt, S, kper, d, d, sp, kper, soff, n, s);
        } else {
            gemm_async<64, 64, 1><<<dim3(1, 1, 4 * sp), 256, shm64>>>(
                qt, kt, S, kper, d, d, sp, kper, soff, n, s);
        }
        k_softmax<<<dim3(n, 4), 256>>>(S, n, sp, alpha);
        if (s < 3) {
            gemm_async<128, 128, 2><<<dim3(d / 128, n / 128, 4), 256, shm128>>>(
                S, vt, attn, n, n, n, sp, 0, soff, n, s);
        } else {
            gemm_async<64, 64, 2><<<dim3(d / 64, n / 64, 4), 256, shm64>>>(
                S, vt, attn, n, n, n, sp, 0, soff, n, s);
        }
    }

    // conv3x3 implicit GEMM -> d_out
    gemm_sync<128, 128, 2, 3><<<dim3(128, 2, 4), 256>>>(Wo, attn, bo, out, 2304, 2304, 0);

    k_stats<<<256, 256>>>(out, meanv, rstdv);
    k_final<<<16384, 1024>>>(out, meanv, rstdv, gamma, beta);
}

// round 4
// speedup vs baseline: 2.7740x; 1.0964x over previous
#include <cuda_runtime.h>
#include <math.h>
#include <stdint.h>

#define BATCH 4
#define HWP 16384
#define CHW 4194304
#define TOKB 4194304
#define KC 16
#define RP 20
#define ST 4

// ---------------- scratch ----------------
__device__ float g_qt[BATCH * TOKB];
__device__ float g_kt[BATCH * TOKB];
__device__ float g_vt[BATCH * TOKB];   // V transposed token layout [scale][d][n]
__device__ float g_S[67108864];
__device__ float g_attn[BATCH * TOKB];
__device__ float g_xT[BATCH * CHW];    // x transposed [b][pixel][chan], tf32
__device__ float g_yT[BATCH * CHW];
__device__ float g_WqR[65536];
__device__ float g_WkR[65536];
__device__ float g_WvR[65536];
__device__ float g_WoR[589824];
__device__ float g_mean[256];
__device__ float g_rstd[256];

// ---------------- helpers ----------------
__device__ __forceinline__ float rtf32(float x) {
    uint32_t u; asm("cvt.rna.tf32.f32 %0, %1;" : "=r"(u) : "f"(x));
    return __uint_as_float(u);
}
__device__ __forceinline__ void cpasync16(uint32_t dst, const float* src) {
    asm volatile("cp.async.cg.shared.global [%0], [%1], 16;" :: "r"(dst), "l"(src));
}
__device__ __forceinline__ void cpasync4z(uint32_t dst, const float* src, int srcsz) {
    asm volatile("cp.async.ca.shared.global [%0], [%1], 4, %2;" :: "r"(dst), "l"(src), "r"(srcsz));
}
__device__ __forceinline__ void ldsm4(uint32_t a, uint32_t& r0, uint32_t& r1, uint32_t& r2, uint32_t& r3) {
    asm volatile("ldmatrix.sync.aligned.m8n8.x4.shared.b16 {%0,%1,%2,%3}, [%4];"
                 : "=r"(r0), "=r"(r1), "=r"(r2), "=r"(r3) : "r"(a));
}
__device__ __forceinline__ void mma_tf32(float* c, const uint32_t* a, const uint32_t* b) {
    asm volatile("mma.sync.aligned.m16n8k8.row.col.f32.tf32.tf32.f32 "
                 "{%0,%1,%2,%3}, {%4,%5,%6,%7}, {%8,%9}, {%0,%1,%2,%3};"
                 : "+f"(c[0]), "+f"(c[1]), "+f"(c[2]), "+f"(c[3])
                 : "r"(a[0]), "r"(a[1]), "r"(a[2]), "r"(a[3]), "r"(b[0]), "r"(b[1]));
}
__device__ __forceinline__ void scatterTok(float* tok, int o, int p, float v) {
    int scl = o >> 6, cl = o & 63, l = scl + 1;
    int msk = (1 << l) - 1;
    int yy = p >> 7, xx = p & 127;
    int wy = yy >> l, py = yy & msk, wx = xx >> l, px = xx & msk;
    int n = (wy << (7 - l)) | wx;
    int d = (cl << (2 * l)) | (py << l) | px;
    tok[(scl << 20) + (size_t)n * (64 << (2 * l)) + d] = v;
}
__device__ __forceinline__ void scatterTokT(float* tok, int o, int p, float v) {
    int scl = o >> 6, cl = o & 63, l = scl + 1;
    int msk = (1 << l) - 1;
    int yy = p >> 7, xx = p & 127;
    int wy = yy >> l, py = yy & msk, wx = xx >> l, px = xx & msk;
    int n = (wy << (7 - l)) | wx;
    int d = (cl << (2 * l)) | (py << l) | px;
    int nTokS = 16384 >> (2 * l);
    tok[(scl << 20) + (size_t)d * nTokS + n] = v;
}
__device__ __forceinline__ void scatterImg(float* img, int b, int scale, int row, int col, float v) {
    int l = scale + 1;
    int owlog = 7 - l;
    int wy = row >> owlog, wx = row & ((1 << owlog) - 1);
    int cl = col >> (2 * l);
    int r = col & ((1 << (2 * l)) - 1);
    int py = r >> l, px = r & ((1 << l) - 1);
    int y = (wy << l) | py, x = (wx << l) | px;
    int c = (scale << 6) | cl;
    img[(((size_t)b * 256 + c) << 14) + (y << 7) + x] = v;
}

// ================= unified async tf32 GEMM (all operands pre-rounded tf32 in gmem) ====
// MODE 0: proj -> token layout (+bias, round)
// MODE 4: proj -> transposed token layout (+bias, round)   [V]
// MODE 1: scores Q@K^T split-K partials -> S
// MODE 2: P@V -> image layout (round)
// MODE 3: conv3x3 implicit GEMM -> image (+bias, fp32)
// LOADB 0: B rows row-major [n][ldb] cp.async 16B; LOADB 2: conv shifted-image zfill loader
template<int BM, int BN, int LOADB, int MODE>
__global__ __launch_bounds__(256) void gemm_async(
    const float* __restrict__ A, const float* __restrict__ B,
    const float* __restrict__ bias, float* __restrict__ C,
    int Kloop, int lda, int ldb,
    int split, int kper, int soff, int nTok, int scale)
{
    constexpr int WM = BM / 2, WN = BN / 4;
    constexpr int MT = WM / 16, NT = WN / 8, NTP = WN / 16;
    extern __shared__ float dynsmem[];
    float* Asm = dynsmem;
    float* Bsm = dynsmem + ST * BM * RP;

    int tid = threadIdx.x;
    int lane = tid & 31, wid = tid >> 5;
    int wm = wid >> 2, wn = wid & 3;
    int m0 = blockIdx.y * BM, n0 = blockIdx.x * BN;

    const float* Ab; const float* Bb;
    int bidx, z = 0;
    if constexpr (MODE == 1) {
        z = blockIdx.z; bidx = z / split; int sp = z - bidx * split;
        Ab = A + (size_t)bidx * TOKB + soff + (size_t)sp * kper;
        Bb = B + (size_t)bidx * TOKB + soff + (size_t)sp * kper;
    } else if constexpr (MODE == 2) {
        bidx = blockIdx.z;
        Ab = A + (size_t)bidx * split * nTok * nTok;
        Bb = B + (size_t)bidx * TOKB + soff;
    } else {
        bidx = blockIdx.z;
        Ab = A;
        Bb = B + (size_t)bidx * CHW;
    }

    constexpr int APER = (BM * KC / 4) / 256;
    constexpr int BPER = (BN * KC / 4) / 256;
    uint32_t sA = (uint32_t)__cvta_generic_to_shared(Asm);
    uint32_t sB = (uint32_t)__cvta_generic_to_shared(Bsm);
    constexpr uint32_t ASTR = BM * RP * 4, BSTR = BN * RP * 4;
    int nc = Kloop / KC;

    auto issue = [&](int c) {
        int st = c % ST;
        int k0 = c * KC;
#pragma unroll
        for (int j = 0; j < APER; j++) {
            int i = tid + j * 256;
            int row = i >> 2, seg = (i & 3) << 2;
            cpasync16(sA + st * ASTR + (uint32_t)(row * RP + seg) * 4,
                      Ab + (size_t)(m0 + row) * lda + k0 + seg);
        }
        if constexpr (LOADB == 0) {
#pragma unroll
            for (int j = 0; j < BPER; j++) {
                int i = tid + j * 256;
                int row = i >> 2, seg = (i & 3) << 2;
                cpasync16(sB + st * BSTR + (uint32_t)(row * RP + seg) * 4,
                          Bb + (size_t)(n0 + row) * ldb + k0 + seg);
            }
        } else {
            // conv loader: BN must be 128 (one image row), blockIdx.x = y
            int kl = tid >> 4, x0 = (tid & 15) << 3;
            int k = k0 + kl;
            int c9 = k / 9, tap = k - c9 * 9;
            int dy = tap / 3, dx = tap - dy * 3;
            int gy = (int)blockIdx.x + dy - 1;
            const float* src = Bb + (size_t)c9 * HWP + gy * 128;
            bool okY = (unsigned)gy < 128u;
#pragma unroll
            for (int i = 0; i < 8; i++) {
                int gx = x0 + i + dx - 1;
                int sz = (okY && (unsigned)gx < 128u) ? 4 : 0;
                cpasync4z(sB + st * BSTR + (uint32_t)((x0 + i) * RP + kl) * 4, src + gx, sz);
            }
        }
    };

    float acc[MT][NT][4];
#pragma unroll
    for (int i = 0; i < MT; i++)
#pragma unroll
        for (int j = 0; j < NT; j++)
#pragma unroll
            for (int e = 0; e < 4; e++) acc[i][j][e] = 0.f;

    int r8 = lane & 7, hi8 = (lane >> 3) & 1, hi16 = (lane >> 4) & 1;
    uint32_t aOff = (uint32_t)((wm * WM + r8 + hi8 * 8) * RP * 4 + hi16 * 16);
    uint32_t bOff = (uint32_t)((wn * WN + r8 + hi8 * 8) * RP * 4 + hi16 * 16);

    if (0 < nc) issue(0);
    asm volatile("cp.async.commit_group;");
    if (1 < nc) issue(1);
    asm volatile("cp.async.commit_group;");
    if (2 < nc) issue(2);
    asm volatile("cp.async.commit_group;");

    for (int c = 0; c < nc; c++) {
        asm volatile("cp.async.wait_group 2;");
        __syncthreads();
        {
            int st = c % ST;
            uint32_t sa = sA + st * ASTR, sb = sB + st * BSTR;
#pragma unroll
            for (int ks = 0; ks < KC / 8; ks++) {
                uint32_t af[MT][4], bf[NTP][4];
#pragma unroll
                for (int mt = 0; mt < MT; mt++)
                    ldsm4(sa + aOff + mt * 16 * RP * 4 + ks * 32, af[mt][0], af[mt][1], af[mt][2], af[mt][3]);
#pragma unroll
                for (int np = 0; np < NTP; np++)
                    ldsm4(sb + bOff + np * 16 * RP * 4 + ks * 32, bf[np][0], bf[np][1], bf[np][2], bf[np][3]);
#pragma unroll
                for (int mt = 0; mt < MT; mt++)
#pragma unroll
                    for (int np = 0; np < NTP; np++) {
                        uint32_t b0[2] = { bf[np][0], bf[np][2] };
                        uint32_t b1[2] = { bf[np][1], bf[np][3] };
                        mma_tf32(acc[mt][np * 2 + 0], af[mt], b0);
                        mma_tf32(acc[mt][np * 2 + 1], af[mt], b1);
                    }
            }
        }
        if (c + 3 < nc) issue(c + 3);
        asm volatile("cp.async.commit_group;");
    }

    // epilogue
    int g = lane >> 2, q2 = (lane & 3) << 1;
#pragma unroll
    for (int mt = 0; mt < MT; mt++) {
        int row0 = m0 + wm * WM + mt * 16 + g;
#pragma unroll
        for (int e2 = 0; e2 < 2; e2++) {
            int row = row0 + e2 * 8;
            float bia = 0.f;
            if constexpr (MODE == 0 || MODE == 3 || MODE == 4) bia = __ldg(&bias[row]);
#pragma unroll
            for (int nt = 0; nt < NT; nt++) {
                int col = n0 + wn * WN + nt * 8 + q2;
                float v0 = acc[mt][nt][e2 * 2 + 0] + bia;
                float v1 = acc[mt][nt][e2 * 2 + 1] + bia;
                if constexpr (MODE == 1) {
                    *(float2*)&C[(size_t)z * nTok * nTok + (size_t)row * nTok + col] = make_float2(v0, v1);
                } else if constexpr (MODE == 0) {
                    float* tok = C + (size_t)bidx * TOKB;
                    scatterTok(tok, row, col, rtf32(v0));
                    scatterTok(tok, row, col + 1, rtf32(v1));
                } else if constexpr (MODE == 4) {
                    float* tok = C + (size_t)bidx * TOKB;
                    scatterTokT(tok, row, col, rtf32(v0));
                    scatterTokT(tok, row, col + 1, rtf32(v1));
                } else if constexpr (MODE == 2) {
                    scatterImg(C, bidx, scale, row, col, rtf32(v0));
                    scatterImg(C, bidx, scale, row, col + 1, rtf32(v1));
                } else {
                    size_t adr = (((size_t)bidx * 256 + row) << 14) + col;
                    *(float2*)&C[adr] = make_float2(v0, v1);
                }
            }
        }
    }
}

// ---------------- prep: round-copy (weights) ----------------
__global__ void k_round(const float* __restrict__ s, float* __restrict__ d, int n)
{
    int i = blockIdx.x * 256 + threadIdx.x;
    if (i < n) d[i] = rtf32(s[i]);
}

// ---------------- prep: transpose [b][256][16384] -> [b][16384][256] + round ----------------
__global__ void k_transpose(const float* __restrict__ src, float* __restrict__ dst)
{
    __shared__ float t[32][33];
    int b = blockIdx.z;
    const float* s = src + (size_t)b * CHW;
    float* d = dst + (size_t)b * CHW;
    int x = blockIdx.x * 32 + threadIdx.x;   // pixel
    int yc = blockIdx.y * 32 + threadIdx.y;  // channel
#pragma unroll
    for (int j = 0; j < 4; j++)
        t[threadIdx.y + j * 8][threadIdx.x] = s[(size_t)(yc + j * 8) * HWP + x];
    __syncthreads();
    int x2 = blockIdx.y * 32 + threadIdx.x;  // channel
    int y2 = blockIdx.x * 32 + threadIdx.y;  // pixel
#pragma unroll
    for (int j = 0; j < 4; j++)
        d[(size_t)(y2 + j * 8) * 256 + x2] = rtf32(t[threadIdx.x][threadIdx.y + j * 8]);
}

// ---------------- softmax (fuses split-K reduction, rounds P to tf32) ----------------
__global__ void k_softmax(float* __restrict__ S, int nTok, int split, float alpha)
{
    __shared__ float rowb[4096];
    __shared__ float red[256];
    int row = blockIdx.x;
    size_t bb = (size_t)blockIdx.y * split * nTok * nTok;
    int tid = threadIdx.x;
    float mx = -1e30f;
    for (int j = tid; j < nTok; j += 256) {
        float s = 0.f;
        for (int sp = 0; sp < split; sp++)
            s += S[bb + ((size_t)sp * nTok + row) * nTok + j];
        s *= alpha;
        rowb[j] = s;
        mx = fmaxf(mx, s);
    }
    red[tid] = mx; __syncthreads();
    for (int st = 128; st; st >>= 1) { if (tid < st) red[tid] = fmaxf(red[tid], red[tid + st]); __syncthreads(); }
    mx = red[0]; __syncthreads();
    float sum = 0.f;
    for (int j = tid; j < nTok; j += 256) {
        float e = __expf(rowb[j] - mx);
        rowb[j] = e; sum += e;
    }
    red[tid] = sum; __syncthreads();
    for (int st = 128; st; st >>= 1) { if (tid < st) red[tid] += red[tid + st]; __syncthreads(); }
    float inv = 1.0f / red[0];
    size_t ob = bb + (size_t)row * nTok;
    for (int j = tid; j < nTok; j += 256)
        S[ob + j] = rtf32(rowb[j] * inv);
}

// ---------------- batchnorm stats ----------------
__global__ void k_stats(const float* __restrict__ z, float* __restrict__ meanv, float* __restrict__ rstdv)
{
    __shared__ float rs[256], rs2[256];
    int c = blockIdx.x;
    int tid = threadIdx.x;
    float s = 0.f, s2 = 0.f;
    for (int i = tid; i < 65536; i += 256) {
        int b = i >> 14, p = i & 16383;
        float v = z[(((size_t)b * 256 + c) << 14) + p];
        s += v; s2 += v * v;
    }
    rs[tid] = s; rs2[tid] = s2; __syncthreads();
    for (int st = 128; st; st >>= 1) {
        if (tid < st) { rs[tid] += rs[tid + st]; rs2[tid] += rs2[tid + st]; }
        __syncthreads();
    }
    if (tid == 0) {
        float m = rs[0] * (1.0f / 65536.0f);
        float var = rs2[0] * (1.0f / 65536.0f) - m * m;
        meanv[c] = m;
        rstdv[c] = rsqrtf(var + 1e-5f);
    }
}

// ---------------- normalize + affine + LeakyReLU ----------------
__global__ void k_final(float* __restrict__ z, const float* __restrict__ meanv, const float* __restrict__ rstdv,
                        const float* __restrict__ gamma, const float* __restrict__ beta)
{
    size_t idx = (size_t)blockIdx.x * 1024 + threadIdx.x;
    int c = (int)((idx >> 14) & 255);
    float v = z[idx];
    v = (v - __ldg(&meanv[c])) * __ldg(&rstdv[c]) * __ldg(&gamma[c]) + __ldg(&beta[c]);
    z[idx] = v >= 0.f ? v : 0.2f * v;
}

// ---------------- host launch ----------------
extern "C" void kernel_launch(void* const* d_in, const int* in_sizes, int n_in,
                              void* d_out, int out_size)
{
    (void)in_sizes; (void)n_in; (void)out_size;
    const float* x     = (const float*)d_in[0];
    const float* y     = (const float*)d_in[1];
    const float* Wq    = (const float*)d_in[2];
    const float* bq    = (const float*)d_in[3];
    const float* Wk    = (const float*)d_in[4];
    const float* bk    = (const float*)d_in[5];
    const float* Wv    = (const float*)d_in[6];
    const float* bv    = (const float*)d_in[7];
    const float* Wo    = (const float*)d_in[8];
    const float* bo    = (const float*)d_in[9];
    const float* gamma = (const float*)d_in[10];
    const float* beta  = (const float*)d_in[11];
    float* out = (float*)d_out;

    float *qt, *kt, *vt, *S, *attn, *xT, *yT, *WqR, *WkR, *WvR, *WoR, *meanv, *rstdv;
    cudaGetSymbolAddress((void**)&qt,    g_qt);
    cudaGetSymbolAddress((void**)&kt,    g_kt);
    cudaGetSymbolAddress((void**)&vt,    g_vt);
    cudaGetSymbolAddress((void**)&S,     g_S);
    cudaGetSymbolAddress((void**)&attn,  g_attn);
    cudaGetSymbolAddress((void**)&xT,    g_xT);
    cudaGetSymbolAddress((void**)&yT,    g_yT);
    cudaGetSymbolAddress((void**)&WqR,   g_WqR);
    cudaGetSymbolAddress((void**)&WkR,   g_WkR);
    cudaGetSymbolAddress((void**)&WvR,   g_WvR);
    cudaGetSymbolAddress((void**)&WoR,   g_WoR);
    cudaGetSymbolAddress((void**)&meanv, g_mean);
    cudaGetSymbolAddress((void**)&rstdv, g_rstd);

    const int shm128 = ST * (128 + 128) * RP * 4;   // 81920
    const int shm64  = ST * (64 + 64) * RP * 4;     // 40960
    cudaFuncSetAttribute(gemm_async<128, 128, 0, 0>, cudaFuncAttributeMaxDynamicSharedMemorySize, shm128);
    cudaFuncSetAttribute(gemm_async<128, 128, 0, 4>, cudaFuncAttributeMaxDynamicSharedMemorySize, shm128);
    cudaFuncSetAttribute(gemm_async<128, 128, 0, 1>, cudaFuncAttributeMaxDynamicSharedMemorySize, shm128);
    cudaFuncSetAttribute(gemm_async<128, 128, 0, 2>, cudaFuncAttributeMaxDynamicSharedMemorySize, shm128);
    cudaFuncSetAttribute(gemm_async<64, 64, 0, 1>,   cudaFuncAttributeMaxDynamicSharedMemorySize, shm64);
    cudaFuncSetAttribute(gemm_async<64, 64, 0, 2>,   cudaFuncAttributeMaxDynamicSharedMemorySize, shm64);
    cudaFuncSetAttribute(gemm_async<128, 128, 2, 3>, cudaFuncAttributeMaxDynamicSharedMemorySize, shm128);

    // ---- prep: round weights, transpose+round inputs ----
    k_round<<<256, 256>>>(Wq, WqR, 65536);
    k_round<<<256, 256>>>(Wk, WkR, 65536);
    k_round<<<256, 256>>>(Wv, WvR, 65536);
    k_round<<<2304, 256>>>(Wo, WoR, 589824);
    k_transpose<<<dim3(512, 8, 4), dim3(32, 8)>>>(x, xT);
    k_transpose<<<dim3(512, 8, 4), dim3(32, 8)>>>(y, yT);

    // ---- projections (async) ----
    gemm_async<128, 128, 0, 0><<<dim3(128, 2, 4), 256, shm128>>>(WqR, xT, bq, qt, 256, 256, 256, 0, 0, 0, 0, 0);
    gemm_async<128, 128, 0, 0><<<dim3(128, 2, 4), 256, shm128>>>(WkR, yT, bk, kt, 256, 256, 256, 0, 0, 0, 0, 0);
    gemm_async<128, 128, 0, 4><<<dim3(128, 2, 4), 256, shm128>>>(WvR, yT, bv, vt, 256, 256, 256, 0, 0, 0, 0, 0);

    const int splits[4] = {1, 1, 8, 64};
    for (int s = 0; s < 4; s++) {
        int l = s + 1;
        int n = 16384 >> (2 * l);
        int d = 64 << (2 * l);
        int sp = splits[s];
        int kper = d / sp;
        int soff = s << 20;
        float alpha = 1.0f / sqrtf((float)d);
        if (s < 3) {
            gemm_async<128, 128, 0, 1><<<dim3(n / 128, n / 128, 4 * sp), 256, shm128>>>(
                qt, kt, nullptr, S, kper, d, d, sp, kper, soff, n, s);
        } else {
            gemm_async<64, 64, 0, 1><<<dim3(1, 1, 4 * sp), 256, shm64>>>(
                qt, kt, nullptr, S, kper, d, d, sp, kper, soff, n, s);
        }
        k_softmax<<<dim3(n, 4), 256>>>(S, n, sp, alpha);
        if (s < 3) {
            gemm_async<128, 128, 0, 2><<<dim3(d / 128, n / 128, 4), 256, shm128>>>(
                S, vt, nullptr, attn, n, n, n, sp, 0, soff, n, s);
        } else {
            gemm_async<64, 64, 0, 2><<<dim3(d / 64, n / 64, 4), 256, shm64>>>(
                S, vt, nullptr, attn, n, n, n, sp, 0, soff, n, s);
        }
    }

    // ---- conv3x3 implicit GEMM (async, zero-fill halo) -> d_out ----
    gemm_async<128, 128, 2, 3><<<dim3(128, 2, 4), 256, shm128>>>(WoR, attn, bo, out, 2304, 2304, 0, 0, 0, 0, 0, 0);

    k_stats<<<256, 256>>>(out, meanv, rstdv);
    k_final<<<16384, 1024>>>(out, meanv, rstdv, gamma, beta);
}

// round 6
// speedup vs baseline: 3.5273x; 1.2716x over previous
#include <cuda_runtime.h>
#include <math.h>
#include <stdint.h>

#define BATCH 4
#define HWP 16384
#define CHW 4194304
#define TOKB 4194304
#define KC 32
#define RP 36
#define ST 3

// ---------------- scratch ----------------
__device__ float g_qt[BATCH * TOKB];
__device__ float g_kt[BATCH * TOKB];
__device__ float g_vt[BATCH * TOKB];    // V transposed token layout [scale][d][n]
__device__ float g_S[67108864];
__device__ float g_attnT[BATCH * CHW];  // attention out, [b][pixel][channel], tf32
__device__ float g_xT[BATCH * CHW];     // [b][pixel][chan], tf32
__device__ float g_yT[BATCH * CHW];
__device__ float g_WqR[65536];
__device__ float g_WkR[65536];
__device__ float g_WvR[65536];
__device__ float g_WoR[589824];         // [o][tap*256+c], tf32
__device__ float g_mean[256];
__device__ float g_rstd[256];

// ---------------- helpers ----------------
__device__ __forceinline__ float rtf32(float x) {
    uint32_t u; asm("cvt.rna.tf32.f32 %0, %1;" : "=r"(u) : "f"(x));
    return __uint_as_float(u);
}
__device__ __forceinline__ void cpasync16(uint32_t dst, const float* src) {
    asm volatile("cp.async.cg.shared.global [%0], [%1], 16;" :: "r"(dst), "l"(src));
}
__device__ __forceinline__ void cpasync16z(uint32_t dst, const float* src, int srcsz) {
    asm volatile("cp.async.cg.shared.global [%0], [%1], 16, %2;" :: "r"(dst), "l"(src), "r"(srcsz));
}
__device__ __forceinline__ void ldsm4(uint32_t a, uint32_t& r0, uint32_t& r1, uint32_t& r2, uint32_t& r3) {
    asm volatile("ldmatrix.sync.aligned.m8n8.x4.shared.b16 {%0,%1,%2,%3}, [%4];"
                 : "=r"(r0), "=r"(r1), "=r"(r2), "=r"(r3) : "r"(a));
}
__device__ __forceinline__ void mma_tf32(float* c, const uint32_t* a, const uint32_t* b) {
    asm volatile("mma.sync.aligned.m16n8k8.row.col.f32.tf32.tf32.f32 "
                 "{%0,%1,%2,%3}, {%4,%5,%6,%7}, {%8,%9}, {%0,%1,%2,%3};"
                 : "+f"(c[0]), "+f"(c[1]), "+f"(c[2]), "+f"(c[3])
                 : "r"(a[0]), "r"(a[1]), "r"(a[2]), "r"(a[3]), "r"(b[0]), "r"(b[1]));
}
__device__ __forceinline__ void scatterTok(float* tok, int o, int p, float v) {
    int scl = o >> 6, cl = o & 63, l = scl + 1;
    int msk = (1 << l) - 1;
    int yy = p >> 7, xx = p & 127;
    int wy = yy >> l, py = yy & msk, wx = xx >> l, px = xx & msk;
    int n = (wy << (7 - l)) | wx;
    int d = (cl << (2 * l)) | (py << l) | px;
    tok[(scl << 20) + (size_t)n * (64 << (2 * l)) + d] = v;
}
__device__ __forceinline__ void scatterTokT(float* tok, int o, int p, float v) {
    int scl = o >> 6, cl = o & 63, l = scl + 1;
    int msk = (1 << l) - 1;
    int yy = p >> 7, xx = p & 127;
    int wy = yy >> l, py = yy & msk, wx = xx >> l, px = xx & msk;
    int n = (wy << (7 - l)) | wx;
    int d = (cl << (2 * l)) | (py << l) | px;
    int nTokS = 16384 >> (2 * l);
    tok[(scl << 20) + (size_t)d * nTokS + n] = v;
}
// write to attnT [b][pixel][channel]
__device__ __forceinline__ void scatterImgT(float* img, int b, int scale, int row, int col, float v) {
    int l = scale + 1;
    int owlog = 7 - l;
    int wy = row >> owlog, wx = row & ((1 << owlog) - 1);
    int cl = col >> (2 * l);
    int r = col & ((1 << (2 * l)) - 1);
    int py = r >> l, px = r & ((1 << l) - 1);
    int y = (wy << l) | py, x = (wx << l) | px;
    int c = (scale << 6) | cl;
    img[(((size_t)b << 14) + (y << 7) + x) * 256 + c] = v;
}

// ================= unified async tf32 GEMM (operands tf32 in gmem) ====
// MODE 0: proj -> token layout (+bias, round)
// MODE 4: proj -> transposed token layout (+bias, round)  [V]
// MODE 1: scores split-K partials -> S
// MODE 2: P@V -> attnT [pixel][channel] (round)
// MODE 3: conv3x3 tap-GEMM -> out image (+bias, fp32)
// LOADB 0: B rows row-major [n][ldb]; LOADB 2: conv shifted-pixel loader over attnT
template<int BM, int BN, int LOADB, int MODE>
__global__ __launch_bounds__(256) void gemm_async(
    const float* __restrict__ A, const float* __restrict__ B,
    const float* __restrict__ bias, float* __restrict__ C,
    int Kloop, int lda, int ldb,
    int split, int kper, int soff, int nTok, int scale)
{
    constexpr int WM = BM / 2, WN = BN / 4;
    constexpr int MT = WM / 16, NT = WN / 8, NTP = WN / 16;
    extern __shared__ float dynsmem[];
    float* Asm = dynsmem;
    float* Bsm = dynsmem + ST * BM * RP;

    int tid = threadIdx.x;
    int lane = tid & 31, wid = tid >> 5;
    int wm = wid >> 2, wn = wid & 3;
    int m0 = blockIdx.y * BM, n0 = blockIdx.x * BN;

    const float* Ab; const float* Bb;
    int bidx, z = 0;
    if constexpr (MODE == 1) {
        z = blockIdx.z; bidx = z / split; int sp = z - bidx * split;
        Ab = A + (size_t)bidx * TOKB + soff + (size_t)sp * kper;
        Bb = B + (size_t)bidx * TOKB + soff + (size_t)sp * kper;
    } else if constexpr (MODE == 2) {
        bidx = blockIdx.z;
        Ab = A + (size_t)bidx * split * nTok * nTok;
        Bb = B + (size_t)bidx * TOKB + soff;
    } else {
        bidx = blockIdx.z;
        Ab = A;
        Bb = B + (size_t)bidx * CHW;
    }

    constexpr int APER = (BM * KC / 4) / 256;
    constexpr int BPER = (BN * KC / 4) / 256;
    constexpr int SEGR = KC / 4;   // 16B segments per row
    uint32_t sA = (uint32_t)__cvta_generic_to_shared(Asm);
    uint32_t sB = (uint32_t)__cvta_generic_to_shared(Bsm);
    constexpr uint32_t ASTR = BM * RP * 4, BSTR = BN * RP * 4;
    int nc = Kloop / KC;

    auto issue = [&](int c) {
        int st = c % ST;
        int k0 = c * KC;
#pragma unroll
        for (int j = 0; j < APER; j++) {
            int i = tid + j * 256;
            int row = i / SEGR, seg = (i % SEGR) << 2;
            cpasync16(sA + st * ASTR + (uint32_t)(row * RP + seg) * 4,
                      Ab + (size_t)(m0 + row) * lda + k0 + seg);
        }
        if constexpr (LOADB == 0) {
#pragma unroll
            for (int j = 0; j < BPER; j++) {
                int i = tid + j * 256;
                int row = i / SEGR, seg = (i % SEGR) << 2;
                cpasync16(sB + st * BSTR + (uint32_t)(row * RP + seg) * 4,
                          Bb + (size_t)(n0 + row) * ldb + k0 + seg);
            }
        } else {
            // conv loader over attnT: BN=128 pixels (one image row y=blockIdx.x)
            // K ordering: k = tap*256 + channel; tap uniform per 32-chunk
            int tap = k0 >> 8;
            int dy = tap / 3, dx = tap - dy * 3;
            int gy = (int)blockIdx.x + dy - 1;
            bool okY = (unsigned)gy < 128u;
#pragma unroll
            for (int j = 0; j < BPER; j++) {
                int i = tid + j * 256;
                int xrow = i / SEGR, seg = (i % SEGR) << 2;
                int ch = (k0 & 255) + seg;
                int gx = xrow + dx - 1;
                int sz = (okY && (unsigned)gx < 128u) ? 16 : 0;
                const float* src = Bb + ((size_t)(gy << 7) + gx) * 256 + ch;
                cpasync16z(sB + st * BSTR + (uint32_t)(xrow * RP + seg) * 4, src, sz);
            }
        }
    };

    float acc[MT][NT][4];
#pragma unroll
    for (int i = 0; i < MT; i++)
#pragma unroll
        for (int j = 0; j < NT; j++)
#pragma unroll
            for (int e = 0; e < 4; e++) acc[i][j][e] = 0.f;

    int r8 = lane & 7, hi8 = (lane >> 3) & 1, hi16 = (lane >> 4) & 1;
    uint32_t aOff = (uint32_t)((wm * WM + r8 + hi8 * 8) * RP * 4 + hi16 * 16);
    uint32_t bOff = (uint32_t)((wn * WN + r8 + hi8 * 8) * RP * 4 + hi16 * 16);

    if (0 < nc) issue(0);
    asm volatile("cp.async.commit_group;");
    if (1 < nc) issue(1);
    asm volatile("cp.async.commit_group;");

    for (int c = 0; c < nc; c++) {
        asm volatile("cp.async.wait_group 1;");
        __syncthreads();
        {
            int st = c % ST;
            uint32_t sa = sA + st * ASTR, sb = sB + st * BSTR;
#pragma unroll
            for (int ks = 0; ks < KC / 8; ks++) {
                uint32_t af[MT][4], bf[NTP][4];
#pragma unroll
                for (int mt = 0; mt < MT; mt++)
                    ldsm4(sa + aOff + mt * 16 * RP * 4 + ks * 32, af[mt][0], af[mt][1], af[mt][2], af[mt][3]);
#pragma unroll
                for (int np = 0; np < NTP; np++)
                    ldsm4(sb + bOff + np * 16 * RP * 4 + ks * 32, bf[np][0], bf[np][1], bf[np][2], bf[np][3]);
#pragma unroll
                for (int mt = 0; mt < MT; mt++)
#pragma unroll
                    for (int np = 0; np < NTP; np++) {
                        uint32_t b0[2] = { bf[np][0], bf[np][2] };
                        uint32_t b1[2] = { bf[np][1], bf[np][3] };
                        mma_tf32(acc[mt][np * 2 + 0], af[mt], b0);
                        mma_tf32(acc[mt][np * 2 + 1], af[mt], b1);
                    }
            }
        }
        if (c + 2 < nc) issue(c + 2);
        asm volatile("cp.async.commit_group;");
    }

    // epilogue
    int g = lane >> 2, q2 = (lane & 3) << 1;
#pragma unroll
    for (int mt = 0; mt < MT; mt++) {
        int row0 = m0 + wm * WM + mt * 16 + g;
#pragma unroll
        for (int e2 = 0; e2 < 2; e2++) {
            int row = row0 + e2 * 8;
            float bia = 0.f;
            if constexpr (MODE == 0 || MODE == 3 || MODE == 4) bia = __ldg(&bias[row]);
#pragma unroll
            for (int nt = 0; nt < NT; nt++) {
                int col = n0 + wn * WN + nt * 8 + q2;
                float v0 = acc[mt][nt][e2 * 2 + 0] + bia;
                float v1 = acc[mt][nt][e2 * 2 + 1] + bia;
                if constexpr (MODE == 1) {
                    *(float2*)&C[(size_t)z * nTok * nTok + (size_t)row * nTok + col] = make_float2(v0, v1);
                } else if constexpr (MODE == 0) {
                    float* tok = C + (size_t)bidx * TOKB;
                    scatterTok(tok, row, col, rtf32(v0));
                    scatterTok(tok, row, col + 1, rtf32(v1));
                } else if constexpr (MODE == 4) {
                    float* tok = C + (size_t)bidx * TOKB;
                    scatterTokT(tok, row, col, rtf32(v0));
                    scatterTokT(tok, row, col + 1, rtf32(v1));
                } else if constexpr (MODE == 2) {
                    scatterImgT(C, bidx, scale, row, col, rtf32(v0));
                    scatterImgT(C, bidx, scale, row, col + 1, rtf32(v1));
                } else {
                    // MODE 3: out[b][o][pixel]; col == y*128 + x  (n0 = blockIdx.x*128 = y*128)
                    size_t adr = (((size_t)bidx * 256 + row) << 14) + col;
                    *(float2*)&C[adr] = make_float2(v0, v1);
                }
            }
        }
    }
}

// ---------------- prep: round-copy (1x1 weights) ----------------
__global__ void k_round(const float* __restrict__ s, float* __restrict__ d, int n)
{
    int i = blockIdx.x * 256 + threadIdx.x;
    if (i < n) d[i] = rtf32(s[i]);
}

// ---------------- prep: repack Wo [o][c][3][3] -> [o][tap*256+c], tf32 ----------------
__global__ void k_packWo(const float* __restrict__ s, float* __restrict__ d)
{
    int i = blockIdx.x * 256 + threadIdx.x;
    if (i < 589824) {
        int o = i / 2304, r = i - o * 2304;
        int tap = r >> 8, c = r & 255;
        d[i] = rtf32(s[((size_t)o * 256 + c) * 9 + tap]);
    }
}

// ---------------- prep: transpose [b][256][16384] -> [b][16384][256] + round ----------------
__global__ void k_transpose(const float* __restrict__ src, float* __restrict__ dst)
{
    __shared__ float t[32][33];
    int b = blockIdx.z;
    const float* s = src + (size_t)b * CHW;
    float* d = dst + (size_t)b * CHW;
    int x = blockIdx.x * 32 + threadIdx.x;
    int yc = blockIdx.y * 32 + threadIdx.y;
#pragma unroll
    for (int j = 0; j < 4; j++)
        t[threadIdx.y + j * 8][threadIdx.x] = s[(size_t)(yc + j * 8) * HWP + x];
    __syncthreads();
    int x2 = blockIdx.y * 32 + threadIdx.x;
    int y2 = blockIdx.x * 32 + threadIdx.y;
#pragma unroll
    for (int j = 0; j < 4; j++)
        d[(size_t)(y2 + j * 8) * 256 + x2] = rtf32(t[threadIdx.x][threadIdx.y + j * 8]);
}

// ---------------- softmax (fuses split-K reduction, rounds P) ----------------
__global__ void k_softmax(float* __restrict__ S, int nTok, int split, float alpha)
{
    __shared__ float rowb[4096];
    __shared__ float red[256];
    int row = blockIdx.x;
    size_t bb = (size_t)blockIdx.y * split * nTok * nTok;
    int tid = threadIdx.x;
    float mx = -1e30f;
    for (int j = tid; j < nTok; j += 256) {
        float s = 0.f;
        for (int sp = 0; sp < split; sp++)
            s += S[bb + ((size_t)sp * nTok + row) * nTok + j];
        s *= alpha;
        rowb[j] = s;
        mx = fmaxf(mx, s);
    }
    red[tid] = mx; __syncthreads();
    for (int st = 128; st; st >>= 1) { if (tid < st) red[tid] = fmaxf(red[tid], red[tid + st]); __syncthreads(); }
    mx = red[0]; __syncthreads();
    float sum = 0.f;
    for (int j = tid; j < nTok; j += 256) {
        float e = __expf(rowb[j] - mx);
        rowb[j] = e; sum += e;
    }
    red[tid] = sum; __syncthreads();
    for (int st = 128; st; st >>= 1) { if (tid < st) red[tid] += red[tid + st]; __syncthreads(); }
    float inv = 1.0f / red[0];
    size_t ob = bb + (size_t)row * nTok;
    for (int j = tid; j < nTok; j += 256)
        S[ob + j] = rtf32(rowb[j] * inv);
}

// ---------------- batchnorm stats ----------------
__global__ void k_stats(const float* __restrict__ z, float* __restrict__ meanv, float* __restrict__ rstdv)
{
    __shared__ float rs[256], rs2[256];
    int c = blockIdx.x;
    int tid = threadIdx.x;
    float s = 0.f, s2 = 0.f;
    for (int i = tid; i < 65536; i += 256) {
        int b = i >> 14, p = i & 16383;
        float v = z[(((size_t)b * 256 + c) << 14) + p];
        s += v; s2 += v * v;
    }
    rs[tid] = s; rs2[tid] = s2; __syncthreads();
    for (int st = 128; st; st >>= 1) {
        if (tid < st) { rs[tid] += rs[tid + st]; rs2[tid] += rs2[tid + st]; }
        __syncthreads();
    }
    if (tid == 0) {
        float m = rs[0] * (1.0f / 65536.0f);
        float var = rs2[0] * (1.0f / 65536.0f) - m * m;
        meanv[c] = m;
        rstdv[c] = rsqrtf(var + 1e-5f);
    }
}

// ---------------- normalize + affine + LeakyReLU ----------------
__global__ void k_final(float* __restrict__ z, const float* __restrict__ meanv, const float* __restrict__ rstdv,
                        const float* __restrict__ gamma, const float* __restrict__ beta)
{
    size_t idx = (size_t)blockIdx.x * 1024 + threadIdx.x;
    int c = (int)((idx >> 14) & 255);
    float v = z[idx];
    v = (v - __ldg(&meanv[c])) * __ldg(&rstdv[c]) * __ldg(&gamma[c]) + __ldg(&beta[c]);
    z[idx] = v >= 0.f ? v : 0.2f * v;
}

// ---------------- host launch ----------------
extern "C" void kernel_launch(void* const* d_in, const int* in_sizes, int n_in,
                              void* d_out, int out_size)
{
    (void)in_sizes; (void)n_in; (void)out_size;
    const float* x     = (const float*)d_in[0];
    const float* y     = (const float*)d_in[1];
    const float* Wq    = (const float*)d_in[2];
    const float* bq    = (const float*)d_in[3];
    const float* Wk    = (const float*)d_in[4];
    const float* bk    = (const float*)d_in[5];
    const float* Wv    = (const float*)d_in[6];
    const float* bv    = (const float*)d_in[7];
    const float* Wo    = (const float*)d_in[8];
    const float* bo    = (const float*)d_in[9];
    const float* gamma = (const float*)d_in[10];
    const float* beta  = (const float*)d_in[11];
    float* out = (float*)d_out;

    float *qt, *kt, *vt, *S, *attnT, *xT, *yT, *WqR, *WkR, *WvR, *WoR, *meanv, *rstdv;
    cudaGetSymbolAddress((void**)&qt,    g_qt);
    cudaGetSymbolAddress((void**)&kt,    g_kt);
    cudaGetSymbolAddress((void**)&vt,    g_vt);
    cudaGetSymbolAddress((void**)&S,     g_S);
    cudaGetSymbolAddress((void**)&attnT, g_attnT);
    cudaGetSymbolAddress((void**)&xT,    g_xT);
    cudaGetSymbolAddress((void**)&yT,    g_yT);
    cudaGetSymbolAddress((void**)&WqR,   g_WqR);
    cudaGetSymbolAddress((void**)&WkR,   g_WkR);
    cudaGetSymbolAddress((void**)&WvR,   g_WvR);
    cudaGetSymbolAddress((void**)&WoR,   g_WoR);
    cudaGetSymbolAddress((void**)&meanv, g_mean);
    cudaGetSymbolAddress((void**)&rstdv, g_rstd);

    const int shm128 = ST * (128 + 128) * RP * 4;   // 110592
    const int shm64  = ST * (64 + 64) * RP * 4;     // 55296
    cudaFuncSetAttribute(gemm_async<128, 128, 0, 0>, cudaFuncAttributeMaxDynamicSharedMemorySize, shm128);
    cudaFuncSetAttribute(gemm_async<128, 128, 0, 4>, cudaFuncAttributeMaxDynamicSharedMemorySize, shm128);
    cudaFuncSetAttribute(gemm_async<128, 128, 0, 1>, cudaFuncAttributeMaxDynamicSharedMemorySize, shm128);
    cudaFuncSetAttribute(gemm_async<128, 128, 0, 2>, cudaFuncAttributeMaxDynamicSharedMemorySize, shm128);
    cudaFuncSetAttribute(gemm_async<64, 64, 0, 1>,   cudaFuncAttributeMaxDynamicSharedMemorySize, shm64);
    cudaFuncSetAttribute(gemm_async<64, 64, 0, 2>,   cudaFuncAttributeMaxDynamicSharedMemorySize, shm64);
    cudaFuncSetAttribute(gemm_async<128, 128, 2, 3>, cudaFuncAttributeMaxDynamicSharedMemorySize, shm128);

    // ---- prep ----
    k_round<<<256, 256>>>(Wq, WqR, 65536);
    k_round<<<256, 256>>>(Wk, WkR, 65536);
    k_round<<<256, 256>>>(Wv, WvR, 65536);
    k_packWo<<<2304, 256>>>(Wo, WoR);
    k_transpose<<<dim3(512, 8, 4), dim3(32, 8)>>>(x, xT);
    k_transpose<<<dim3(512, 8, 4), dim3(32, 8)>>>(y, yT);

    // ---- projections ----
    gemm_async<128, 128, 0, 0><<<dim3(128, 2, 4), 256, shm128>>>(WqR, xT, bq, qt, 256, 256, 256, 0, 0, 0, 0, 0);
    gemm_async<128, 128, 0, 0><<<dim3(128, 2, 4), 256, shm128>>>(WkR, yT, bk, kt, 256, 256, 256, 0, 0, 0, 0, 0);
    gemm_async<128, 128, 0, 4><<<dim3(128, 2, 4), 256, shm128>>>(WvR, yT, bv, vt, 256, 256, 256, 0, 0, 0, 0, 0);

    const int splits[4] = {1, 1, 8, 64};
    for (int s = 0; s < 4; s++) {
        int l = s + 1;
        int n = 16384 >> (2 * l);
        int d = 64 << (2 * l);
        int sp = splits[s];
        int kper = d / sp;
        int soff = s << 20;
        float alpha = 1.0f / sqrtf((float)d);
        if (s < 3) {
            gemm_async<128, 128, 0, 1><<<dim3(n / 128, n / 128, 4 * sp), 256, shm128>>>(
                qt, kt, nullptr, S, kper, d, d, sp, kper, soff, n, s);
        } else {
            gemm_async<64, 64, 0, 1><<<dim3(1, 1, 4 * sp), 256, shm64>>>(
                qt, kt, nullptr, S, kper, d, d, sp, kper, soff, n, s);
        }
        k_softmax<<<dim3(n, 4), 256>>>(S, n, sp, alpha);
        if (s < 3) {
            gemm_async<128, 128, 0, 2><<<dim3(d / 128, n / 128, 4), 256, shm128>>>(
                S, vt, nullptr, attnT, n, n, n, sp, 0, soff, n, s);
        } else {
            gemm_async<64, 64, 0, 2><<<dim3(d / 64, n / 64, 4), 256, shm64>>>(
                S, vt, nullptr, attnT, n, n, n, sp, 0, soff, n, s);
        }
    }

    // ---- conv3x3 tap-GEMM over attnT -> d_out ----
    gemm_async<128, 128, 2, 3><<<dim3(128, 2, 4), 256, shm128>>>(WoR, attnT, bo, out, 2304, 2304, 0, 0, 0, 0, 0, 0);

    k_stats<<<256, 256>>>(out, meanv, rstdv);
    k_final<<<16384, 1024>>>(out, meanv, rstdv, gamma, beta);
}

// round 7
// speedup vs baseline: 4.8507x; 1.3752x over previous
#include <cuda_runtime.h>
#include <cuda_fp16.h>
#include <math.h>
#include <stdint.h>

#define BATCH 4
#define HWP 16384
#define CHW 4194304
#define TOKB 4194304
#define KC 64          // halves per k-chunk
#define SEGR 8         // 16B segments per row (KC/8)
#define RPH 72         // smem row stride in halves (144B)
#define ST 3

// ---------------- scratch ----------------
__device__ __half g_qt[BATCH * TOKB];
__device__ __half g_kt[BATCH * TOKB];
__device__ __half g_vt[BATCH * TOKB];    // V transposed token layout [scale][d][n]
__device__ float  g_S[67108864];         // fp32 score partials
__device__ __half g_P[67108864];         // softmax probs, fp16
__device__ __half g_attnT[BATCH * CHW];  // attention out, [b][pixel][channel]
__device__ __half g_xT[BATCH * CHW];     // [b][pixel][chan]
__device__ __half g_yT[BATCH * CHW];
__device__ __half g_WqH[65536];
__device__ __half g_WkH[65536];
__device__ __half g_WvH[65536];
__device__ __half g_WoH[589824];         // [o][tap*256+c]
__device__ float  g_mean[256];
__device__ float  g_rstd[256];

// ---------------- helpers ----------------
__device__ __forceinline__ void cpasync16(uint32_t dst, const void* src) {
    asm volatile("cp.async.cg.shared.global [%0], [%1], 16;" :: "r"(dst), "l"(src));
}
__device__ __forceinline__ void cpasync16z(uint32_t dst, const void* src, int srcsz) {
    asm volatile("cp.async.cg.shared.global [%0], [%1], 16, %2;" :: "r"(dst), "l"(src), "r"(srcsz));
}
__device__ __forceinline__ void ldsm4(uint32_t a, uint32_t& r0, uint32_t& r1, uint32_t& r2, uint32_t& r3) {
    asm volatile("ldmatrix.sync.aligned.m8n8.x4.shared.b16 {%0,%1,%2,%3}, [%4];"
                 : "=r"(r0), "=r"(r1), "=r"(r2), "=r"(r3) : "r"(a));
}
__device__ __forceinline__ void mma_f16(float* c, const uint32_t* a, const uint32_t* b) {
    asm volatile("mma.sync.aligned.m16n8k16.row.col.f32.f16.f16.f32 "
                 "{%0,%1,%2,%3}, {%4,%5,%6,%7}, {%8,%9}, {%0,%1,%2,%3};"
                 : "+f"(c[0]), "+f"(c[1]), "+f"(c[2]), "+f"(c[3])
                 : "r"(a[0]), "r"(a[1]), "r"(a[2]), "r"(a[3]), "r"(b[0]), "r"(b[1]));
}
__device__ __forceinline__ void scatterTok(__half* tok, int o, int p, __half v) {
    int scl = o >> 6, cl = o & 63, l = scl + 1;
    int msk = (1 << l) - 1;
    int yy = p >> 7, xx = p & 127;
    int wy = yy >> l, py = yy & msk, wx = xx >> l, px = xx & msk;
    int n = (wy << (7 - l)) | wx;
    int d = (cl << (2 * l)) | (py << l) | px;
    tok[(scl << 20) + (size_t)n * (64 << (2 * l)) + d] = v;
}
__device__ __forceinline__ void scatterTokT(__half* tok, int o, int p, __half v) {
    int scl = o >> 6, cl = o & 63, l = scl + 1;
    int msk = (1 << l) - 1;
    int yy = p >> 7, xx = p & 127;
    int wy = yy >> l, py = yy & msk, wx = xx >> l, px = xx & msk;
    int n = (wy << (7 - l)) | wx;
    int d = (cl << (2 * l)) | (py << l) | px;
    int nTokS = 16384 >> (2 * l);
    tok[(scl << 20) + (size_t)d * nTokS + n] = v;
}
__device__ __forceinline__ void scatterImgT(__half* img, int b, int scale, int row, int col, __half v) {
    int l = scale + 1;
    int owlog = 7 - l;
    int wy = row >> owlog, wx = row & ((1 << owlog) - 1);
    int cl = col >> (2 * l);
    int r = col & ((1 << (2 * l)) - 1);
    int py = r >> l, px = r & ((1 << l) - 1);
    int y = (wy << l) | py, x = (wx << l) | px;
    int c = (scale << 6) | cl;
    img[(((size_t)b << 14) + (y << 7) + x) * 256 + c] = v;
}

// ================= unified async fp16 GEMM (fp32 accumulate) ====
// MODE 0: proj -> token layout (+bias) ; MODE 4: proj -> transposed token layout (+bias)
// MODE 1: scores split-K partials -> fp32 S
// MODE 2: P@V -> attnT [pixel][channel]
// MODE 3: conv3x3 tap-GEMM -> out image (+bias, fp32)
// LOADB 0: B rows row-major [n][ldb]; LOADB 2: conv shifted-pixel loader over attnT
template<int BM, int BN, int LOADB, int MODE>
__global__ __launch_bounds__(256) void gemm_async(
    const __half* __restrict__ A, const __half* __restrict__ B,
    const float* __restrict__ bias, void* __restrict__ Cv,
    int Kloop, int lda, int ldb,
    int split, int kper, int soff, int nTok, int scale)
{
    constexpr int WM = BM / 2, WN = BN / 4;
    constexpr int MT = WM / 16, NT = WN / 8, NTP = WN / 16;
    extern __shared__ __half dynsmem[];
    __half* Asm = dynsmem;
    __half* Bsm = dynsmem + ST * BM * RPH;

    int tid = threadIdx.x;
    int lane = tid & 31, wid = tid >> 5;
    int wm = wid >> 2, wn = wid & 3;
    int m0 = blockIdx.y * BM, n0 = blockIdx.x * BN;

    const __half* Ab; const __half* Bb;
    int bidx, z = 0;
    if constexpr (MODE == 1) {
        z = blockIdx.z; bidx = z / split; int sp = z - bidx * split;
        Ab = A + (size_t)bidx * TOKB + soff + (size_t)sp * kper;
        Bb = B + (size_t)bidx * TOKB + soff + (size_t)sp * kper;
    } else if constexpr (MODE == 2) {
        bidx = blockIdx.z;
        Ab = A + (size_t)bidx * nTok * nTok;
        Bb = B + (size_t)bidx * TOKB + soff;
    } else {
        bidx = blockIdx.z;
        Ab = A;
        Bb = B + (size_t)bidx * CHW;
    }

    constexpr int APER = (BM * KC / 8) / 256;
    constexpr int BPER = (BN * KC / 8) / 256;
    uint32_t sA = (uint32_t)__cvta_generic_to_shared(Asm);
    uint32_t sB = (uint32_t)__cvta_generic_to_shared(Bsm);
    constexpr uint32_t ASTR = BM * RPH * 2, BSTR = BN * RPH * 2;
    int nc = Kloop / KC;

    auto issue = [&](int c) {
        int st = c % ST;
        int k0 = c * KC;
#pragma unroll
        for (int j = 0; j < APER; j++) {
            int i = tid + j * 256;
            int row = i / SEGR, seg = (i % SEGR) << 3;
            cpasync16(sA + st * ASTR + (uint32_t)(row * RPH + seg) * 2,
                      Ab + (size_t)(m0 + row) * lda + k0 + seg);
        }
        if constexpr (LOADB == 0) {
#pragma unroll
            for (int j = 0; j < BPER; j++) {
                int i = tid + j * 256;
                int row = i / SEGR, seg = (i % SEGR) << 3;
                cpasync16(sB + st * BSTR + (uint32_t)(row * RPH + seg) * 2,
                          Bb + (size_t)(n0 + row) * ldb + k0 + seg);
            }
        } else {
            // conv loader over attnT: BN=128 pixels (one image row y=blockIdx.x)
            // k = tap*256 + channel; tap uniform per 64-chunk (256/64=4 chunks per tap)
            int tap = k0 >> 8;
            int dy = tap / 3, dx = tap - dy * 3;
            int gy = (int)blockIdx.x + dy - 1;
            bool okY = (unsigned)gy < 128u;
#pragma unroll
            for (int j = 0; j < BPER; j++) {
                int i = tid + j * 256;
                int xrow = i / SEGR, seg = (i % SEGR) << 3;
                int ch = (k0 & 255) + seg;
                int gx = xrow + dx - 1;
                int sz = (okY && (unsigned)gx < 128u) ? 16 : 0;
                const __half* src = Bb + ((size_t)(gy << 7) + gx) * 256 + ch;
                cpasync16z(sB + st * BSTR + (uint32_t)(xrow * RPH + seg) * 2, src, sz);
            }
        }
    };

    float acc[MT][NT][4];
#pragma unroll
    for (int i = 0; i < MT; i++)
#pragma unroll
        for (int j = 0; j < NT; j++)
#pragma unroll
            for (int e = 0; e < 4; e++) acc[i][j][e] = 0.f;

    int r8 = lane & 7, hi8 = (lane >> 3) & 1, hi16 = (lane >> 4) & 1;
    uint32_t aOff = (uint32_t)((wm * WM + r8 + hi8 * 8) * RPH * 2 + hi16 * 16);
    uint32_t bOff = (uint32_t)((wn * WN + r8 + hi8 * 8) * RPH * 2 + hi16 * 16);

    if (0 < nc) issue(0);
    asm volatile("cp.async.commit_group;");
    if (1 < nc) issue(1);
    asm volatile("cp.async.commit_group;");

    for (int c = 0; c < nc; c++) {
        asm volatile("cp.async.wait_group 1;");
        __syncthreads();
        {
            int st = c % ST;
            uint32_t sa = sA + st * ASTR, sb = sB + st * BSTR;
#pragma unroll
            for (int ks = 0; ks < KC / 16; ks++) {
                uint32_t af[MT][4], bf[NTP][4];
#pragma unroll
                for (int mt = 0; mt < MT; mt++)
                    ldsm4(sa + aOff + mt * 16 * RPH * 2 + ks * 32, af[mt][0], af[mt][1], af[mt][2], af[mt][3]);
#pragma unroll
                for (int np = 0; np < NTP; np++)
                    ldsm4(sb + bOff + np * 16 * RPH * 2 + ks * 32, bf[np][0], bf[np][1], bf[np][2], bf[np][3]);
#pragma unroll
                for (int mt = 0; mt < MT; mt++)
#pragma unroll
                    for (int np = 0; np < NTP; np++) {
                        uint32_t b0[2] = { bf[np][0], bf[np][2] };
                        uint32_t b1[2] = { bf[np][1], bf[np][3] };
                        mma_f16(acc[mt][np * 2 + 0], af[mt], b0);
                        mma_f16(acc[mt][np * 2 + 1], af[mt], b1);
                    }
            }
        }
        if (c + 2 < nc) issue(c + 2);
        asm volatile("cp.async.commit_group;");
    }

    // epilogue
    int g = lane >> 2, q2 = (lane & 3) << 1;
#pragma unroll
    for (int mt = 0; mt < MT; mt++) {
        int row0 = m0 + wm * WM + mt * 16 + g;
#pragma unroll
        for (int e2 = 0; e2 < 2; e2++) {
            int row = row0 + e2 * 8;
            float bia = 0.f;
            if constexpr (MODE == 0 || MODE == 3 || MODE == 4) bia = __ldg(&bias[row]);
#pragma unroll
            for (int nt = 0; nt < NT; nt++) {
                int col = n0 + wn * WN + nt * 8 + q2;
                float v0 = acc[mt][nt][e2 * 2 + 0] + bia;
                float v1 = acc[mt][nt][e2 * 2 + 1] + bia;
                if constexpr (MODE == 1) {
                    float* C = (float*)Cv;
                    *(float2*)&C[(size_t)z * nTok * nTok + (size_t)row * nTok + col] = make_float2(v0, v1);
                } else if constexpr (MODE == 0) {
                    __half* tok = (__half*)Cv + (size_t)bidx * TOKB;
                    scatterTok(tok, row, col, __float2half_rn(v0));
                    scatterTok(tok, row, col + 1, __float2half_rn(v1));
                } else if constexpr (MODE == 4) {
                    __half* tok = (__half*)Cv + (size_t)bidx * TOKB;
                    scatterTokT(tok, row, col, __float2half_rn(v0));
                    scatterTokT(tok, row, col + 1, __float2half_rn(v1));
                } else if constexpr (MODE == 2) {
                    scatterImgT((__half*)Cv, bidx, scale, row, col, __float2half_rn(v0));
                    scatterImgT((__half*)Cv, bidx, scale, row, col + 1, __float2half_rn(v1));
                } else {
                    // MODE 3: out[b][o][pixel]; col == y*128 + x (n0 = blockIdx.x*128)
                    float* C = (float*)Cv;
                    size_t adr = (((size_t)bidx * 256 + row) << 14) + col;
                    *(float2*)&C[adr] = make_float2(v0, v1);
                }
            }
        }
    }
}

// ---------------- prep: fp32 -> fp16 copy (1x1 weights) ----------------
__global__ void k_half(const float* __restrict__ s, __half* __restrict__ d, int n)
{
    int i = blockIdx.x * 256 + threadIdx.x;
    if (i < n) d[i] = __float2half_rn(s[i]);
}

// ---------------- prep: repack Wo [o][c][3][3] -> [o][tap*256+c] fp16 ----------------
__global__ void k_packWo(const float* __restrict__ s, __half* __restrict__ d)
{
    int i = blockIdx.x * 256 + threadIdx.x;
    if (i < 589824) {
        int o = i / 2304, r = i - o * 2304;
        int tap = r >> 8, c = r & 255;
        d[i] = __float2half_rn(s[((size_t)o * 256 + c) * 9 + tap]);
    }
}

// ---------------- prep: transpose [b][256][16384] -> [b][16384][256] fp16 ----------------
__global__ void k_transpose(const float* __restrict__ src, __half* __restrict__ dst)
{
    __shared__ float t[32][33];
    int b = blockIdx.z;
    const float* s = src + (size_t)b * CHW;
    __half* d = dst + (size_t)b * CHW;
    int x = blockIdx.x * 32 + threadIdx.x;
    int yc = blockIdx.y * 32 + threadIdx.y;
#pragma unroll
    for (int j = 0; j < 4; j++)
        t[threadIdx.y + j * 8][threadIdx.x] = s[(size_t)(yc + j * 8) * HWP + x];
    __syncthreads();
    int x2 = blockIdx.y * 32 + threadIdx.x;
    int y2 = blockIdx.x * 32 + threadIdx.y;
#pragma unroll
    for (int j = 0; j < 4; j++)
        d[(size_t)(y2 + j * 8) * 256 + x2] = __float2half_rn(t[threadIdx.x][threadIdx.y + j * 8]);
}

// ---------------- softmax (fuses split-K reduction, writes fp16 P) ----------------
__global__ void k_softmax(const float* __restrict__ S, __half* __restrict__ P,
                          int nTok, int split, float alpha)
{
    __shared__ float rowb[4096];
    __shared__ float red[256];
    int row = blockIdx.x;
    size_t bb = (size_t)blockIdx.y * split * nTok * nTok;
    int tid = threadIdx.x;
    float mx = -1e30f;
    for (int j = tid; j < nTok; j += 256) {
        float s = 0.f;
        for (int sp = 0; sp < split; sp++)
            s += S[bb + ((size_t)sp * nTok + row) * nTok + j];
        s *= alpha;
        rowb[j] = s;
        mx = fmaxf(mx, s);
    }
    red[tid] = mx; __syncthreads();
    for (int st = 128; st; st >>= 1) { if (tid < st) red[tid] = fmaxf(red[tid], red[tid + st]); __syncthreads(); }
    mx = red[0]; __syncthreads();
    float sum = 0.f;
    for (int j = tid; j < nTok; j += 256) {
        float e = __expf(rowb[j] - mx);
        rowb[j] = e; sum += e;
    }
    red[tid] = sum; __syncthreads();
    for (int st = 128; st; st >>= 1) { if (tid < st) red[tid] += red[tid + st]; __syncthreads(); }
    float inv = 1.0f / red[0];
    size_t ob = (size_t)blockIdx.y * nTok * nTok + (size_t)row * nTok;
    for (int j = tid; j < nTok; j += 256)
        P[ob + j] = __float2half_rn(rowb[j] * inv);
}

// ---------------- batchnorm stats ----------------
__global__ void k_stats(const float* __restrict__ z, float* __restrict__ meanv, float* __restrict__ rstdv)
{
    __shared__ float rs[256], rs2[256];
    int c = blockIdx.x;
    int tid = threadIdx.x;
    float s = 0.f, s2 = 0.f;
    for (int i = tid; i < 65536; i += 256) {
        int b = i >> 14, p = i & 16383;
        float v = z[(((size_t)b * 256 + c) << 14) + p];
        s += v; s2 += v * v;
    }
    rs[tid] = s; rs2[tid] = s2; __syncthreads();
    for (int st = 128; st; st >>= 1) {
        if (tid < st) { rs[tid] += rs[tid + st]; rs2[tid] += rs2[tid + st]; }
        __syncthreads();
    }
    if (tid == 0) {
        float m = rs[0] * (1.0f / 65536.0f);
        float var = rs2[0] * (1.0f / 65536.0f) - m * m;
        meanv[c] = m;
        rstdv[c] = rsqrtf(var + 1e-5f);
    }
}

// ---------------- normalize + affine + LeakyReLU ----------------
__global__ void k_final(float* __restrict__ z, const float* __restrict__ meanv, const float* __restrict__ rstdv,
                        const float* __restrict__ gamma, const float* __restrict__ beta)
{
    size_t idx = (size_t)blockIdx.x * 1024 + threadIdx.x;
    int c = (int)((idx >> 14) & 255);
    float v = z[idx];
    v = (v - __ldg(&meanv[c])) * __ldg(&rstdv[c]) * __ldg(&gamma[c]) + __ldg(&beta[c]);
    z[idx] = v >= 0.f ? v : 0.2f * v;
}

// ---------------- host launch ----------------
extern "C" void kernel_launch(void* const* d_in, const int* in_sizes, int n_in,
                              void* d_out, int out_size)
{
    (void)in_sizes; (void)n_in; (void)out_size;
    const float* x     = (const float*)d_in[0];
    const float* y     = (const float*)d_in[1];
    const float* Wq    = (const float*)d_in[2];
    const float* bq    = (const float*)d_in[3];
    const float* Wk    = (const float*)d_in[4];
    const float* bk    = (const float*)d_in[5];
    const float* Wv    = (const float*)d_in[6];
    const float* bv    = (const float*)d_in[7];
    const float* Wo    = (const float*)d_in[8];
    const float* bo    = (const float*)d_in[9];
    const float* gamma = (const float*)d_in[10];
    const float* beta  = (const float*)d_in[11];
    float* out = (float*)d_out;

    __half *qt, *kt, *vt, *P, *attnT, *xT, *yT, *WqH, *WkH, *WvH, *WoH;
    float *S, *meanv, *rstdv;
    cudaGetSymbolAddress((void**)&qt,    g_qt);
    cudaGetSymbolAddress((void**)&kt,    g_kt);
    cudaGetSymbolAddress((void**)&vt,    g_vt);
    cudaGetSymbolAddress((void**)&S,     g_S);
    cudaGetSymbolAddress((void**)&P,     g_P);
    cudaGetSymbolAddress((void**)&attnT, g_attnT);
    cudaGetSymbolAddress((void**)&xT,    g_xT);
    cudaGetSymbolAddress((void**)&yT,    g_yT);
    cudaGetSymbolAddress((void**)&WqH,   g_WqH);
    cudaGetSymbolAddress((void**)&WkH,   g_WkH);
    cudaGetSymbolAddress((void**)&WvH,   g_WvH);
    cudaGetSymbolAddress((void**)&WoH,   g_WoH);
    cudaGetSymbolAddress((void**)&meanv, g_mean);
    cudaGetSymbolAddress((void**)&rstdv, g_rstd);

    const int shm128 = ST * (128 + 128) * RPH * 2;   // 110592
    const int shm64  = ST * (64 + 64) * RPH * 2;     // 55296
    cudaFuncSetAttribute(gemm_async<128, 128, 0, 0>, cudaFuncAttributeMaxDynamicSharedMemorySize, shm128);
    cudaFuncSetAttribute(gemm_async<128, 128, 0, 4>, cudaFuncAttributeMaxDynamicSharedMemorySize, shm128);
    cudaFuncSetAttribute(gemm_async<128, 128, 0, 1>, cudaFuncAttributeMaxDynamicSharedMemorySize, shm128);
    cudaFuncSetAttribute(gemm_async<128, 128, 0, 2>, cudaFuncAttributeMaxDynamicSharedMemorySize, shm128);
    cudaFuncSetAttribute(gemm_async<64, 64, 0, 1>,   cudaFuncAttributeMaxDynamicSharedMemorySize, shm64);
    cudaFuncSetAttribute(gemm_async<64, 64, 0, 2>,   cudaFuncAttributeMaxDynamicSharedMemorySize, shm64);
    cudaFuncSetAttribute(gemm_async<128, 128, 2, 3>, cudaFuncAttributeMaxDynamicSharedMemorySize, shm128);

    // ---- prep ----
    k_half<<<256, 256>>>(Wq, WqH, 65536);
    k_half<<<256, 256>>>(Wk, WkH, 65536);
    k_half<<<256, 256>>>(Wv, WvH, 65536);
    k_packWo<<<2304, 256>>>(Wo, WoH);
    k_transpose<<<dim3(512, 8, 4), dim3(32, 8)>>>(x, xT);
    k_transpose<<<dim3(512, 8, 4), dim3(32, 8)>>>(y, yT);

    // ---- projections ----
    gemm_async<128, 128, 0, 0><<<dim3(128, 2, 4), 256, shm128>>>(WqH, xT, bq, qt, 256, 256, 256, 0, 0, 0, 0, 0);
    gemm_async<128, 128, 0, 0><<<dim3(128, 2, 4), 256, shm128>>>(WkH, yT, bk, kt, 256, 256, 256, 0, 0, 0, 0, 0);
    gemm_async<128, 128, 0, 4><<<dim3(128, 2, 4), 256, shm128>>>(WvH, yT, bv, vt, 256, 256, 256, 0, 0, 0, 0, 0);

    const int splits[4] = {1, 1, 8, 64};
    for (int s = 0; s < 4; s++) {
        int l = s + 1;
        int n = 16384 >> (2 * l);
        int d = 64 << (2 * l);
        int sp = splits[s];
        int kper = d / sp;
        int soff = s << 20;
        float alpha = 1.0f / sqrtf((float)d);
        if (s < 3) {
            gemm_async<128, 128, 0, 1><<<dim3(n / 128, n / 128, 4 * sp), 256, shm128>>>(
                qt, kt, nullptr, S, kper, d, d, sp, kper, soff, n, s);
        } else {
            gemm_async<64, 64, 0, 1><<<dim3(1, 1, 4 * sp), 256, shm64>>>(
                qt, kt, nullptr, S, kper, d, d, sp, kper, soff, n, s);
        }
        k_softmax<<<dim3(n, 4), 256>>>(S, P, n, sp, alpha);
        if (s < 3) {
            gemm_async<128, 128, 0, 2><<<dim3(d / 128, n / 128, 4), 256, shm128>>>(
                P, vt, nullptr, attnT, n, n, n, sp, 0, soff, n, s);
        } else {
            gemm_async<64, 64, 0, 2><<<dim3(d / 64, n / 64, 4), 256, shm64>>>(
                P, vt, nullptr, attnT, n, n, n, sp, 0, soff, n, s);
        }
    }

    // ---- conv3x3 tap-GEMM over attnT -> d_out ----
    gemm_async<128, 128, 2, 3><<<dim3(128, 2, 4), 256, shm128>>>(WoH, attnT, bo, out, 2304, 2304, 0, 0, 0, 0, 0, 0);

    k_stats<<<256, 256>>>(out, meanv, rstdv);
    k_final<<<16384, 1024>>>(out, meanv, rstdv, gamma, beta);
}

// round 9
// speedup vs baseline: 6.2088x; 1.2800x over previous
#include <cuda_runtime.h>
#include <cuda_fp16.h>
#include <math.h>
#include <stdint.h>

#define BATCH 4
#define HWP 16384
#define CHW 4194304
#define TOKB 4194304
#define KC 64
#define RPH 72
#define ST 3

// ---------------- scratch ----------------
__device__ __half g_qt[BATCH * TOKB];
__device__ __half g_kt[BATCH * TOKB];
__device__ __half g_vt[BATCH * TOKB];      // V transposed token layout [scale][d][n]
__device__ float  g_S[72613888];           // score partials: per-scale offsets
__device__ __half g_P[71581696];           // probs
__device__ __half g_attnT[BATCH * CHW];
__device__ __half g_xT[BATCH * CHW];
__device__ __half g_yT[BATCH * CHW];
__device__ __half g_WqH[65536];
__device__ __half g_WkH[65536];
__device__ __half g_WvH[65536];
__device__ __half g_WoH[589824];
__device__ float  g_mean[256];
__device__ float  g_rstd[256];

// per-scale tables
#define NS0 4096
#define SOFF1 67108864ull
#define SOFF2 71303168ull
#define SOFF3 71565312ull

__device__ __forceinline__ int nssF(int s) { return 16384 >> (2 * (s + 1)); }
__device__ __forceinline__ int dssF(int s) { return 64 << (2 * (s + 1)); }
__device__ __forceinline__ size_t soffF(int s) { return s == 0 ? 0ull : (s == 1 ? SOFF1 : (s == 2 ? SOFF2 : SOFF3)); }

// ---------------- helpers ----------------
__device__ __forceinline__ void cpasync16(uint32_t dst, const void* src) {
    asm volatile("cp.async.cg.shared.global [%0], [%1], 16;" :: "r"(dst), "l"(src));
}
__device__ __forceinline__ void cpasync16z(uint32_t dst, const void* src, int srcsz) {
    asm volatile("cp.async.cg.shared.global [%0], [%1], 16, %2;" :: "r"(dst), "l"(src), "r"(srcsz));
}
__device__ __forceinline__ void ldsm4(uint32_t a, uint32_t& r0, uint32_t& r1, uint32_t& r2, uint32_t& r3) {
    asm volatile("ldmatrix.sync.aligned.m8n8.x4.shared.b16 {%0,%1,%2,%3}, [%4];"
                 : "=r"(r0), "=r"(r1), "=r"(r2), "=r"(r3) : "r"(a));
}
__device__ __forceinline__ void mma_f16(float* c, const uint32_t* a, const uint32_t* b) {
    asm volatile("mma.sync.aligned.m16n8k16.row.col.f32.f16.f16.f32 "
                 "{%0,%1,%2,%3}, {%4,%5,%6,%7}, {%8,%9}, {%0,%1,%2,%3};"
                 : "+f"(c[0]), "+f"(c[1]), "+f"(c[2]), "+f"(c[3])
                 : "r"(a[0]), "r"(a[1]), "r"(a[2]), "r"(a[3]), "r"(b[0]), "r"(b[1]));
}
__device__ __forceinline__ void scatterTok(__half* tok, int o, int p, __half v) {
    int scl = o >> 6, cl = o & 63, l = scl + 1;
    int msk = (1 << l) - 1;
    int yy = p >> 7, xx = p & 127;
    int wy = yy >> l, py = yy & msk, wx = xx >> l, px = xx & msk;
    int n = (wy << (7 - l)) | wx;
    int d = (cl << (2 * l)) | (py << l) | px;
    tok[(scl << 20) + (size_t)n * (64 << (2 * l)) + d] = v;
}
__device__ __forceinline__ void scatterTokT(__half* tok, int o, int p, __half v) {
    int scl = o >> 6, cl = o & 63, l = scl + 1;
    int msk = (1 << l) - 1;
    int yy = p >> 7, xx = p & 127;
    int wy = yy >> l, py = yy & msk, wx = xx >> l, px = xx & msk;
    int n = (wy << (7 - l)) | wx;
    int d = (cl << (2 * l)) | (py << l) | px;
    int nTokS = 16384 >> (2 * l);
    tok[(scl << 20) + (size_t)d * nTokS + n] = v;
}
__device__ __forceinline__ void scatterImgT(__half* img, int b, int scale, int row, int col, __half v) {
    int l = scale + 1;
    int owlog = 7 - l;
    int wy = row >> owlog, wx = row & ((1 << owlog) - 1);
    int cl = col >> (2 * l);
    int r = col & ((1 << (2 * l)) - 1);
    int py = r >> l, px = r & ((1 << l) - 1);
    int y = (wy << l) | py, x = (wx << l) | px;
    int c = (scale << 6) | cl;
    img[(((size_t)b << 14) + (y << 7) + x) * 256 + c] = v;
}

// ---------------- shared 128x128 fp16 mainloop (row-clamped loaders) ----------------
__device__ __forceinline__ void mainloop128(
    const __half* __restrict__ Ab, const __half* __restrict__ Bb,
    int lda, int ldb, int nc, int rmaxA, int rmaxB, int m0, int n0,
    __half* Asm, __half* Bsm, float (&acc)[4][4][4])
{
    int tid = threadIdx.x;
    int lane = tid & 31, wid = tid >> 5;
    int wm = wid >> 2, wn = wid & 3;
    uint32_t sA = (uint32_t)__cvta_generic_to_shared(Asm);
    uint32_t sB = (uint32_t)__cvta_generic_to_shared(Bsm);
    const uint32_t ASTR = 128 * RPH * 2, BSTR = 128 * RPH * 2;

    auto issue = [&](int c) {
        int st = c % ST;
        int k0 = c * KC;
#pragma unroll
        for (int j = 0; j < 4; j++) {
            int i = tid + j * 256;
            int row = i >> 3, seg = (i & 7) << 3;
            int ar = min(m0 + row, rmaxA);
            cpasync16(sA + st * ASTR + (uint32_t)(row * RPH + seg) * 2,
                      Ab + (size_t)ar * lda + k0 + seg);
        }
#pragma unroll
        for (int j = 0; j < 4; j++) {
            int i = tid + j * 256;
            int row = i >> 3, seg = (i & 7) << 3;
            int br = min(n0 + row, rmaxB);
            cpasync16(sB + st * BSTR + (uint32_t)(row * RPH + seg) * 2,
                      Bb + (size_t)br * ldb + k0 + seg);
        }
    };

#pragma unroll
    for (int i = 0; i < 4; i++)
#pragma unroll
        for (int j = 0; j < 4; j++)
#pragma unroll
            for (int e = 0; e < 4; e++) acc[i][j][e] = 0.f;

    int r8 = lane & 7, hi8 = (lane >> 3) & 1, hi16 = (lane >> 4) & 1;
    uint32_t aOff = (uint32_t)((wm * 64 + r8 + hi8 * 8) * RPH * 2 + hi16 * 16);
    uint32_t bOff = (uint32_t)((wn * 32 + r8 + hi8 * 8) * RPH * 2 + hi16 * 16);

    if (0 < nc) issue(0);
    asm volatile("cp.async.commit_group;");
    if (1 < nc) issue(1);
    asm volatile("cp.async.commit_group;");

    for (int c = 0; c < nc; c++) {
        asm volatile("cp.async.wait_group 1;");
        __syncthreads();
        {
            int st = c % ST;
            uint32_t sa = sA + st * ASTR, sb = sB + st * BSTR;
#pragma unroll
            for (int ks = 0; ks < 4; ks++) {
                uint32_t af[4][4], bf[2][4];
#pragma unroll
                for (int mt = 0; mt < 4; mt++)
                    ldsm4(sa + aOff + mt * 16 * RPH * 2 + ks * 32, af[mt][0], af[mt][1], af[mt][2], af[mt][3]);
#pragma unroll
                for (int np = 0; np < 2; np++)
                    ldsm4(sb + bOff + np * 16 * RPH * 2 + ks * 32, bf[np][0], bf[np][1], bf[np][2], bf[np][3]);
#pragma unroll
                for (int mt = 0; mt < 4; mt++)
#pragma unroll
                    for (int np = 0; np < 2; np++) {
                        uint32_t b0[2] = { bf[np][0], bf[np][2] };
                        uint32_t b1[2] = { bf[np][1], bf[np][3] };
                        mma_f16(acc[mt][np * 2 + 0], af[mt], b0);
                        mma_f16(acc[mt][np * 2 + 1], af[mt], b1);
                    }
            }
        }
        if (c + 2 < nc) issue(c + 2);
        asm volatile("cp.async.commit_group;");
    }
}

// ---------------- merged projections: Q,K,V in one launch ----------------
__global__ __launch_bounds__(256) void k_proj(
    const __half* __restrict__ Wq, const __half* __restrict__ Wk, const __half* __restrict__ Wv,
    const __half* __restrict__ xT, const __half* __restrict__ yT,
    const float* __restrict__ bq, const float* __restrict__ bk, const float* __restrict__ bv,
    __half* __restrict__ qt, __half* __restrict__ kt, __half* __restrict__ vt)
{
    extern __shared__ __half dynsmem[];
    int which = blockIdx.z >> 2, b = blockIdx.z & 3;
    const __half* A = which == 0 ? Wq : (which == 1 ? Wk : Wv);
    const __half* Bb = (which == 0 ? xT : yT) + (size_t)b * CHW;
    const float* bias = which == 0 ? bq : (which == 1 ? bk : bv);
    __half* outp = (which == 0 ? qt : (which == 1 ? kt : vt)) + (size_t)b * TOKB;

    int m0 = blockIdx.y * 128, n0 = blockIdx.x * 128;
    float acc[4][4][4];
    mainloop128(A, Bb, 256, 256, 4, 255, 16383, m0, n0, dynsmem, dynsmem + ST * 128 * RPH, acc);

    int tid = threadIdx.x, lane = tid & 31, wid = tid >> 5;
    int wm = wid >> 2, wn = wid & 3;
    int g = lane >> 2, q2 = (lane & 3) << 1;
#pragma unroll
    for (int mt = 0; mt < 4; mt++) {
        int row0 = m0 + wm * 64 + mt * 16 + g;
#pragma unroll
        for (int e2 = 0; e2 < 2; e2++) {
            int row = row0 + e2 * 8;
            float bia = __ldg(&bias[row]);
#pragma unroll
            for (int nt = 0; nt < 4; nt++) {
                int col = n0 + wn * 32 + nt * 8 + q2;
                __half v0 = __float2half_rn(acc[mt][nt][e2 * 2 + 0] + bia);
                __half v1 = __float2half_rn(acc[mt][nt][e2 * 2 + 1] + bia);
                if (which < 2) { scatterTok(outp, row, col, v0); scatterTok(outp, row, col + 1, v1); }
                else           { scatterTokT(outp, row, col, v0); scatterTokT(outp, row, col + 1, v1); }
            }
        }
    }
}

// ---------------- merged scores: all scales in one launch (4624 blocks) ----------------
__global__ __launch_bounds__(256) void k_scores(
    const __half* __restrict__ qt, const __half* __restrict__ kt, float* __restrict__ S)
{
    extern __shared__ __half dynsmem[];
    int f = blockIdx.x;
    int s, b, zS, sp = 0, bx, by;
    if (f < 4096)      { s = 0; zS = f >> 10; b = zS; int t = f & 1023; by = t >> 5; bx = t & 31; }
    else if (f < 4352) { s = 1; int r = f - 4096; zS = r >> 6; b = zS; int t = r & 63; by = t >> 3; bx = t & 7; }
    else if (f < 4368) { s = 2; int r = f - 4352; zS = r >> 2; b = zS; int t = r & 3; by = t >> 1; bx = t & 1; }
    else               { s = 3; int zz = f - 4368; zS = zz; b = zz >> 6; sp = zz & 63; bx = 0; by = 0; }

    int nTok = nssF(s), d = dssF(s);
    int Kl = (s == 3) ? 256 : d;
    const __half* Ab = qt + (size_t)b * TOKB + ((size_t)s << 20) + (size_t)sp * 256;
    const __half* Bb = kt + (size_t)b * TOKB + ((size_t)s << 20) + (size_t)sp * 256;
    int m0 = by * 128, n0 = bx * 128;

    float acc[4][4][4];
    mainloop128(Ab, Bb, d, d, Kl / KC, nTok - 1, nTok - 1, m0, n0,
                dynsmem, dynsmem + ST * 128 * RPH, acc);

    float* Sb = S + soffF(s) + (size_t)zS * nTok * nTok;
    int tid = threadIdx.x, lane = tid & 31, wid = tid >> 5;
    int wm = wid >> 2, wn = wid & 3;
    int g = lane >> 2, q2 = (lane & 3) << 1;
#pragma unroll
    for (int mt = 0; mt < 4; mt++) {
        int row0 = m0 + wm * 64 + mt * 16 + g;
#pragma unroll
        for (int e2 = 0; e2 < 2; e2++) {
            int row = row0 + e2 * 8;
            if (row >= nTok) continue;
#pragma unroll
            for (int nt = 0; nt < 4; nt++) {
                int col = n0 + wn * 32 + nt * 8 + q2;
                if (col >= nTok) continue;
                *(float2*)&Sb[(size_t)row * nTok + col] =
                    make_float2(acc[mt][nt][e2 * 2 + 0], acc[mt][nt][e2 * 2 + 1]);
            }
        }
    }
}

// ---------------- merged P@V: all scales in one launch (1280 blocks) ----------------
__global__ __launch_bounds__(256) void k_pv(
    const __half* __restrict__ P, const __half* __restrict__ vt, __half* __restrict__ attnT)
{
    extern __shared__ __half dynsmem[];
    int f = blockIdx.x;
    int s, b, bx, by;
    if (f < 256)      { s = 0; b = f >> 6; int t = f & 63; by = t >> 1; bx = t & 1; }
    else if (f < 512) { s = 1; int r = f - 256; b = r >> 6; int t = r & 63; by = t >> 3; bx = t & 7; }
    else if (f < 768) { s = 2; int r = f - 512; b = r >> 6; int t = r & 63; bx = t >> 1; by = t & 1; }
    else              { s = 3; int r = f - 768; b = r >> 7; bx = r & 127; by = 0; }

    int nTok = nssF(s), d = dssF(s);
    const __half* Ab = P + soffF(s) + (size_t)b * nTok * nTok;
    const __half* Bb = vt + (size_t)b * TOKB + ((size_t)s << 20);
    int m0 = by * 128, n0 = bx * 128;

    float acc[4][4][4];
    mainloop128(Ab, Bb, nTok, nTok, nTok / KC, nTok - 1, d - 1, m0, n0,
                dynsmem, dynsmem + ST * 128 * RPH, acc);

    int tid = threadIdx.x, lane = tid & 31, wid = tid >> 5;
    int wm = wid >> 2, wn = wid & 3;
    int g = lane >> 2, q2 = (lane & 3) << 1;
#pragma unroll
    for (int mt = 0; mt < 4; mt++) {
        int row0 = m0 + wm * 64 + mt * 16 + g;
#pragma unroll
        for (int e2 = 0; e2 < 2; e2++) {
            int row = row0 + e2 * 8;
            if (row >= nTok) continue;
#pragma unroll
            for (int nt = 0; nt < 4; nt++) {
                int col = n0 + wn * 32 + nt * 8 + q2;
                scatterImgT(attnT, b, s, row, col, __float2half_rn(acc[mt][nt][e2 * 2 + 0]));
                scatterImgT(attnT, b, s, row, col + 1, __float2half_rn(acc[mt][nt][e2 * 2 + 1]));
            }
        }
    }
}

// ---------------- conv3x3 tap-GEMM (unchanged structure) ----------------
__global__ __launch_bounds__(256) void k_conv(
    const __half* __restrict__ Wo, const __half* __restrict__ attnT,
    const float* __restrict__ bo, float* __restrict__ out)
{
    extern __shared__ __half dynsmem[];
    __half* Asm = dynsmem;
    __half* Bsm = dynsmem + ST * 128 * RPH;
    int tid = threadIdx.x;
    int lane = tid & 31, wid = tid >> 5;
    int wm = wid >> 2, wn = wid & 3;
    int m0 = blockIdx.y * 128, n0 = blockIdx.x * 128;
    int bidx = blockIdx.z;
    const __half* Ab = Wo;
    const __half* Bb = attnT + (size_t)bidx * CHW;

    uint32_t sA = (uint32_t)__cvta_generic_to_shared(Asm);
    uint32_t sB = (uint32_t)__cvta_generic_to_shared(Bsm);
    const uint32_t ASTR = 128 * RPH * 2, BSTR = 128 * RPH * 2;
    const int nc = 36;  // 2304/64

    auto issue = [&](int c) {
        int st = c % ST;
        int k0 = c * KC;
#pragma unroll
        for (int j = 0; j < 4; j++) {
            int i = tid + j * 256;
            int row = i >> 3, seg = (i & 7) << 3;
            cpasync16(sA + st * ASTR + (uint32_t)(row * RPH + seg) * 2,
                      Ab + (size_t)(m0 + row) * 2304 + k0 + seg);
        }
        int tap = k0 >> 8;
        int dy = tap / 3, dx = tap - dy * 3;
        int gy = (int)blockIdx.x + dy - 1;
        bool okY = (unsigned)gy < 128u;
#pragma unroll
        for (int j = 0; j < 4; j++) {
            int i = tid + j * 256;
            int xrow = i >> 3, seg = (i & 7) << 3;
            int ch = (k0 & 255) + seg;
            int gx = xrow + dx - 1;
            int sz = (okY && (unsigned)gx < 128u) ? 16 : 0;
            const __half* src = Bb + ((size_t)(gy << 7) + gx) * 256 + ch;
            cpasync16z(sB + st * BSTR + (uint32_t)(xrow * RPH + seg) * 2, src, sz);
        }
    };

    float acc[4][4][4];
#pragma unroll
    for (int i = 0; i < 4; i++)
#pragma unroll
        for (int j = 0; j < 4; j++)
#pragma unroll
            for (int e = 0; e < 4; e++) acc[i][j][e] = 0.f;

    int r8 = lane & 7, hi8 = (lane >> 3) & 1, hi16 = (lane >> 4) & 1;
    uint32_t aOff = (uint32_t)((wm * 64 + r8 + hi8 * 8) * RPH * 2 + hi16 * 16);
    uint32_t bOff = (uint32_t)((wn * 32 + r8 + hi8 * 8) * RPH * 2 + hi16 * 16);

    issue(0);
    asm volatile("cp.async.commit_group;");
    issue(1);
    asm volatile("cp.async.commit_group;");

    for (int c = 0; c < nc; c++) {
        asm volatile("cp.async.wait_group 1;");
        __syncthreads();
        {
            int st = c % ST;
            uint32_t sa = sA + st * ASTR, sb = sB + st * BSTR;
#pragma unroll
            for (int ks = 0; ks < 4; ks++) {
                uint32_t af[4][4], bf[2][4];
#pragma unroll
                for (int mt = 0; mt < 4; mt++)
                    ldsm4(sa + aOff + mt * 16 * RPH * 2 + ks * 32, af[mt][0], af[mt][1], af[mt][2], af[mt][3]);
#pragma unroll
                for (int np = 0; np < 2; np++)
                    ldsm4(sb + bOff + np * 16 * RPH * 2 + ks * 32, bf[np][0], bf[np][1], bf[np][2], bf[np][3]);
#pragma unroll
                for (int mt = 0; mt < 4; mt++)
#pragma unroll
                    for (int np = 0; np < 2; np++) {
                        uint32_t b0[2] = { bf[np][0], bf[np][2] };
                        uint32_t b1[2] = { bf[np][1], bf[np][3] };
                        mma_f16(acc[mt][np * 2 + 0], af[mt], b0);
                        mma_f16(acc[mt][np * 2 + 1], af[mt], b1);
                    }
            }
        }
        if (c + 2 < nc) issue(c + 2);
        asm volatile("cp.async.commit_group;");
    }

    int g = lane >> 2, q2 = (lane & 3) << 1;
#pragma unroll
    for (int mt = 0; mt < 4; mt++) {
        int row0 = m0 + wm * 64 + mt * 16 + g;
#pragma unroll
        for (int e2 = 0; e2 < 2; e2++) {
            int row = row0 + e2 * 8;
            float bia = __ldg(&bo[row]);
#pragma unroll
            for (int nt = 0; nt < 4; nt++) {
                int col = n0 + wn * 32 + nt * 8 + q2;
                size_t adr = (((size_t)bidx * 256 + row) << 14) + col;
                *(float2*)&out[adr] = make_float2(acc[mt][nt][e2 * 2 + 0] + bia,
                                                  acc[mt][nt][e2 * 2 + 1] + bia);
            }
        }
    }
}

// ---------------- prep kernels ----------------
__global__ void k_halfAll(const float* __restrict__ a, const float* __restrict__ b, const float* __restrict__ c,
                          __half* __restrict__ da, __half* __restrict__ db, __half* __restrict__ dc)
{
    int i = blockIdx.x * 256 + threadIdx.x;
    if (i < 65536) da[i] = __float2half_rn(a[i]);
    else if (i < 131072) db[i - 65536] = __float2half_rn(b[i - 65536]);
    else if (i < 196608) dc[i - 131072] = __float2half_rn(c[i - 131072]);
}

__global__ void k_packWo(const float* __restrict__ s, __half* __restrict__ d)
{
    int i = blockIdx.x * 256 + threadIdx.x;
    if (i < 589824) {
        int o = i / 2304, r = i - o * 2304;
        int tap = r >> 8, c = r & 255;
        d[i] = __float2half_rn(s[((size_t)o * 256 + c) * 9 + tap]);
    }
}

__global__ void k_transpose2(const float* __restrict__ xs, const float* __restrict__ ys,
                             __half* __restrict__ xd, __half* __restrict__ yd)
{
    __shared__ float t[32][33];
    int zz = blockIdx.z;
    int b = zz & 3;
    const float* s = ((zz >> 2) ? ys : xs) + (size_t)b * CHW;
    __half* d = ((zz >> 2) ? yd : xd) + (size_t)b * CHW;
    int x = blockIdx.x * 32 + threadIdx.x;
    int yc = blockIdx.y * 32 + threadIdx.y;
#pragma unroll
    for (int j = 0; j < 4; j++)
        t[threadIdx.y + j * 8][threadIdx.x] = s[(size_t)(yc + j * 8) * HWP + x];
    __syncthreads();
    int x2 = blockIdx.y * 32 + threadIdx.x;
    int y2 = blockIdx.x * 32 + threadIdx.y;
#pragma unroll
    for (int j = 0; j < 4; j++)
        d[(size_t)(y2 + j * 8) * 256 + x2] = __float2half_rn(t[threadIdx.x][threadIdx.y + j * 8]);
}

// ---------------- merged softmax (all scales; split-K fused for scale 3) ----------------
__global__ void k_softmax(const float* __restrict__ S, __half* __restrict__ P)
{
    __shared__ float rowb[4096];
    __shared__ float red[256];
    int f = blockIdx.x;
    int s, row;
    if (f < 4096)      { s = 0; row = f; }
    else if (f < 5120) { s = 1; row = f - 4096; }
    else if (f < 5376) { s = 2; row = f - 5120; }
    else               { s = 3; row = f - 5376; }
    int batch = blockIdx.y;
    int nTok = nssF(s);
    int split = (s == 3) ? 64 : 1;
    float alpha = rsqrtf((float)dssF(s));

    size_t bb = soffF(s) + (size_t)batch * split * nTok * nTok;
    int tid = threadIdx.x;
    float mx = -1e30f;
    for (int j = tid * 4; j < nTok; j += 1024) {
        float4 sv = make_float4(0.f, 0.f, 0.f, 0.f);
        for (int sp = 0; sp < split; sp++) {
            float4 v = *(const float4*)&S[bb + ((size_t)sp * nTok + row) * nTok + j];
            sv.x += v.x; sv.y += v.y; sv.z += v.z; sv.w += v.w;
        }
        sv.x *= alpha; sv.y *= alpha; sv.z *= alpha; sv.w *= alpha;
        *(float4*)&rowb[j] = sv;
        mx = fmaxf(mx, fmaxf(fmaxf(sv.x, sv.y), fmaxf(sv.z, sv.w)));
    }
    red[tid] = mx; __syncthreads();
    for (int st = 128; st; st >>= 1) { if (tid < st) red[tid] = fmaxf(red[tid], red[tid + st]); __syncthreads(); }
    mx = red[0]; __syncthreads();
    float sum = 0.f;
    for (int j = tid; j < nTok; j += 256) {
        float e = __expf(rowb[j] - mx);
        rowb[j] = e; sum += e;
    }
    red[tid] = sum; __syncthreads();
    for (int st = 128; st; st >>= 1) { if (tid < st) red[tid] += red[tid + st]; __syncthreads(); }
    float inv = 1.0f / red[0];
    size_t ob = soffF(s) + (size_t)batch * nTok * nTok + (size_t)row * nTok;
    for (int j = tid * 4; j < nTok; j += 1024) {
        __half2 h0 = __floats2half2_rn(rowb[j] * inv, rowb[j + 1] * inv);
        __half2 h1 = __floats2half2_rn(rowb[j + 2] * inv, rowb[j + 3] * inv);
        *(__half2*)&P[ob + j] = h0;
        *(__half2*)&P[ob + j + 2] = h1;
    }
}

// ---------------- batchnorm stats (float4) ----------------
__global__ void k_stats(const float* __restrict__ z, float* __restrict__ meanv, float* __restrict__ rstdv)
{
    __shared__ float rs[256], rs2[256];
    int c = blockIdx.x;
    int tid = threadIdx.x;
    float s = 0.f, s2 = 0.f;
    for (int i = tid * 4; i < 65536; i += 1024) {
        int b = i >> 14, p = i & 16383;
        float4 v = *(const float4*)&z[(((size_t)b * 256 + c) << 14) + p];
        s += v.x + v.y + v.z + v.w;
        s2 += v.x * v.x + v.y * v.y + v.z * v.z + v.w * v.w;
    }
    rs[tid] = s; rs2[tid] = s2; __syncthreads();
    for (int st = 128; st; st >>= 1) {
        if (tid < st) { rs[tid] += rs[tid + st]; rs2[tid] += rs2[tid + st]; }
        __syncthreads();
    }
    if (tid == 0) {
        float m = rs[0] * (1.0f / 65536.0f);
        float var = rs2[0] * (1.0f / 65536.0f) - m * m;
        meanv[c] = m;
        rstdv[c] = rsqrtf(var + 1e-5f);
    }
}

// ---------------- normalize + affine + LeakyReLU (float4) ----------------
__global__ void k_final(float* __restrict__ z, const float* __restrict__ meanv, const float* __restrict__ rstdv,
                        const float* __restrict__ gamma, const float* __restrict__ beta)
{
    size_t idx = ((size_t)blockIdx.x * 1024 + threadIdx.x) * 4;
    int c = (int)((idx >> 14) & 255);
    float m = __ldg(&meanv[c]);
    float sc = __ldg(&rstdv[c]) * __ldg(&gamma[c]);
    float bt = __ldg(&beta[c]);
    float4 v = *(float4*)&z[idx];
    v.x = (v.x - m) * sc + bt; v.y = (v.y - m) * sc + bt;
    v.z = (v.z - m) * sc + bt; v.w = (v.w - m) * sc + bt;
    v.x = v.x >= 0.f ? v.x : 0.2f * v.x;
    v.y = v.y >= 0.f ? v.y : 0.2f * v.y;
    v.z = v.z >= 0.f ? v.z : 0.2f * v.z;
    v.w = v.w >= 0.f ? v.w : 0.2f * v.w;
    *(float4*)&z[idx] = v;
}

// ---------------- host launch ----------------
extern "C" void kernel_launch(void* const* d_in, const int* in_sizes, int n_in,
                              void* d_out, int out_size)
{
    (void)in_sizes; (void)n_in; (void)out_size;
    const float* x     = (const float*)d_in[0];
    const float* y     = (const float*)d_in[1];
    const float* Wq    = (const float*)d_in[2];
    const float* bq    = (const float*)d_in[3];
    const float* Wk    = (const float*)d_in[4];
    const float* bk    = (const float*)d_in[5];
    const float* Wv    = (const float*)d_in[6];
    const float* bv    = (const float*)d_in[7];
    const float* Wo    = (const float*)d_in[8];
    const float* bo    = (const float*)d_in[9];
    const float* gamma = (const float*)d_in[10];
    const float* beta  = (const float*)d_in[11];
    float* out = (float*)d_out;

    __half *qt, *kt, *vt, *P, *attnT, *xT, *yT, *WqH, *WkH, *WvH, *WoH;
    float *S, *meanv, *rstdv;
    cudaGetSymbolAddress((void**)&qt,    g_qt);
    cudaGetSymbolAddress((void**)&kt,    g_kt);
    cudaGetSymbolAddress((void**)&vt,    g_vt);
    cudaGetSymbolAddress((void**)&S,     g_S);
    cudaGetSymbolAddress((void**)&P,     g_P);
    cudaGetSymbolAddress((void**)&attnT, g_attnT);
    cudaGetSymbolAddress((void**)&xT,    g_xT);
    cudaGetSymbolAddress((void**)&yT,    g_yT);
    cudaGetSymbolAddress((void**)&WqH,   g_WqH);
    cudaGetSymbolAddress((void**)&WkH,   g_WkH);
    cudaGetSymbolAddress((void**)&WvH,   g_WvH);
    cudaGetSymbolAddress((void**)&WoH,   g_WoH);
    cudaGetSymbolAddress((void**)&meanv, g_mean);
    cudaGetSymbolAddress((void**)&rstdv, g_rstd);

    const int shm = ST * (128 + 128) * RPH * 2;   // 110592
    cudaFuncSetAttribute(k_proj,   cudaFuncAttributeMaxDynamicSharedMemorySize, shm);
    cudaFuncSetAttribute(k_scores, cudaFuncAttributeMaxDynamicSharedMemorySize, shm);
    cudaFuncSetAttribute(k_pv,     cudaFuncAttributeMaxDynamicSharedMemorySize, shm);
    cudaFuncSetAttribute(k_conv,   cudaFuncAttributeMaxDynamicSharedMemorySize, shm);

    // prep
    k_halfAll<<<768, 256>>>(Wq, Wk, Wv, WqH, WkH, WvH);
    k_packWo<<<2304, 256>>>(Wo, WoH);
    k_transpose2<<<dim3(512, 8, 8), dim3(32, 8)>>>(x, y, xT, yT);

    // merged stages
    k_proj<<<dim3(128, 2, 12), 256, shm>>>(WqH, WkH, WvH, xT, yT, bq, bk, bv, qt, kt, vt);
    k_scores<<<4624, 256, shm>>>(qt, kt, S);
    k_softmax<<<dim3(5440, 4), 256>>>(S, P);
    k_pv<<<1280, 256, shm>>>(P, vt, attnT);
    k_conv<<<dim3(128, 2, 4), 256, shm>>>(WoH, attnT, bo, out);
    k_stats<<<256, 256>>>(out, meanv, rstdv);
    k_final<<<4096, 1024>>>(out, meanv, rstdv, gamma, beta);
}

// round 10
// speedup vs baseline: 6.9606x; 1.1211x over previous
#include <cuda_runtime.h>
#include <cuda_fp16.h>
#include <math.h>
#include <stdint.h>

#define BATCH 4
#define HWP 16384
#define CHW 4194304
#define TOKB 4194304
#define KC 64
#define RPH 72
#define ST 3

// ---------------- scratch ----------------
__device__ __half g_qt[BATCH * TOKB];      // tokens [scale][n][d_new]
__device__ __half g_kt[BATCH * TOKB];
__device__ __half g_vt[BATCH * TOKB];      // V transposed [scale][d_new][n]
__device__ float  g_S[72613888];
__device__ __half g_P[71581696];
__device__ __half g_attnT[BATCH * CHW];    // [b][pixel][channel]
__device__ __half g_xT[BATCH * CHW];
__device__ __half g_yT[BATCH * CHW];
__device__ __half g_WqH[65536];
__device__ __half g_WkH[65536];
__device__ __half g_WvH[65536];
__device__ __half g_WoH[589824];
__device__ float  g_mean[256];
__device__ float  g_rstd[256];

#define SOFF1 67108864ull
#define SOFF2 71303168ull
#define SOFF3 71565312ull

__device__ __forceinline__ int nssF(int s) { return 16384 >> (2 * (s + 1)); }
__device__ __forceinline__ int dssF(int s) { return 64 << (2 * (s + 1)); }
__device__ __forceinline__ size_t soffF(int s) { return s == 0 ? 0ull : (s == 1 ? SOFF1 : (s == 2 ? SOFF2 : SOFF3)); }

// ---------------- helpers ----------------
__device__ __forceinline__ void cpasync16(uint32_t dst, const void* src) {
    asm volatile("cp.async.cg.shared.global [%0], [%1], 16;" :: "r"(dst), "l"(src));
}
__device__ __forceinline__ void cpasync16z(uint32_t dst, const void* src, int srcsz) {
    asm volatile("cp.async.cg.shared.global [%0], [%1], 16, %2;" :: "r"(dst), "l"(src), "r"(srcsz));
}
__device__ __forceinline__ void ldsm4(uint32_t a, uint32_t& r0, uint32_t& r1, uint32_t& r2, uint32_t& r3) {
    asm volatile("ldmatrix.sync.aligned.m8n8.x4.shared.b16 {%0,%1,%2,%3}, [%4];"
                 : "=r"(r0), "=r"(r1), "=r"(r2), "=r"(r3) : "r"(a));
}
__device__ __forceinline__ void mma_f16(float* c, const uint32_t* a, const uint32_t* b) {
    asm volatile("mma.sync.aligned.m16n8k16.row.col.f32.f16.f16.f32 "
                 "{%0,%1,%2,%3}, {%4,%5,%6,%7}, {%8,%9}, {%0,%1,%2,%3};"
                 : "+f"(c[0]), "+f"(c[1]), "+f"(c[2]), "+f"(c[3])
                 : "r"(a[0]), "r"(a[1]), "r"(a[2]), "r"(a[3]), "r"(b[0]), "r"(b[1]));
}

// ---------------- shared 128x128 fp16 mainloop (row-clamped loaders) ----------------
__device__ __forceinline__ void mainloop128(
    const __half* __restrict__ Ab, const __half* __restrict__ Bb,
    int lda, int ldb, int nc, int rmaxA, int rmaxB, int m0, int n0,
    __half* Asm, __half* Bsm, float (&acc)[4][4][4])
{
    int tid = threadIdx.x;
    int lane = tid & 31, wid = tid >> 5;
    int wm = wid >> 2, wn = wid & 3;
    uint32_t sA = (uint32_t)__cvta_generic_to_shared(Asm);
    uint32_t sB = (uint32_t)__cvta_generic_to_shared(Bsm);
    const uint32_t ASTR = 128 * RPH * 2, BSTR = 128 * RPH * 2;

    auto issue = [&](int c) {
        int st = c % ST;
        int k0 = c * KC;
#pragma unroll
        for (int j = 0; j < 4; j++) {
            int i = tid + j * 256;
            int row = i >> 3, seg = (i & 7) << 3;
            int ar = min(m0 + row, rmaxA);
            cpasync16(sA + st * ASTR + (uint32_t)(row * RPH + seg) * 2,
                      Ab + (size_t)ar * lda + k0 + seg);
        }
#pragma unroll
        for (int j = 0; j < 4; j++) {
            int i = tid + j * 256;
            int row = i >> 3, seg = (i & 7) << 3;
            int br = min(n0 + row, rmaxB);
            cpasync16(sB + st * BSTR + (uint32_t)(row * RPH + seg) * 2,
                      Bb + (size_t)br * ldb + k0 + seg);
        }
    };

#pragma unroll
    for (int i = 0; i < 4; i++)
#pragma unroll
        for (int j = 0; j < 4; j++)
#pragma unroll
            for (int e = 0; e < 4; e++) acc[i][j][e] = 0.f;

    int r8 = lane & 7, hi8 = (lane >> 3) & 1, hi16 = (lane >> 4) & 1;
    uint32_t aOff = (uint32_t)((wm * 64 + r8 + hi8 * 8) * RPH * 2 + hi16 * 16);
    uint32_t bOff = (uint32_t)((wn * 32 + r8 + hi8 * 8) * RPH * 2 + hi16 * 16);

    if (0 < nc) issue(0);
    asm volatile("cp.async.commit_group;");
    if (1 < nc) issue(1);
    asm volatile("cp.async.commit_group;");

    for (int c = 0; c < nc; c++) {
        asm volatile("cp.async.wait_group 1;");
        __syncthreads();
        {
            int st = c % ST;
            uint32_t sa = sA + st * ASTR, sb = sB + st * BSTR;
#pragma unroll
            for (int ks = 0; ks < 4; ks++) {
                uint32_t af[4][4], bf[2][4];
#pragma unroll
                for (int mt = 0; mt < 4; mt++)
                    ldsm4(sa + aOff + mt * 16 * RPH * 2 + ks * 32, af[mt][0], af[mt][1], af[mt][2], af[mt][3]);
#pragma unroll
                for (int np = 0; np < 2; np++)
                    ldsm4(sb + bOff + np * 16 * RPH * 2 + ks * 32, bf[np][0], bf[np][1], bf[np][2], bf[np][3]);
#pragma unroll
                for (int mt = 0; mt < 4; mt++)
#pragma unroll
                    for (int np = 0; np < 2; np++) {
                        uint32_t b0[2] = { bf[np][0], bf[np][2] };
                        uint32_t b1[2] = { bf[np][1], bf[np][3] };
                        mma_f16(acc[mt][np * 2 + 0], af[mt], b0);
                        mma_f16(acc[mt][np * 2 + 1], af[mt], b1);
                    }
            }
        }
        if (c + 2 < nc) issue(c + 2);
        asm volatile("cp.async.commit_group;");
    }
}

// ---------------- merged projections: M=pixels, N=channels; coalesced Q/K epilogue ----
__global__ __launch_bounds__(256) void k_proj(
    const __half* __restrict__ Wq, const __half* __restrict__ Wk, const __half* __restrict__ Wv,
    const __half* __restrict__ xT, const __half* __restrict__ yT,
    const float* __restrict__ bq, const float* __restrict__ bk, const float* __restrict__ bv,
    __half* __restrict__ qt, __half* __restrict__ kt, __half* __restrict__ vt)
{
    extern __shared__ __half dynsmem[];
    int which = blockIdx.z >> 2, b = blockIdx.z & 3;
    const __half* A = (which == 0 ? xT : yT) + (size_t)b * CHW;
    const __half* Bw = which == 0 ? Wq : (which == 1 ? Wk : Wv);
    const float* bias = which == 0 ? bq : (which == 1 ? bk : bv);
    __half* outp = (which == 0 ? qt : (which == 1 ? kt : vt)) + (size_t)b * TOKB;

    int m0 = blockIdx.y * 128, n0 = blockIdx.x * 128;   // m: pixels, n: channels
    float acc[4][4][4];
    mainloop128(A, Bw, 256, 256, 4, 16383, 255, m0, n0, dynsmem, dynsmem + ST * 128 * RPH, acc);

    int tid = threadIdx.x, lane = tid & 31, wid = tid >> 5;
    int wm = wid >> 2, wn = wid & 3;
    int g = lane >> 2, q2 = (lane & 3) << 1;

    int colb = n0 + wn * 32;
    int scl = colb >> 6;
    int l = scl + 1, msk = (1 << l) - 1, owlog = 7 - l;
    int dsz = 64 << (2 * l);
    int nTokS = 16384 >> (2 * l);

    float bia0[4], bia1[4];
#pragma unroll
    for (int nt = 0; nt < 4; nt++) {
        bia0[nt] = __ldg(&bias[colb + nt * 8 + q2]);
        bia1[nt] = __ldg(&bias[colb + nt * 8 + q2 + 1]);
    }
    size_t sbase = (size_t)scl << 20;

#pragma unroll
    for (int mt = 0; mt < 4; mt++) {
#pragma unroll
        for (int e2 = 0; e2 < 2; e2++) {
            int p = m0 + wm * 64 + mt * 16 + g + e2 * 8;
            int yy = p >> 7, xx = p & 127;
            int wy = yy >> l, py = yy & msk, wx = xx >> l, px = xx & msk;
            int n = (wy << owlog) | wx;
            int pix = (py << l) | px;
#pragma unroll
            for (int nt = 0; nt < 4; nt++) {
                int cl = (colb + nt * 8 + q2) & 63;
                __half v0 = __float2half_rn(acc[mt][nt][e2 * 2 + 0] + bia0[nt]);
                __half v1 = __float2half_rn(acc[mt][nt][e2 * 2 + 1] + bia1[nt]);
                if (which < 2) {
                    *(__half2*)&outp[sbase + (size_t)n * dsz + pix * 64 + cl] = __halves2half2(v0, v1);
                } else {
                    size_t adr = sbase + (size_t)(pix * 64 + cl) * nTokS + n;
                    outp[adr] = v0;
                    outp[adr + nTokS] = v1;
                }
            }
        }
    }
}

// ---------------- merged scores: all scales (loader unchanged — token rows contiguous) ----
__global__ __launch_bounds__(256) void k_scores(
    const __half* __restrict__ qt, const __half* __restrict__ kt, float* __restrict__ S)
{
    extern __shared__ __half dynsmem[];
    int f = blockIdx.x;
    int s, b, zS, sp = 0, bx, by;
    if (f < 4096)      { s = 0; zS = f >> 10; b = zS; int t = f & 1023; by = t >> 5; bx = t & 31; }
    else if (f < 4352) { s = 1; int r = f - 4096; zS = r >> 6; b = zS; int t = r & 63; by = t >> 3; bx = t & 7; }
    else if (f < 4368) { s = 2; int r = f - 4352; zS = r >> 2; b = zS; int t = r & 3; by = t >> 1; bx = t & 1; }
    else               { s = 3; int zz = f - 4368; zS = zz; b = zz >> 6; sp = zz & 63; bx = 0; by = 0; }

    int nTok = nssF(s), d = dssF(s);
    int Kl = (s == 3) ? 256 : d;
    const __half* Ab = qt + (size_t)b * TOKB + ((size_t)s << 20) + (size_t)sp * 256;
    const __half* Bb = kt + (size_t)b * TOKB + ((size_t)s << 20) + (size_t)sp * 256;
    int m0 = by * 128, n0 = bx * 128;

    float acc[4][4][4];
    mainloop128(Ab, Bb, d, d, Kl / KC, nTok - 1, nTok - 1, m0, n0,
                dynsmem, dynsmem + ST * 128 * RPH, acc);

    float* Sb = S + soffF(s) + (size_t)zS * nTok * nTok;
    int tid = threadIdx.x, lane = tid & 31, wid = tid >> 5;
    int wm = wid >> 2, wn = wid & 3;
    int g = lane >> 2, q2 = (lane & 3) << 1;
#pragma unroll
    for (int mt = 0; mt < 4; mt++) {
        int row0 = m0 + wm * 64 + mt * 16 + g;
#pragma unroll
        for (int e2 = 0; e2 < 2; e2++) {
            int row = row0 + e2 * 8;
            if (row >= nTok) continue;
#pragma unroll
            for (int nt = 0; nt < 4; nt++) {
                int col = n0 + wn * 32 + nt * 8 + q2;
                if (col >= nTok) continue;
                *(float2*)&Sb[(size_t)row * nTok + col] =
                    make_float2(acc[mt][nt][e2 * 2 + 0], acc[mt][nt][e2 * 2 + 1]);
            }
        }
    }
}

// ---------------- merged P@V: coalesced epilogue (d_new = pix*64 + cl) ----------------
__global__ __launch_bounds__(256) void k_pv(
    const __half* __restrict__ P, const __half* __restrict__ vt, __half* __restrict__ attnT)
{
    extern __shared__ __half dynsmem[];
    int f = blockIdx.x;
    int s, b, bx, by;
    if (f < 256)      { s = 0; b = f >> 6; int t = f & 63; by = t >> 1; bx = t & 1; }
    else if (f < 512) { s = 1; int r = f - 256; b = r >> 6; int t = r & 63; by = t >> 3; bx = t & 7; }
    else if (f < 768) { s = 2; int r = f - 512; b = r >> 6; int t = r & 63; bx = t >> 1; by = t & 1; }
    else              { s = 3; int r = f - 768; b = r >> 7; bx = r & 127; by = 0; }

    int nTok = nssF(s), d = dssF(s);
    const __half* Ab = P + soffF(s) + (size_t)b * nTok * nTok;
    const __half* Bb = vt + (size_t)b * TOKB + ((size_t)s << 20);
    int m0 = by * 128, n0 = bx * 128;

    float acc[4][4][4];
    mainloop128(Ab, Bb, nTok, nTok, nTok / KC, nTok - 1, d - 1, m0, n0,
                dynsmem, dynsmem + ST * 128 * RPH, acc);

    int tid = threadIdx.x, lane = tid & 31, wid = tid >> 5;
    int wm = wid >> 2, wn = wid & 3;
    int g = lane >> 2, q2 = (lane & 3) << 1;

    int l = s + 1, msk = (1 << l) - 1, owlog = 7 - l;
    int colb = n0 + wn * 32;
    int pix = colb >> 6;
    int py = pix >> l, px = pix & msk;

#pragma unroll
    for (int mt = 0; mt < 4; mt++) {
        int row0 = m0 + wm * 64 + mt * 16 + g;
#pragma unroll
        for (int e2 = 0; e2 < 2; e2++) {
            int row = row0 + e2 * 8;
            if (row >= nTok) continue;
            int wy = row >> owlog, wx = row & ((1 << owlog) - 1);
            int y = (wy << l) | py, x = (wx << l) | px;
            size_t pbase = ((((size_t)b << 14) + (y << 7) + x) << 8) + (s << 6);
#pragma unroll
            for (int nt = 0; nt < 4; nt++) {
                int cl = (colb + nt * 8 + q2) & 63;
                __half v0 = __float2half_rn(acc[mt][nt][e2 * 2 + 0]);
                __half v1 = __float2half_rn(acc[mt][nt][e2 * 2 + 1]);
                *(__half2*)&attnT[pbase + cl] = __halves2half2(v0, v1);
            }
        }
    }
}

// ---------------- conv3x3 tap-GEMM ----------------
__global__ __launch_bounds__(256) void k_conv(
    const __half* __restrict__ Wo, const __half* __restrict__ attnT,
    const float* __restrict__ bo, float* __restrict__ out)
{
    extern __shared__ __half dynsmem[];
    __half* Asm = dynsmem;
    __half* Bsm = dynsmem + ST * 128 * RPH;
    int tid = threadIdx.x;
    int lane = tid & 31, wid = tid >> 5;
    int wm = wid >> 2, wn = wid & 3;
    int m0 = blockIdx.y * 128, n0 = blockIdx.x * 128;
    int bidx = blockIdx.z;
    const __half* Ab = Wo;
    const __half* Bb = attnT + (size_t)bidx * CHW;

    uint32_t sA = (uint32_t)__cvta_generic_to_shared(Asm);
    uint32_t sB = (uint32_t)__cvta_generic_to_shared(Bsm);
    const uint32_t ASTR = 128 * RPH * 2, BSTR = 128 * RPH * 2;
    const int nc = 36;

    auto issue = [&](int c) {
        int st = c % ST;
        int k0 = c * KC;
#pragma unroll
        for (int j = 0; j < 4; j++) {
            int i = tid + j * 256;
            int row = i >> 3, seg = (i & 7) << 3;
            cpasync16(sA + st * ASTR + (uint32_t)(row * RPH + seg) * 2,
                      Ab + (size_t)(m0 + row) * 2304 + k0 + seg);
        }
        int tap = k0 >> 8;
        int dy = tap / 3, dx = tap - dy * 3;
        int gy = (int)blockIdx.x + dy - 1;
        bool okY = (unsigned)gy < 128u;
#pragma unroll
        for (int j = 0; j < 4; j++) {
            int i = tid + j * 256;
            int xrow = i >> 3, seg = (i & 7) << 3;
            int ch = (k0 & 255) + seg;
            int gx = xrow + dx - 1;
            int sz = (okY && (unsigned)gx < 128u) ? 16 : 0;
            const __half* src = Bb + ((size_t)(gy << 7) + gx) * 256 + ch;
            cpasync16z(sB + st * BSTR + (uint32_t)(xrow * RPH + seg) * 2, src, sz);
        }
    };

    float acc[4][4][4];
#pragma unroll
    for (int i = 0; i < 4; i++)
#pragma unroll
        for (int j = 0; j < 4; j++)
#pragma unroll
            for (int e = 0; e < 4; e++) acc[i][j][e] = 0.f;

    int r8 = lane & 7, hi8 = (lane >> 3) & 1, hi16 = (lane >> 4) & 1;
    uint32_t aOff = (uint32_t)((wm * 64 + r8 + hi8 * 8) * RPH * 2 + hi16 * 16);
    uint32_t bOff = (uint32_t)((wn * 32 + r8 + hi8 * 8) * RPH * 2 + hi16 * 16);

    issue(0);
    asm volatile("cp.async.commit_group;");
    issue(1);
    asm volatile("cp.async.commit_group;");

    for (int c = 0; c < nc; c++) {
        asm volatile("cp.async.wait_group 1;");
        __syncthreads();
        {
            int st = c % ST;
            uint32_t sa = sA + st * ASTR, sb = sB + st * BSTR;
#pragma unroll
            for (int ks = 0; ks < 4; ks++) {
                uint32_t af[4][4], bf[2][4];
#pragma unroll
                for (int mt = 0; mt < 4; mt++)
                    ldsm4(sa + aOff + mt * 16 * RPH * 2 + ks * 32, af[mt][0], af[mt][1], af[mt][2], af[mt][3]);
#pragma unroll
                for (int np = 0; np < 2; np++)
                    ldsm4(sb + bOff + np * 16 * RPH * 2 + ks * 32, bf[np][0], bf[np][1], bf[np][2], bf[np][3]);
#pragma unroll
                for (int mt = 0; mt < 4; mt++)
#pragma unroll
                    for (int np = 0; np < 2; np++) {
                        uint32_t b0[2] = { bf[np][0], bf[np][2] };
                        uint32_t b1[2] = { bf[np][1], bf[np][3] };
                        mma_f16(acc[mt][np * 2 + 0], af[mt], b0);
                        mma_f16(acc[mt][np * 2 + 1], af[mt], b1);
                    }
            }
        }
        if (c + 2 < nc) issue(c + 2);
        asm volatile("cp.async.commit_group;");
    }

    int g = lane >> 2, q2 = (lane & 3) << 1;
#pragma unroll
    for (int mt = 0; mt < 4; mt++) {
        int row0 = m0 + wm * 64 + mt * 16 + g;
#pragma unroll
        for (int e2 = 0; e2 < 2; e2++) {
            int row = row0 + e2 * 8;
            float bia = __ldg(&bo[row]);
#pragma unroll
            for (int nt = 0; nt < 4; nt++) {
                int col = n0 + wn * 32 + nt * 8 + q2;
                size_t adr = (((size_t)bidx * 256 + row) << 14) + col;
                *(float2*)&out[adr] = make_float2(acc[mt][nt][e2 * 2 + 0] + bia,
                                                  acc[mt][nt][e2 * 2 + 1] + bia);
            }
        }
    }
}

// ---------------- prep kernels ----------------
__global__ void k_halfAll(const float* __restrict__ a, const float* __restrict__ b, const float* __restrict__ c,
                          __half* __restrict__ da, __half* __restrict__ db, __half* __restrict__ dc)
{
    int i = blockIdx.x * 256 + threadIdx.x;
    if (i < 65536) da[i] = __float2half_rn(a[i]);
    else if (i < 131072) db[i - 65536] = __float2half_rn(b[i - 65536]);
    else if (i < 196608) dc[i - 131072] = __float2half_rn(c[i - 131072]);
}

__global__ void k_packWo(const float* __restrict__ s, __half* __restrict__ d)
{
    int i = blockIdx.x * 256 + threadIdx.x;
    if (i < 589824) {
        int o = i / 2304, r = i - o * 2304;
        int tap = r >> 8, c = r & 255;
        d[i] = __float2half_rn(s[((size_t)o * 256 + c) * 9 + tap]);
    }
}

__global__ void k_transpose2(const float* __restrict__ xs, const float* __restrict__ ys,
                             __half* __restrict__ xd, __half* __restrict__ yd)
{
    __shared__ float t[32][33];
    int zz = blockIdx.z;
    int b = zz & 3;
    const float* s = ((zz >> 2) ? ys : xs) + (size_t)b * CHW;
    __half* d = ((zz >> 2) ? yd : xd) + (size_t)b * CHW;
    int x = blockIdx.x * 32 + threadIdx.x;
    int yc = blockIdx.y * 32 + threadIdx.y;
#pragma unroll
    for (int j = 0; j < 4; j++)
        t[threadIdx.y + j * 8][threadIdx.x] = s[(size_t)(yc + j * 8) * HWP + x];
    __syncthreads();
    int x2 = blockIdx.y * 32 + threadIdx.x;
    int y2 = blockIdx.x * 32 + threadIdx.y;
#pragma unroll
    for (int j = 0; j < 4; j++)
        d[(size_t)(y2 + j * 8) * 256 + x2] = __float2half_rn(t[threadIdx.x][threadIdx.y + j * 8]);
}

// ---------------- merged softmax ----------------
__global__ void k_softmax(const float* __restrict__ S, __half* __restrict__ P)
{
    __shared__ float rowb[4096];
    __shared__ float red[256];
    int f = blockIdx.x;
    int s, row;
    if (f < 4096)      { s = 0; row = f; }
    else if (f < 5120) { s = 1; row = f - 4096; }
    else if (f < 5376) { s = 2; row = f - 5120; }
    else               { s = 3; row = f - 5376; }
    int batch = blockIdx.y;
    int nTok = nssF(s);
    int split = (s == 3) ? 64 : 1;
    float alpha = rsqrtf((float)dssF(s));

    size_t bb = soffF(s) + (size_t)batch * split * nTok * nTok;
    int tid = threadIdx.x;
    float mx = -1e30f;
    for (int j = tid * 4; j < nTok; j += 1024) {
        float4 sv = make_float4(0.f, 0.f, 0.f, 0.f);
        for (int sp = 0; sp < split; sp++) {
            float4 v = *(const float4*)&S[bb + ((size_t)sp * nTok + row) * nTok + j];
            sv.x += v.x; sv.y += v.y; sv.z += v.z; sv.w += v.w;
        }
        sv.x *= alpha; sv.y *= alpha; sv.z *= alpha; sv.w *= alpha;
        *(float4*)&rowb[j] = sv;
        mx = fmaxf(mx, fmaxf(fmaxf(sv.x, sv.y), fmaxf(sv.z, sv.w)));
    }
    red[tid] = mx; __syncthreads();
    for (int st = 128; st; st >>= 1) { if (tid < st) red[tid] = fmaxf(red[tid], red[tid + st]); __syncthreads(); }
    mx = red[0]; __syncthreads();
    float sum = 0.f;
    for (int j = tid; j < nTok; j += 256) {
        float e = __expf(rowb[j] - mx);
        rowb[j] = e; sum += e;
    }
    red[tid] = sum; __syncthreads();
    for (int st = 128; st; st >>= 1) { if (tid < st) red[tid] += red[tid + st]; __syncthreads(); }
    float inv = 1.0f / red[0];
    size_t ob = soffF(s) + (size_t)batch * nTok * nTok + (size_t)row * nTok;
    for (int j = tid * 4; j < nTok; j += 1024) {
        __half2 h0 = __floats2half2_rn(rowb[j] * inv, rowb[j + 1] * inv);
        __half2 h1 = __floats2half2_rn(rowb[j + 2] * inv, rowb[j + 3] * inv);
        *(__half2*)&P[ob + j] = h0;
        *(__half2*)&P[ob + j + 2] = h1;
    }
}

// ---------------- batchnorm stats ----------------
__global__ void k_stats(const float* __restrict__ z, float* __restrict__ meanv, float* __restrict__ rstdv)
{
    __shared__ float rs[256], rs2[256];
    int c = blockIdx.x;
    int tid = threadIdx.x;
    float s = 0.f, s2 = 0.f;
    for (int i = tid * 4; i < 65536; i += 1024) {
        int b = i >> 14, p = i & 16383;
        float4 v = *(const float4*)&z[(((size_t)b * 256 + c) << 14) + p];
        s += v.x + v.y + v.z + v.w;
        s2 += v.x * v.x + v.y * v.y + v.z * v.z + v.w * v.w;
    }
    rs[tid] = s; rs2[tid] = s2; __syncthreads();
    for (int st = 128; st; st >>= 1) {
        if (tid < st) { rs[tid] += rs[tid + st]; rs2[tid] += rs2[tid + st]; }
        __syncthreads();
    }
    if (tid == 0) {
        float m = rs[0] * (1.0f / 65536.0f);
        float var = rs2[0] * (1.0f / 65536.0f) - m * m;
        meanv[c] = m;
        rstdv[c] = rsqrtf(var + 1e-5f);
    }
}

// ---------------- normalize + affine + LeakyReLU ----------------
__global__ void k_final(float* __restrict__ z, const float* __restrict__ meanv, const float* __restrict__ rstdv,
                        const float* __restrict__ gamma, const float* __restrict__ beta)
{
    size_t idx = ((size_t)blockIdx.x * 1024 + threadIdx.x) * 4;
    int c = (int)((idx >> 14) & 255);
    float m = __ldg(&meanv[c]);
    float sc = __ldg(&rstdv[c]) * __ldg(&gamma[c]);
    float bt = __ldg(&beta[c]);
    float4 v = *(float4*)&z[idx];
    v.x = (v.x - m) * sc + bt; v.y = (v.y - m) * sc + bt;
    v.z = (v.z - m) * sc + bt; v.w = (v.w - m) * sc + bt;
    v.x = v.x >= 0.f ? v.x : 0.2f * v.x;
    v.y = v.y >= 0.f ? v.y : 0.2f * v.y;
    v.z = v.z >= 0.f ? v.z : 0.2f * v.z;
    v.w = v.w >= 0.f ? v.w : 0.2f * v.w;
    *(float4*)&z[idx] = v;
}

// ---------------- host launch ----------------
extern "C" void kernel_launch(void* const* d_in, const int* in_sizes, int n_in,
                              void* d_out, int out_size)
{
    (void)in_sizes; (void)n_in; (void)out_size;
    const float* x     = (const float*)d_in[0];
    const float* y     = (const float*)d_in[1];
    const float* Wq    = (const float*)d_in[2];
    const float* bq    = (const float*)d_in[3];
    const float* Wk    = (const float*)d_in[4];
    const float* bk    = (const float*)d_in[5];
    const float* Wv    = (const float*)d_in[6];
    const float* bv    = (const float*)d_in[7];
    const float* Wo    = (const float*)d_in[8];
    const float* bo    = (const float*)d_in[9];
    const float* gamma = (const float*)d_in[10];
    const float* beta  = (const float*)d_in[11];
    float* out = (float*)d_out;

    __half *qt, *kt, *vt, *P, *attnT, *xT, *yT, *WqH, *WkH, *WvH, *WoH;
    float *S, *meanv, *rstdv;
    cudaGetSymbolAddress((void**)&qt,    g_qt);
    cudaGetSymbolAddress((void**)&kt,    g_kt);
    cudaGetSymbolAddress((void**)&vt,    g_vt);
    cudaGetSymbolAddress((void**)&S,     g_S);
    cudaGetSymbolAddress((void**)&P,     g_P);
    cudaGetSymbolAddress((void**)&attnT, g_attnT);
    cudaGetSymbolAddress((void**)&xT,    g_xT);
    cudaGetSymbolAddress((void**)&yT,    g_yT);
    cudaGetSymbolAddress((void**)&WqH,   g_WqH);
    cudaGetSymbolAddress((void**)&WkH,   g_WkH);
    cudaGetSymbolAddress((void**)&WvH,   g_WvH);
    cudaGetSymbolAddress((void**)&WoH,   g_WoH);
    cudaGetSymbolAddress((void**)&meanv, g_mean);
    cudaGetSymbolAddress((void**)&rstdv, g_rstd);

    const int shm = ST * (128 + 128) * RPH * 2;   // 110592
    cudaFuncSetAttribute(k_proj,   cudaFuncAttributeMaxDynamicSharedMemorySize, shm);
    cudaFuncSetAttribute(k_scores, cudaFuncAttributeMaxDynamicSharedMemorySize, shm);
    cudaFuncSetAttribute(k_pv,     cudaFuncAttributeMaxDynamicSharedMemorySize, shm);
    cudaFuncSetAttribute(k_conv,   cudaFuncAttributeMaxDynamicSharedMemorySize, shm);

    // prep
    k_halfAll<<<768, 256>>>(Wq, Wk, Wv, WqH, WkH, WvH);
    k_packWo<<<2304, 256>>>(Wo, WoH);
    k_transpose2<<<dim3(512, 8, 8), dim3(32, 8)>>>(x, y, xT, yT);

    // merged stages
    k_proj<<<dim3(2, 128, 12), 256, shm>>>(WqH, WkH, WvH, xT, yT, bq, bk, bv, qt, kt, vt);
    k_scores<<<4624, 256, shm>>>(qt, kt, S);
    k_softmax<<<dim3(5440, 4), 256>>>(S, P);
    k_pv<<<1280, 256, shm>>>(P, vt, attnT);
    k_conv<<<dim3(128, 2, 4), 256, shm>>>(WoH, attnT, bo, out);
    k_stats<<<256, 256>>>(out, meanv, rstdv);
    k_final<<<4096, 1024>>>(out, meanv, rstdv, gamma, beta);
}

// round 11
// speedup vs baseline: 7.5674x; 1.0872x over previous
#include <cuda_runtime.h>
#include <cuda_fp16.h>
#include <math.h>
#include <stdint.h>

#define BATCH 4
#define HWP 16384
#define CHW 4194304
#define TOKB 4194304
#define KC 64
#define RPH 72
#define ST 3

// ---------------- scratch ----------------
__device__ __half g_qt[BATCH * TOKB];      // tokens [scale][n][d_new]
__device__ __half g_kt[BATCH * TOKB];
__device__ __half g_vt[BATCH * TOKB];      // V transposed [scale][d_new][n]
__device__ float  g_S[72613888];
__device__ __half g_P[71581696];
__device__ __half g_attnT[BATCH * CHW];    // [b][pixel][channel]
__device__ __half g_xT[BATCH * CHW];
__device__ __half g_yT[BATCH * CHW];
__device__ __half g_WqH[65536];
__device__ __half g_WkH[65536];
__device__ __half g_WvH[65536];
__device__ __half g_WoH[589824];
__device__ float  g_mean[256];
__device__ float  g_rstd[256];

#define SOFF1 67108864ull
#define SOFF2 71303168ull
#define SOFF3 71565312ull

__device__ __forceinline__ int nssF(int s) { return 16384 >> (2 * (s + 1)); }
__device__ __forceinline__ int dssF(int s) { return 64 << (2 * (s + 1)); }
__device__ __forceinline__ size_t soffF(int s) { return s == 0 ? 0ull : (s == 1 ? SOFF1 : (s == 2 ? SOFF2 : SOFF3)); }

// ---------------- helpers ----------------
__device__ __forceinline__ void cpasync16(uint32_t dst, const void* src) {
    asm volatile("cp.async.cg.shared.global [%0], [%1], 16;" :: "r"(dst), "l"(src));
}
__device__ __forceinline__ void cpasync16z(uint32_t dst, const void* src, int srcsz) {
    asm volatile("cp.async.cg.shared.global [%0], [%1], 16, %2;" :: "r"(dst), "l"(src), "r"(srcsz));
}
__device__ __forceinline__ void ldsm4(uint32_t a, uint32_t& r0, uint32_t& r1, uint32_t& r2, uint32_t& r3) {
    asm volatile("ldmatrix.sync.aligned.m8n8.x4.shared.b16 {%0,%1,%2,%3}, [%4];"
                 : "=r"(r0), "=r"(r1), "=r"(r2), "=r"(r3) : "r"(a));
}
__device__ __forceinline__ void mma_f16(float* c, const uint32_t* a, const uint32_t* b) {
    asm volatile("mma.sync.aligned.m16n8k16.row.col.f32.f16.f16.f32 "
                 "{%0,%1,%2,%3}, {%4,%5,%6,%7}, {%8,%9}, {%0,%1,%2,%3};"
                 : "+f"(c[0]), "+f"(c[1]), "+f"(c[2]), "+f"(c[3])
                 : "r"(a[0]), "r"(a[1]), "r"(a[2]), "r"(a[3]), "r"(b[0]), "r"(b[1]));
}

// ---------------- shared 128x128 fp16 mainloop (row-clamped loaders) ----------------
__device__ __forceinline__ void mainloop128(
    const __half* __restrict__ Ab, const __half* __restrict__ Bb,
    int lda, int ldb, int nc, int rmaxA, int rmaxB, int m0, int n0,
    __half* Asm, __half* Bsm, float (&acc)[4][4][4])
{
    int tid = threadIdx.x;
    int lane = tid & 31, wid = tid >> 5;
    int wm = wid >> 2, wn = wid & 3;
    uint32_t sA = (uint32_t)__cvta_generic_to_shared(Asm);
    uint32_t sB = (uint32_t)__cvta_generic_to_shared(Bsm);
    const uint32_t ASTR = 128 * RPH * 2, BSTR = 128 * RPH * 2;

    auto issue = [&](int c) {
        int st = c % ST;
        int k0 = c * KC;
#pragma unroll
        for (int j = 0; j < 4; j++) {
            int i = tid + j * 256;
            int row = i >> 3, seg = (i & 7) << 3;
            int ar = min(m0 + row, rmaxA);
            cpasync16(sA + st * ASTR + (uint32_t)(row * RPH + seg) * 2,
                      Ab + (size_t)ar * lda + k0 + seg);
        }
#pragma unroll
        for (int j = 0; j < 4; j++) {
            int i = tid + j * 256;
            int row = i >> 3, seg = (i & 7) << 3;
            int br = min(n0 + row, rmaxB);
            cpasync16(sB + st * BSTR + (uint32_t)(row * RPH + seg) * 2,
                      Bb + (size_t)br * ldb + k0 + seg);
        }
    };

#pragma unroll
    for (int i = 0; i < 4; i++)
#pragma unroll
        for (int j = 0; j < 4; j++)
#pragma unroll
            for (int e = 0; e < 4; e++) acc[i][j][e] = 0.f;

    int r8 = lane & 7, hi8 = (lane >> 3) & 1, hi16 = (lane >> 4) & 1;
    uint32_t aOff = (uint32_t)((wm * 64 + r8 + hi8 * 8) * RPH * 2 + hi16 * 16);
    uint32_t bOff = (uint32_t)((wn * 32 + r8 + hi8 * 8) * RPH * 2 + hi16 * 16);

    if (0 < nc) issue(0);
    asm volatile("cp.async.commit_group;");
    if (1 < nc) issue(1);
    asm volatile("cp.async.commit_group;");

    for (int c = 0; c < nc; c++) {
        asm volatile("cp.async.wait_group 1;");
        __syncthreads();
        {
            int st = c % ST;
            uint32_t sa = sA + st * ASTR, sb = sB + st * BSTR;
#pragma unroll
            for (int ks = 0; ks < 4; ks++) {
                uint32_t af[4][4], bf[2][4];
#pragma unroll
                for (int mt = 0; mt < 4; mt++)
                    ldsm4(sa + aOff + mt * 16 * RPH * 2 + ks * 32, af[mt][0], af[mt][1], af[mt][2], af[mt][3]);
#pragma unroll
                for (int np = 0; np < 2; np++)
                    ldsm4(sb + bOff + np * 16 * RPH * 2 + ks * 32, bf[np][0], bf[np][1], bf[np][2], bf[np][3]);
#pragma unroll
                for (int mt = 0; mt < 4; mt++)
#pragma unroll
                    for (int np = 0; np < 2; np++) {
                        uint32_t b0[2] = { bf[np][0], bf[np][2] };
                        uint32_t b1[2] = { bf[np][1], bf[np][3] };
                        mma_f16(acc[mt][np * 2 + 0], af[mt], b0);
                        mma_f16(acc[mt][np * 2 + 1], af[mt], b1);
                    }
            }
        }
        if (c + 2 < nc) issue(c + 2);
        asm volatile("cp.async.commit_group;");
    }
}

// ---------------- merged projections: M=pixels(one image row/block), N=channels ------
#define TRP 132   // transpose buffer row stride in halves
__global__ __launch_bounds__(256) void k_proj(
    const __half* __restrict__ Wq, const __half* __restrict__ Wk, const __half* __restrict__ Wv,
    const __half* __restrict__ xT, const __half* __restrict__ yT,
    const float* __restrict__ bq, const float* __restrict__ bk, const float* __restrict__ bv,
    __half* __restrict__ qt, __half* __restrict__ kt, __half* __restrict__ vt)
{
    extern __shared__ __half dynsmem[];
    int which = blockIdx.z >> 2, b = blockIdx.z & 3;
    const __half* A = (which == 0 ? xT : yT) + (size_t)b * CHW;
    const __half* Bw = which == 0 ? Wq : (which == 1 ? Wk : Wv);
    const float* bias = which == 0 ? bq : (which == 1 ? bk : bv);
    __half* outp = (which == 0 ? qt : (which == 1 ? kt : vt)) + (size_t)b * TOKB;

    int m0 = blockIdx.y * 128, n0 = blockIdx.x * 128;   // m: pixels, n: channels
    float acc[4][4][4];
    mainloop128(A, Bw, 256, 256, 4, 16383, 255, m0, n0, dynsmem, dynsmem + ST * 128 * RPH, acc);

    int tid = threadIdx.x, lane = tid & 31, wid = tid >> 5;
    int wm = wid >> 2, wn = wid & 3;
    int g = lane >> 2, q2 = (lane & 3) << 1;
    int colb = n0 + wn * 32;

    float bia0[4], bia1[4];
#pragma unroll
    for (int nt = 0; nt < 4; nt++) {
        bia0[nt] = __ldg(&bias[colb + nt * 8 + q2]);
        bia1[nt] = __ldg(&bias[colb + nt * 8 + q2 + 1]);
    }

    if (which < 2) {
        int scl = colb >> 6;
        int l = scl + 1, msk = (1 << l) - 1, owlog = 7 - l;
        int dsz = 64 << (2 * l);
        size_t sbase = (size_t)scl << 20;
#pragma unroll
        for (int mt = 0; mt < 4; mt++) {
#pragma unroll
            for (int e2 = 0; e2 < 2; e2++) {
                int p = m0 + wm * 64 + mt * 16 + g + e2 * 8;
                int yy = p >> 7, xx = p & 127;
                int wy = yy >> l, py = yy & msk, wx = xx >> l, px = xx & msk;
                int n = (wy << owlog) | wx;
                int pix = (py << l) | px;
#pragma unroll
                for (int nt = 0; nt < 4; nt++) {
                    int cl = (colb + nt * 8 + q2) & 63;
                    __half v0 = __float2half_rn(acc[mt][nt][e2 * 2 + 0] + bia0[nt]);
                    __half v1 = __float2half_rn(acc[mt][nt][e2 * 2 + 1] + bia1[nt]);
                    *(__half2*)&outp[sbase + (size_t)n * dsz + pix * 64 + cl] = __halves2half2(v0, v1);
                }
            }
        }
    } else {
        // V: stage tile in smem, emit coalesced token-run stores
        __syncthreads();
        __half* T = dynsmem;   // [128 pixels][TRP] halves (33.8 KB)
#pragma unroll
        for (int mt = 0; mt < 4; mt++) {
#pragma unroll
            for (int e2 = 0; e2 < 2; e2++) {
                int row = wm * 64 + mt * 16 + g + e2 * 8;
#pragma unroll
                for (int nt = 0; nt < 4; nt++) {
                    int col = wn * 32 + nt * 8 + q2;
                    __half v0 = __float2half_rn(acc[mt][nt][e2 * 2 + 0] + bia0[nt]);
                    __half v1 = __float2half_rn(acc[mt][nt][e2 * 2 + 1] + bia1[nt]);
                    *(__half2*)&T[row * TRP + col] = __halves2half2(v0, v1);
                }
            }
        }
        __syncthreads();
        int yrow = blockIdx.y;   // one image row per block
#pragma unroll
        for (int i = 0; i < 8; i++) {
            int t = tid * 8 + i;             // 2048 run-store tasks
            int h = t >> 10, ht = t & 1023;  // channel half within block
            int cl = ht >> 4, sub = ht & 15;
            int scl = (n0 >> 6) + h;
            int l = scl + 1;
            int px = sub >> (4 - l);
            int chunk = sub & ((16 >> l) - 1);
            int nTokS = 16384 >> (2 * l);
            int py = yrow & ((1 << l) - 1);
            int wy = yrow >> l;
            int d = ((py << l) | px) * 64 + cl;
            int nst = (wy << (7 - l)) + chunk * 8;
            uint4 u;
            __half* tp = (__half*)&u;
#pragma unroll
            for (int r = 0; r < 8; r++) {
                int xx = ((chunk * 8 + r) << l) | px;
                tp[r] = T[xx * TRP + h * 64 + cl];
            }
            *(uint4*)&outp[((size_t)scl << 20) + (size_t)d * nTokS + nst] = u;
        }
    }
}

// ---------------- merged scores: all scales ----------------
__global__ __launch_bounds__(256) void k_scores(
    const __half* __restrict__ qt, const __half* __restrict__ kt, float* __restrict__ S)
{
    extern __shared__ __half dynsmem[];
    int f = blockIdx.x;
    int s, b, zS, sp = 0, bx, by;
    if (f < 4096)      { s = 0; zS = f >> 10; b = zS; int t = f & 1023; by = t >> 5; bx = t & 31; }
    else if (f < 4352) { s = 1; int r = f - 4096; zS = r >> 6; b = zS; int t = r & 63; by = t >> 3; bx = t & 7; }
    else if (f < 4368) { s = 2; int r = f - 4352; zS = r >> 2; b = zS; int t = r & 3; by = t >> 1; bx = t & 1; }
    else               { s = 3; int zz = f - 4368; zS = zz; b = zz >> 6; sp = zz & 63; bx = 0; by = 0; }

    int nTok = nssF(s), d = dssF(s);
    int Kl = (s == 3) ? 256 : d;
    const __half* Ab = qt + (size_t)b * TOKB + ((size_t)s << 20) + (size_t)sp * 256;
    const __half* Bb = kt + (size_t)b * TOKB + ((size_t)s << 20) + (size_t)sp * 256;
    int m0 = by * 128, n0 = bx * 128;

    float acc[4][4][4];
    mainloop128(Ab, Bb, d, d, Kl / KC, nTok - 1, nTok - 1, m0, n0,
                dynsmem, dynsmem + ST * 128 * RPH, acc);

    float* Sb = S + soffF(s) + (size_t)zS * nTok * nTok;
    int tid = threadIdx.x, lane = tid & 31, wid = tid >> 5;
    int wm = wid >> 2, wn = wid & 3;
    int g = lane >> 2, q2 = (lane & 3) << 1;
#pragma unroll
    for (int mt = 0; mt < 4; mt++) {
        int row0 = m0 + wm * 64 + mt * 16 + g;
#pragma unroll
        for (int e2 = 0; e2 < 2; e2++) {
            int row = row0 + e2 * 8;
            if (row >= nTok) continue;
#pragma unroll
            for (int nt = 0; nt < 4; nt++) {
                int col = n0 + wn * 32 + nt * 8 + q2;
                if (col >= nTok) continue;
                *(float2*)&Sb[(size_t)row * nTok + col] =
                    make_float2(acc[mt][nt][e2 * 2 + 0], acc[mt][nt][e2 * 2 + 1]);
            }
        }
    }
}

// ---------------- merged P@V: coalesced epilogue ----------------
__global__ __launch_bounds__(256) void k_pv(
    const __half* __restrict__ P, const __half* __restrict__ vt, __half* __restrict__ attnT)
{
    extern __shared__ __half dynsmem[];
    int f = blockIdx.x;
    int s, b, bx, by;
    if (f < 256)      { s = 0; b = f >> 6; int t = f & 63; by = t >> 1; bx = t & 1; }
    else if (f < 512) { s = 1; int r = f - 256; b = r >> 6; int t = r & 63; by = t >> 3; bx = t & 7; }
    else if (f < 768) { s = 2; int r = f - 512; b = r >> 6; int t = r & 63; bx = t >> 1; by = t & 1; }
    else              { s = 3; int r = f - 768; b = r >> 7; bx = r & 127; by = 0; }

    int nTok = nssF(s), d = dssF(s);
    const __half* Ab = P + soffF(s) + (size_t)b * nTok * nTok;
    const __half* Bb = vt + (size_t)b * TOKB + ((size_t)s << 20);
    int m0 = by * 128, n0 = bx * 128;

    float acc[4][4][4];
    mainloop128(Ab, Bb, nTok, nTok, nTok / KC, nTok - 1, d - 1, m0, n0,
                dynsmem, dynsmem + ST * 128 * RPH, acc);

    int tid = threadIdx.x, lane = tid & 31, wid = tid >> 5;
    int wm = wid >> 2, wn = wid & 3;
    int g = lane >> 2, q2 = (lane & 3) << 1;

    int l = s + 1, msk = (1 << l) - 1, owlog = 7 - l;
    int colb = n0 + wn * 32;
    int pix = colb >> 6;
    int py = pix >> l, px = pix & msk;

#pragma unroll
    for (int mt = 0; mt < 4; mt++) {
        int row0 = m0 + wm * 64 + mt * 16 + g;
#pragma unroll
        for (int e2 = 0; e2 < 2; e2++) {
            int row = row0 + e2 * 8;
            if (row >= nTok) continue;
            int wy = row >> owlog, wx = row & ((1 << owlog) - 1);
            int y = (wy << l) | py, x = (wx << l) | px;
            size_t pbase = ((((size_t)b << 14) + (y << 7) + x) << 8) + (s << 6);
#pragma unroll
            for (int nt = 0; nt < 4; nt++) {
                int cl = (colb + nt * 8 + q2) & 63;
                __half v0 = __float2half_rn(acc[mt][nt][e2 * 2 + 0]);
                __half v1 = __float2half_rn(acc[mt][nt][e2 * 2 + 1]);
                *(__half2*)&attnT[pbase + cl] = __halves2half2(v0, v1);
            }
        }
    }
}

// ---------------- conv3x3 tap-GEMM ----------------
__global__ __launch_bounds__(256) void k_conv(
    const __half* __restrict__ Wo, const __half* __restrict__ attnT,
    const float* __restrict__ bo, float* __restrict__ out)
{
    extern __shared__ __half dynsmem[];
    __half* Asm = dynsmem;
    __half* Bsm = dynsmem + ST * 128 * RPH;
    int tid = threadIdx.x;
    int lane = tid & 31, wid = tid >> 5;
    int wm = wid >> 2, wn = wid & 3;
    int m0 = blockIdx.y * 128, n0 = blockIdx.x * 128;
    int bidx = blockIdx.z;
    const __half* Ab = Wo;
    const __half* Bb = attnT + (size_t)bidx * CHW;

    uint32_t sA = (uint32_t)__cvta_generic_to_shared(Asm);
    uint32_t sB = (uint32_t)__cvta_generic_to_shared(Bsm);
    const uint32_t ASTR = 128 * RPH * 2, BSTR = 128 * RPH * 2;
    const int nc = 36;

    auto issue = [&](int c) {
        int st = c % ST;
        int k0 = c * KC;
#pragma unroll
        for (int j = 0; j < 4; j++) {
            int i = tid + j * 256;
            int row = i >> 3, seg = (i & 7) << 3;
            cpasync16(sA + st * ASTR + (uint32_t)(row * RPH + seg) * 2,
                      Ab + (size_t)(m0 + row) * 2304 + k0 + seg);
        }
        int tap = k0 >> 8;
        int dy = tap / 3, dx = tap - dy * 3;
        int gy = (int)blockIdx.x + dy - 1;
        bool okY = (unsigned)gy < 128u;
#pragma unroll
        for (int j = 0; j < 4; j++) {
            int i = tid + j * 256;
            int xrow = i >> 3, seg = (i & 7) << 3;
            int ch = (k0 & 255) + seg;
            int gx = xrow + dx - 1;
            int sz = (okY && (unsigned)gx < 128u) ? 16 : 0;
            const __half* src = Bb + ((size_t)(gy << 7) + gx) * 256 + ch;
            cpasync16z(sB + st * BSTR + (uint32_t)(xrow * RPH + seg) * 2, src, sz);
        }
    };

    float acc[4][4][4];
#pragma unroll
    for (int i = 0; i < 4; i++)
#pragma unroll
        for (int j = 0; j < 4; j++)
#pragma unroll
            for (int e = 0; e < 4; e++) acc[i][j][e] = 0.f;

    int r8 = lane & 7, hi8 = (lane >> 3) & 1, hi16 = (lane >> 4) & 1;
    uint32_t aOff = (uint32_t)((wm * 64 + r8 + hi8 * 8) * RPH * 2 + hi16 * 16);
    uint32_t bOff = (uint32_t)((wn * 32 + r8 + hi8 * 8) * RPH * 2 + hi16 * 16);

    issue(0);
    asm volatile("cp.async.commit_group;");
    issue(1);
    asm volatile("cp.async.commit_group;");

    for (int c = 0; c < nc; c++) {
        asm volatile("cp.async.wait_group 1;");
        __syncthreads();
        {
            int st = c % ST;
            uint32_t sa = sA + st * ASTR, sb = sB + st * BSTR;
#pragma unroll
            for (int ks = 0; ks < 4; ks++) {
                uint32_t af[4][4], bf[2][4];
#pragma unroll
                for (int mt = 0; mt < 4; mt++)
                    ldsm4(sa + aOff + mt * 16 * RPH * 2 + ks * 32, af[mt][0], af[mt][1], af[mt][2], af[mt][3]);
#pragma unroll
                for (int np = 0; np < 2; np++)
                    ldsm4(sb + bOff + np * 16 * RPH * 2 + ks * 32, bf[np][0], bf[np][1], bf[np][2], bf[np][3]);
#pragma unroll
                for (int mt = 0; mt < 4; mt++)
#pragma unroll
                    for (int np = 0; np < 2; np++) {
                        uint32_t b0[2] = { bf[np][0], bf[np][2] };
                        uint32_t b1[2] = { bf[np][1], bf[np][3] };
                        mma_f16(acc[mt][np * 2 + 0], af[mt], b0);
                        mma_f16(acc[mt][np * 2 + 1], af[mt], b1);
                    }
            }
        }
        if (c + 2 < nc) issue(c + 2);
        asm volatile("cp.async.commit_group;");
    }

    int g = lane >> 2, q2 = (lane & 3) << 1;
#pragma unroll
    for (int mt = 0; mt < 4; mt++) {
        int row0 = m0 + wm * 64 + mt * 16 + g;
#pragma unroll
        for (int e2 = 0; e2 < 2; e2++) {
            int row = row0 + e2 * 8;
            float bia = __ldg(&bo[row]);
#pragma unroll
            for (int nt = 0; nt < 4; nt++) {
                int col = n0 + wn * 32 + nt * 8 + q2;
                size_t adr = (((size_t)bidx * 256 + row) << 14) + col;
                *(float2*)&out[adr] = make_float2(acc[mt][nt][e2 * 2 + 0] + bia,
                                                  acc[mt][nt][e2 * 2 + 1] + bia);
            }
        }
    }
}

// ---------------- prep: all weights in one launch ----------------
__global__ void k_prepW(const float* __restrict__ wq, const float* __restrict__ wk, const float* __restrict__ wv,
                        const float* __restrict__ wo,
                        __half* __restrict__ dq, __half* __restrict__ dk, __half* __restrict__ dv,
                        __half* __restrict__ dwo)
{
    int i = blockIdx.x * 256 + threadIdx.x;
    if (i < 65536) dq[i] = __float2half_rn(wq[i]);
    else if (i < 131072) dk[i - 65536] = __float2half_rn(wk[i - 65536]);
    else if (i < 196608) dv[i - 131072] = __float2half_rn(wv[i - 131072]);
    else {
        int j = i - 196608;
        if (j < 589824) {
            int o = j / 2304, r = j - o * 2304;
            int tap = r >> 8, c = r & 255;
            dwo[j] = __float2half_rn(wo[((size_t)o * 256 + c) * 9 + tap]);
        }
    }
}

__global__ void k_transpose2(const float* __restrict__ xs, const float* __restrict__ ys,
                             __half* __restrict__ xd, __half* __restrict__ yd)
{
    __shared__ float t[32][33];
    int zz = blockIdx.z;
    int b = zz & 3;
    const float* s = ((zz >> 2) ? ys : xs) + (size_t)b * CHW;
    __half* d = ((zz >> 2) ? yd : xd) + (size_t)b * CHW;
    int x = blockIdx.x * 32 + threadIdx.x;
    int yc = blockIdx.y * 32 + threadIdx.y;
#pragma unroll
    for (int j = 0; j < 4; j++)
        t[threadIdx.y + j * 8][threadIdx.x] = s[(size_t)(yc + j * 8) * HWP + x];
    __syncthreads();
    int x2 = blockIdx.y * 32 + threadIdx.x;
    int y2 = blockIdx.x * 32 + threadIdx.y;
#pragma unroll
    for (int j = 0; j < 4; j++)
        d[(size_t)(y2 + j * 8) * 256 + x2] = __float2half_rn(t[threadIdx.x][threadIdx.y + j * 8]);
}

// ---------------- merged softmax ----------------
__global__ void k_softmax(const float* __restrict__ S, __half* __restrict__ P)
{
    __shared__ float rowb[4096];
    __shared__ float red[256];
    int f = blockIdx.x;
    int s, row;
    if (f < 4096)      { s = 0; row = f; }
    else if (f < 5120) { s = 1; row = f - 4096; }
    else if (f < 5376) { s = 2; row = f - 5120; }
    else               { s = 3; row = f - 5376; }
    int batch = blockIdx.y;
    int nTok = nssF(s);
    int split = (s == 3) ? 64 : 1;
    float alpha = rsqrtf((float)dssF(s));

    size_t bb = soffF(s) + (size_t)batch * split * nTok * nTok;
    int tid = threadIdx.x;
    float mx = -1e30f;
    for (int j = tid * 4; j < nTok; j += 1024) {
        float4 sv = make_float4(0.f, 0.f, 0.f, 0.f);
        for (int sp = 0; sp < split; sp++) {
            float4 v = *(const float4*)&S[bb + ((size_t)sp * nTok + row) * nTok + j];
            sv.x += v.x; sv.y += v.y; sv.z += v.z; sv.w += v.w;
        }
        sv.x *= alpha; sv.y *= alpha; sv.z *= alpha; sv.w *= alpha;
        *(float4*)&rowb[j] = sv;
        mx = fmaxf(mx, fmaxf(fmaxf(sv.x, sv.y), fmaxf(sv.z, sv.w)));
    }
    red[tid] = mx; __syncthreads();
    for (int st = 128; st; st >>= 1) { if (tid < st) red[tid] = fmaxf(red[tid], red[tid + st]); __syncthreads(); }
    mx = red[0]; __syncthreads();
    float sum = 0.f;
    for (int j = tid; j < nTok; j += 256) {
        float e = __expf(rowb[j] - mx);
        rowb[j] = e; sum += e;
    }
    red[tid] = sum; __syncthreads();
    for (int st = 128; st; st >>= 1) { if (tid < st) red[tid] += red[tid + st]; __syncthreads(); }
    float inv = 1.0f / red[0];
    size_t ob = soffF(s) + (size_t)batch * nTok * nTok + (size_t)row * nTok;
    for (int j = tid * 4; j < nTok; j += 1024) {
        __half2 h0 = __floats2half2_rn(rowb[j] * inv, rowb[j + 1] * inv);
        __half2 h1 = __floats2half2_rn(rowb[j + 2] * inv, rowb[j + 3] * inv);
        *(__half2*)&P[ob + j] = h0;
        *(__half2*)&P[ob + j + 2] = h1;
    }
}

// ---------------- batchnorm stats ----------------
__global__ void k_stats(const float* __restrict__ z, float* __restrict__ meanv, float* __restrict__ rstdv)
{
    __shared__ float rs[256], rs2[256];
    int c = blockIdx.x;
    int tid = threadIdx.x;
    float s = 0.f, s2 = 0.f;
    for (int i = tid * 4; i < 65536; i += 1024) {
        int b = i >> 14, p = i & 16383;
        float4 v = *(const float4*)&z[(((size_t)b * 256 + c) << 14) + p];
        s += v.x + v.y + v.z + v.w;
        s2 += v.x * v.x + v.y * v.y + v.z * v.z + v.w * v.w;
    }
    rs[tid] = s; rs2[tid] = s2; __syncthreads();
    for (int st = 128; st; st >>= 1) {
        if (tid < st) { rs[tid] += rs[tid + st]; rs2[tid] += rs2[tid + st]; }
        __syncthreads();
    }
    if (tid == 0) {
        float m = rs[0] * (1.0f / 65536.0f);
        float var = rs2[0] * (1.0f / 65536.0f) - m * m;
        meanv[c] = m;
        rstdv[c] = rsqrtf(var + 1e-5f);
    }
}

// ---------------- normalize + affine + LeakyReLU ----------------
__global__ void k_final(float* __restrict__ z, const float* __restrict__ meanv, const float* __restrict__ rstdv,
                        const float* __restrict__ gamma, const float* __restrict__ beta)
{
    size_t idx = ((size_t)blockIdx.x * 1024 + threadIdx.x) * 4;
    int c = (int)((idx >> 14) & 255);
    float m = __ldg(&meanv[c]);
    float sc = __ldg(&rstdv[c]) * __ldg(&gamma[c]);
    float bt = __ldg(&beta[c]);
    float4 v = *(float4*)&z[idx];
    v.x = (v.x - m) * sc + bt; v.y = (v.y - m) * sc + bt;
    v.z = (v.z - m) * sc + bt; v.w = (v.w - m) * sc + bt;
    v.x = v.x >= 0.f ? v.x : 0.2f * v.x;
    v.y = v.y >= 0.f ? v.y : 0.2f * v.y;
    v.z = v.z >= 0.f ? v.z : 0.2f * v.z;
    v.w = v.w >= 0.f ? v.w : 0.2f * v.w;
    *(float4*)&z[idx] = v;
}

// ---------------- host launch ----------------
extern "C" void kernel_launch(void* const* d_in, const int* in_sizes, int n_in,
                              void* d_out, int out_size)
{
    (void)in_sizes; (void)n_in; (void)out_size;
    const float* x     = (const float*)d_in[0];
    const float* y     = (const float*)d_in[1];
    const float* Wq    = (const float*)d_in[2];
    const float* bq    = (const float*)d_in[3];
    const float* Wk    = (const float*)d_in[4];
    const float* bk    = (const float*)d_in[5];
    const float* Wv    = (const float*)d_in[6];
    const float* bv    = (const float*)d_in[7];
    const float* Wo    = (const float*)d_in[8];
    const float* bo    = (const float*)d_in[9];
    const float* gamma = (const float*)d_in[10];
    const float* beta  = (const float*)d_in[11];
    float* out = (float*)d_out;

    __half *qt, *kt, *vt, *P, *attnT, *xT, *yT, *WqH, *WkH, *WvH, *WoH;
    float *S, *meanv, *rstdv;
    cudaGetSymbolAddress((void**)&qt,    g_qt);
    cudaGetSymbolAddress((void**)&kt,    g_kt);
    cudaGetSymbolAddress((void**)&vt,    g_vt);
    cudaGetSymbolAddress((void**)&S,     g_S);
    cudaGetSymbolAddress((void**)&P,     g_P);
    cudaGetSymbolAddress((void**)&attnT, g_attnT);
    cudaGetSymbolAddress((void**)&xT,    g_xT);
    cudaGetSymbolAddress((void**)&yT,    g_yT);
    cudaGetSymbolAddress((void**)&WqH,   g_WqH);
    cudaGetSymbolAddress((void**)&WkH,   g_WkH);
    cudaGetSymbolAddress((void**)&WvH,   g_WvH);
    cudaGetSymbolAddress((void**)&WoH,   g_WoH);
    cudaGetSymbolAddress((void**)&meanv, g_mean);
    cudaGetSymbolAddress((void**)&rstdv, g_rstd);

    const int shm = ST * (128 + 128) * RPH * 2;   // 110592
    cudaFuncSetAttribute(k_proj,   cudaFuncAttributeMaxDynamicSharedMemorySize, shm);
    cudaFuncSetAttribute(k_scores, cudaFuncAttributeMaxDynamicSharedMemorySize, shm);
    cudaFuncSetAttribute(k_pv,     cudaFuncAttributeMaxDynamicSharedMemorySize, shm);
    cudaFuncSetAttribute(k_conv,   cudaFuncAttributeMaxDynamicSharedMemorySize, shm);

    // prep
    k_prepW<<<3072, 256>>>(Wq, Wk, Wv, Wo, WqH, WkH, WvH, WoH);
    k_transpose2<<<dim3(512, 8, 8), dim3(32, 8)>>>(x, y, xT, yT);

    // merged stages
    k_proj<<<dim3(2, 128, 12), 256, shm>>>(WqH, WkH, WvH, xT, yT, bq, bk, bv, qt, kt, vt);
    k_scores<<<4624, 256, shm>>>(qt, kt, S);
    k_softmax<<<dim3(5440, 4), 256>>>(S, P);
    k_pv<<<1280, 256, shm>>>(P, vt, attnT);
    k_conv<<<dim3(128, 2, 4), 256, shm>>>(WoH, attnT, bo, out);
    k_stats<<<256, 256>>>(out, meanv, rstdv);
    k_final<<<4096, 1024>>>(out, meanv, rstdv, gamma, beta);
}

// round 13
// speedup vs baseline: 8.3796x; 1.1073x over previous
#include <cuda_runtime.h>
#include <cuda_fp16.h>
#include <math.h>
#include <stdint.h>

#define BATCH 4
#define HWP 16384
#define CHW 4194304
#define TOKB 4194304
#define KC 64
#define RPH 72
#define ST 3

// ---------------- scratch ----------------
__device__ __half g_qt[BATCH * TOKB];      // tokens [scale][n][d_new]
__device__ __half g_kt[BATCH * TOKB];
__device__ __half g_vt[BATCH * TOKB];      // V transposed [scale][d_new][n]
__device__ float  g_S3[1048576];           // scale-3 split-K partials
__device__ __half g_P[71581696];           // unnormalized exp(scores)
__device__ float  g_invZ[4 * 5440];        // per-row 1/sum
__device__ __half g_attnT[BATCH * CHW];    // [b][pixel][channel]
__device__ __half g_xT[BATCH * CHW];
__device__ __half g_yT[BATCH * CHW];
__device__ __half g_WqH[65536];
__device__ __half g_WkH[65536];
__device__ __half g_WvH[65536];
__device__ __half g_WoH[589824];
__device__ float  g_mean[256];
__device__ float  g_rstd[256];

#define SOFF1 67108864ull
#define SOFF2 71303168ull
#define SOFF3 71565312ull

__device__ __forceinline__ int nssF(int s) { return 16384 >> (2 * (s + 1)); }
__device__ __forceinline__ int dssF(int s) { return 64 << (2 * (s + 1)); }
__device__ __forceinline__ size_t soffF(int s) { return s == 0 ? 0ull : (s == 1 ? SOFF1 : (s == 2 ? SOFF2 : SOFF3)); }

// ---------------- helpers ----------------
__device__ __forceinline__ void cpasync16(uint32_t dst, const void* src) {
    asm volatile("cp.async.cg.shared.global [%0], [%1], 16;" :: "r"(dst), "l"(src));
}
__device__ __forceinline__ void cpasync16z(uint32_t dst, const void* src, int srcsz) {
    asm volatile("cp.async.cg.shared.global [%0], [%1], 16, %2;" :: "r"(dst), "l"(src), "r"(srcsz));
}
__device__ __forceinline__ void ldsm4(uint32_t a, uint32_t& r0, uint32_t& r1, uint32_t& r2, uint32_t& r3) {
    asm volatile("ldmatrix.sync.aligned.m8n8.x4.shared.b16 {%0,%1,%2,%3}, [%4];"
                 : "=r"(r0), "=r"(r1), "=r"(r2), "=r"(r3) : "r"(a));
}
__device__ __forceinline__ void mma_f16(float* c, const uint32_t* a, const uint32_t* b) {
    asm volatile("mma.sync.aligned.m16n8k16.row.col.f32.f16.f16.f32 "
                 "{%0,%1,%2,%3}, {%4,%5,%6,%7}, {%8,%9}, {%0,%1,%2,%3};"
                 : "+f"(c[0]), "+f"(c[1]), "+f"(c[2]), "+f"(c[3])
                 : "r"(a[0]), "r"(a[1]), "r"(a[2]), "r"(a[3]), "r"(b[0]), "r"(b[1]));
}

// ---------------- shared 128x128 fp16 mainloop (row-clamped loaders) ----------------
__device__ __forceinline__ void mainloop128(
    const __half* __restrict__ Ab, const __half* __restrict__ Bb,
    int lda, int ldb, int nc, int rmaxA, int rmaxB, int m0, int n0,
    __half* Asm, __half* Bsm, float (&acc)[4][4][4])
{
    int tid = threadIdx.x;
    int lane = tid & 31, wid = tid >> 5;
    int wm = wid >> 2, wn = wid & 3;
    uint32_t sA = (uint32_t)__cvta_generic_to_shared(Asm);
    uint32_t sB = (uint32_t)__cvta_generic_to_shared(Bsm);
    const uint32_t ASTR = 128 * RPH * 2, BSTR = 128 * RPH * 2;

    auto issue = [&](int c) {
        int st = c % ST;
        int k0 = c * KC;
#pragma unroll
        for (int j = 0; j < 4; j++) {
            int i = tid + j * 256;
            int row = i >> 3, seg = (i & 7) << 3;
            int ar = min(m0 + row, rmaxA);
            cpasync16(sA + st * ASTR + (uint32_t)(row * RPH + seg) * 2,
                      Ab + (size_t)ar * lda + k0 + seg);
        }
#pragma unroll
        for (int j = 0; j < 4; j++) {
            int i = tid + j * 256;
            int row = i >> 3, seg = (i & 7) << 3;
            int br = min(n0 + row, rmaxB);
            cpasync16(sB + st * BSTR + (uint32_t)(row * RPH + seg) * 2,
                      Bb + (size_t)br * ldb + k0 + seg);
        }
    };

#pragma unroll
    for (int i = 0; i < 4; i++)
#pragma unroll
        for (int j = 0; j < 4; j++)
#pragma unroll
            for (int e = 0; e < 4; e++) acc[i][j][e] = 0.f;

    int r8 = lane & 7, hi8 = (lane >> 3) & 1, hi16 = (lane >> 4) & 1;
    uint32_t aOff = (uint32_t)((wm * 64 + r8 + hi8 * 8) * RPH * 2 + hi16 * 16);
    uint32_t bOff = (uint32_t)((wn * 32 + r8 + hi8 * 8) * RPH * 2 + hi16 * 16);

    if (0 < nc) issue(0);
    asm volatile("cp.async.commit_group;");
    if (1 < nc) issue(1);
    asm volatile("cp.async.commit_group;");

    for (int c = 0; c < nc; c++) {
        asm volatile("cp.async.wait_group 1;");
        __syncthreads();
        {
            int st = c % ST;
            uint32_t sa = sA + st * ASTR, sb = sB + st * BSTR;
#pragma unroll
            for (int ks = 0; ks < 4; ks++) {
                uint32_t af[4][4], bf[2][4];
#pragma unroll
                for (int mt = 0; mt < 4; mt++)
                    ldsm4(sa + aOff + mt * 16 * RPH * 2 + ks * 32, af[mt][0], af[mt][1], af[mt][2], af[mt][3]);
#pragma unroll
                for (int np = 0; np < 2; np++)
                    ldsm4(sb + bOff + np * 16 * RPH * 2 + ks * 32, bf[np][0], bf[np][1], bf[np][2], bf[np][3]);
#pragma unroll
                for (int mt = 0; mt < 4; mt++)
#pragma unroll
                    for (int np = 0; np < 2; np++) {
                        uint32_t b0[2] = { bf[np][0], bf[np][2] };
                        uint32_t b1[2] = { bf[np][1], bf[np][3] };
                        mma_f16(acc[mt][np * 2 + 0], af[mt], b0);
                        mma_f16(acc[mt][np * 2 + 1], af[mt], b1);
                    }
            }
        }
        if (c + 2 < nc) issue(c + 2);
        asm volatile("cp.async.commit_group;");
    }
}

// ---------------- merged projections ----------------
#define TRP 132
__global__ __launch_bounds__(256) void k_proj(
    const __half* __restrict__ Wq, const __half* __restrict__ Wk, const __half* __restrict__ Wv,
    const __half* __restrict__ xT, const __half* __restrict__ yT,
    const float* __restrict__ bq, const float* __restrict__ bk, const float* __restrict__ bv,
    __half* __restrict__ qt, __half* __restrict__ kt, __half* __restrict__ vt)
{
    extern __shared__ __half dynsmem[];
    int which = blockIdx.z >> 2, b = blockIdx.z & 3;
    const __half* A = (which == 0 ? xT : yT) + (size_t)b * CHW;
    const __half* Bw = which == 0 ? Wq : (which == 1 ? Wk : Wv);
    const float* bias = which == 0 ? bq : (which == 1 ? bk : bv);
    __half* outp = (which == 0 ? qt : (which == 1 ? kt : vt)) + (size_t)b * TOKB;

    int m0 = blockIdx.y * 128, n0 = blockIdx.x * 128;
    float acc[4][4][4];
    mainloop128(A, Bw, 256, 256, 4, 16383, 255, m0, n0, dynsmem, dynsmem + ST * 128 * RPH, acc);

    int tid = threadIdx.x, lane = tid & 31, wid = tid >> 5;
    int wm = wid >> 2, wn = wid & 3;
    int g = lane >> 2, q2 = (lane & 3) << 1;
    int colb = n0 + wn * 32;

    float bia0[4], bia1[4];
#pragma unroll
    for (int nt = 0; nt < 4; nt++) {
        bia0[nt] = __ldg(&bias[colb + nt * 8 + q2]);
        bia1[nt] = __ldg(&bias[colb + nt * 8 + q2 + 1]);
    }

    if (which < 2) {
        int scl = colb >> 6;
        int l = scl + 1, msk = (1 << l) - 1, owlog = 7 - l;
        int dsz = 64 << (2 * l);
        size_t sbase = (size_t)scl << 20;
#pragma unroll
        for (int mt = 0; mt < 4; mt++) {
#pragma unroll
            for (int e2 = 0; e2 < 2; e2++) {
                int p = m0 + wm * 64 + mt * 16 + g + e2 * 8;
                int yy = p >> 7, xx = p & 127;
                int wy = yy >> l, py = yy & msk, wx = xx >> l, px = xx & msk;
                int n = (wy << owlog) | wx;
                int pix = (py << l) | px;
#pragma unroll
                for (int nt = 0; nt < 4; nt++) {
                    int cl = (colb + nt * 8 + q2) & 63;
                    __half v0 = __float2half_rn(acc[mt][nt][e2 * 2 + 0] + bia0[nt]);
                    __half v1 = __float2half_rn(acc[mt][nt][e2 * 2 + 1] + bia1[nt]);
                    *(__half2*)&outp[sbase + (size_t)n * dsz + pix * 64 + cl] = __halves2half2(v0, v1);
                }
            }
        }
    } else {
        __syncthreads();
        __half* T = dynsmem;
#pragma unroll
        for (int mt = 0; mt < 4; mt++) {
#pragma unroll
            for (int e2 = 0; e2 < 2; e2++) {
                int row = wm * 64 + mt * 16 + g + e2 * 8;
#pragma unroll
                for (int nt = 0; nt < 4; nt++) {
                    int col = wn * 32 + nt * 8 + q2;
                    __half v0 = __float2half_rn(acc[mt][nt][e2 * 2 + 0] + bia0[nt]);
                    __half v1 = __float2half_rn(acc[mt][nt][e2 * 2 + 1] + bia1[nt]);
                    *(__half2*)&T[row * TRP + col] = __halves2half2(v0, v1);
                }
            }
        }
        __syncthreads();
        int yrow = blockIdx.y;
#pragma unroll
        for (int i = 0; i < 8; i++) {
            int t = tid * 8 + i;
            int h = t >> 10, ht = t & 1023;
            int cl = ht >> 4, sub = ht & 15;
            int scl = (n0 >> 6) + h;
            int l = scl + 1;
            int px = sub >> (4 - l);
            int chunk = sub & ((16 >> l) - 1);
            int nTokS = 16384 >> (2 * l);
            int py = yrow & ((1 << l) - 1);
            int wy = yrow >> l;
            int d = ((py << l) | px) * 64 + cl;
            int nst = (wy << (7 - l)) + chunk * 8;
            uint4 u;
            __half* tp = (__half*)&u;
#pragma unroll
            for (int r = 0; r < 8; r++) {
                int xx = ((chunk * 8 + r) << l) | px;
                tp[r] = T[xx * TRP + h * 64 + cl];
            }
            *(uint4*)&outp[((size_t)scl << 20) + (size_t)d * nTokS + nst] = u;
        }
    }
}

// ---------------- merged scores: fused exp -> unnormalized P (fp16) ----------------
__global__ __launch_bounds__(256) void k_scores(
    const __half* __restrict__ qt, const __half* __restrict__ kt,
    __half* __restrict__ P, float* __restrict__ S3)
{
    extern __shared__ __half dynsmem[];
    int f = blockIdx.x;
    int s, b, zS, sp = 0, bx, by;
    if (f < 4096)      { s = 0; zS = f >> 10; b = zS; int t = f & 1023; by = t >> 5; bx = t & 31; }
    else if (f < 4352) { s = 1; int r = f - 4096; zS = r >> 6; b = zS; int t = r & 63; by = t >> 3; bx = t & 7; }
    else if (f < 4368) { s = 2; int r = f - 4352; zS = r >> 2; b = zS; int t = r & 3; by = t >> 1; bx = t & 1; }
    else               { s = 3; int zz = f - 4368; zS = zz; b = zz >> 6; sp = zz & 63; bx = 0; by = 0; }

    int nTok = nssF(s), d = dssF(s);
    int Kl = (s == 3) ? 256 : d;
    const __half* Ab = qt + (size_t)b * TOKB + ((size_t)s << 20) + (size_t)sp * 256;
    const __half* Bb = kt + (size_t)b * TOKB + ((size_t)s << 20) + (size_t)sp * 256;
    int m0 = by * 128, n0 = bx * 128;

    float acc[4][4][4];
    mainloop128(Ab, Bb, d, d, Kl / KC, nTok - 1, nTok - 1, m0, n0,
                dynsmem, dynsmem + ST * 128 * RPH, acc);

    int tid = threadIdx.x, lane = tid & 31, wid = tid >> 5;
    int wm = wid >> 2, wn = wid & 3;
    int g = lane >> 2, q2 = (lane & 3) << 1;

    if (s < 3) {
        float alpha = rsqrtf((float)d);
        __half* Pb = P + soffF(s) + (size_t)zS * nTok * nTok;
#pragma unroll
        for (int mt = 0; mt < 4; mt++) {
            int row0 = m0 + wm * 64 + mt * 16 + g;
#pragma unroll
            for (int e2 = 0; e2 < 2; e2++) {
                int row = row0 + e2 * 8;
#pragma unroll
                for (int nt = 0; nt < 4; nt++) {
                    int col = n0 + wn * 32 + nt * 8 + q2;
                    float e0 = __expf(acc[mt][nt][e2 * 2 + 0] * alpha);
                    float e1 = __expf(acc[mt][nt][e2 * 2 + 1] * alpha);
                    *(__half2*)&Pb[(size_t)row * nTok + col] = __floats2half2_rn(e0, e1);
                }
            }
        }
    } else {
        float* Sb = S3 + (size_t)zS * 4096;
#pragma unroll
        for (int mt = 0; mt < 4; mt++) {
            int row0 = m0 + wm * 64 + mt * 16 + g;
#pragma unroll
            for (int e2 = 0; e2 < 2; e2++) {
                int row = row0 + e2 * 8;
                if (row >= 64) continue;
#pragma unroll
                for (int nt = 0; nt < 4; nt++) {
                    int col = n0 + wn * 32 + nt * 8 + q2;
                    if (col >= 64) continue;
                    *(float2*)&Sb[(size_t)row * 64 + col] =
                        make_float2(acc[mt][nt][e2 * 2 + 0], acc[mt][nt][e2 * 2 + 1]);
                }
            }
        }
    }
}

// ---------------- norm: row sums -> invZ (s0-2); s3 split-reduce + exp + Z ----------
__global__ void k_norm(const __half* __restrict__ P, const float* __restrict__ S3,
                       __half* __restrict__ P3out, float* __restrict__ invZ)
{
    __shared__ float red[256];
    int f = blockIdx.x;
    int b = blockIdx.y;
    int tid = threadIdx.x;

    if (f < 5376) {
        int s, row;
        if (f < 4096)      { s = 0; row = f; }
        else if (f < 5120) { s = 1; row = f - 4096; }
        else               { s = 2; row = f - 5120; }
        int nTok = nssF(s);
        const __half* Pr = P + soffF(s) + (size_t)b * nTok * nTok + (size_t)row * nTok;
        float sum = 0.f;
        for (int j = tid * 8; j < nTok; j += 2048) {
            uint4 u = *(const uint4*)&Pr[j];
            const __half2* h2 = (const __half2*)&u;
#pragma unroll
            for (int q = 0; q < 4; q++) {
                float2 fv = __half22float2(h2[q]);
                sum += fv.x + fv.y;
            }
        }
        red[tid] = sum; __syncthreads();
        for (int st = 128; st; st >>= 1) { if (tid < st) red[tid] += red[tid + st]; __syncthreads(); }
        if (tid == 0) invZ[b * 5440 + f] = 1.0f / red[0];
    } else {
        int row = f - 5376;   // 0..63
        float e = 0.f;
        if (tid < 64) {
            float sv = 0.f;
            for (int sp = 0; sp < 64; sp++)
                sv += S3[(size_t)((b << 6) + sp) * 4096 + row * 64 + tid];
            e = __expf(sv * 0.0078125f);   // alpha = 1/sqrt(16384) = 1/128
            P3out[SOFF3 + (size_t)b * 4096 + row * 64 + tid] = __float2half_rn(e);
        }
        red[tid] = e; __syncthreads();
        for (int st = 128; st; st >>= 1) { if (tid < st) red[tid] += red[tid + st]; __syncthreads(); }
        if (tid == 0) invZ[b * 5440 + f] = 1.0f / red[0];
    }
}

// ---------------- merged P@V: normalize-by-invZ epilogue ----------------
__global__ __launch_bounds__(256) void k_pv(
    const __half* __restrict__ P, const __half* __restrict__ vt,
    const float* __restrict__ invZ, __half* __restrict__ attnT)
{
    extern __shared__ __half dynsmem[];
    int f = blockIdx.x;
    int s, b, bx, by;
    if (f < 256)      { s = 0; b = f >> 6; int t = f & 63; by = t >> 1; bx = t & 1; }
    else if (f < 512) { s = 1; int r = f - 256; b = r >> 6; int t = r & 63; by = t >> 3; bx = t & 7; }
    else if (f < 768) { s = 2; int r = f - 512; b = r >> 6; int t = r & 63; bx = t >> 1; by = t & 1; }
    else              { s = 3; int r = f - 768; b = r >> 7; bx = r & 127; by = 0; }

    int nTok = nssF(s), d = dssF(s);
    const __half* Ab = P + soffF(s) + (size_t)b * nTok * nTok;
    const __half* Bb = vt + (size_t)b * TOKB + ((size_t)s << 20);
    int m0 = by * 128, n0 = bx * 128;

    float acc[4][4][4];
    mainloop128(Ab, Bb, nTok, nTok, nTok / KC, nTok - 1, d - 1, m0, n0,
                dynsmem, dynsmem + ST * 128 * RPH, acc);

    int tid = threadIdx.x, lane = tid & 31, wid = tid >> 5;
    int wm = wid >> 2, wn = wid & 3;
    int g = lane >> 2, q2 = (lane & 3) << 1;

    int l = s + 1, msk = (1 << l) - 1, owlog = 7 - l;
    int colb = n0 + wn * 32;
    int pix = colb >> 6;
    int py = pix >> l, px = pix & msk;
    int rowbase = (s == 0) ? 0 : (s == 1 ? 4096 : (s == 2 ? 5120 : 5376));

#pragma unroll
    for (int mt = 0; mt < 4; mt++) {
        int row0 = m0 + wm * 64 + mt * 16 + g;
#pragma unroll
        for (int e2 = 0; e2 < 2; e2++) {
            int row = row0 + e2 * 8;
            if (row >= nTok) continue;
            float iz = __ldg(&invZ[b * 5440 + rowbase + row]);
            int wy = row >> owlog, wx = row & ((1 << owlog) - 1);
            int y = (wy << l) | py, x = (wx << l) | px;
            size_t pbase = ((((size_t)b << 14) + (y << 7) + x) << 8) + (s << 6);
#pragma unroll
            for (int nt = 0; nt < 4; nt++) {
                int cl = (colb + nt * 8 + q2) & 63;
                __half v0 = __float2half_rn(acc[mt][nt][e2 * 2 + 0] * iz);
                __half v1 = __float2half_rn(acc[mt][nt][e2 * 2 + 1] * iz);
                *(__half2*)&attnT[pbase + cl] = __halves2half2(v0, v1);
            }
        }
    }
}

// ---------------- conv3x3 tap-GEMM ----------------
__global__ __launch_bounds__(256) void k_conv(
    const __half* __restrict__ Wo, const __half* __restrict__ attnT,
    const float* __restrict__ bo, float* __restrict__ out)
{
    extern __shared__ __half dynsmem[];
    __half* Asm = dynsmem;
    __half* Bsm = dynsmem + ST * 128 * RPH;
    int tid = threadIdx.x;
    int lane = tid & 31, wid = tid >> 5;
    int wm = wid >> 2, wn = wid & 3;
    int m0 = blockIdx.y * 128, n0 = blockIdx.x * 128;
    int bidx = blockIdx.z;
    const __half* Ab = Wo;
    const __half* Bb = attnT + (size_t)bidx * CHW;

    uint32_t sA = (uint32_t)__cvta_generic_to_shared(Asm);
    uint32_t sB = (uint32_t)__cvta_generic_to_shared(Bsm);
    const uint32_t ASTR = 128 * RPH * 2, BSTR = 128 * RPH * 2;
    const int nc = 36;

    auto issue = [&](int c) {
        int st = c % ST;
        int k0 = c * KC;
#pragma unroll
        for (int j = 0; j < 4; j++) {
            int i = tid + j * 256;
            int row = i >> 3, seg = (i & 7) << 3;
            cpasync16(sA + st * ASTR + (uint32_t)(row * RPH + seg) * 2,
                      Ab + (size_t)(m0 + row) * 2304 + k0 + seg);
        }
        int tap = k0 >> 8;
        int dy = tap / 3, dx = tap - dy * 3;
        int gy = (int)blockIdx.x + dy - 1;
        bool okY = (unsigned)gy < 128u;
#pragma unroll
        for (int j = 0; j < 4; j++) {
            int i = tid + j * 256;
            int xrow = i >> 3, seg = (i & 7) << 3;
            int ch = (k0 & 255) + seg;
            int gx = xrow + dx - 1;
            int sz = (okY && (unsigned)gx < 128u) ? 16 : 0;
            const __half* src = Bb + ((size_t)(gy << 7) + gx) * 256 + ch;
            cpasync16z(sB + st * BSTR + (uint32_t)(xrow * RPH + seg) * 2, src, sz);
        }
    };

    float acc[4][4][4];
#pragma unroll
    for (int i = 0; i < 4; i++)
#pragma unroll
        for (int j = 0; j < 4; j++)
#pragma unroll
            for (int e = 0; e < 4; e++) acc[i][j][e] = 0.f;

    int r8 = lane & 7, hi8 = (lane >> 3) & 1, hi16 = (lane >> 4) & 1;
    uint32_t aOff = (uint32_t)((wm * 64 + r8 + hi8 * 8) * RPH * 2 + hi16 * 16);
    uint32_t bOff = (uint32_t)((wn * 32 + r8 + hi8 * 8) * RPH * 2 + hi16 * 16);

    issue(0);
    asm volatile("cp.async.commit_group;");
    issue(1);
    asm volatile("cp.async.commit_group;");

    for (int c = 0; c < nc; c++) {
        asm volatile("cp.async.wait_group 1;");
        __syncthreads();
        {
            int st = c % ST;
            uint32_t sa = sA + st * ASTR, sb = sB + st * BSTR;
#pragma unroll
            for (int ks = 0; ks < 4; ks++) {
                uint32_t af[4][4], bf[2][4];
#pragma unroll
                for (int mt = 0; mt < 4; mt++)
                    ldsm4(sa + aOff + mt * 16 * RPH * 2 + ks * 32, af[mt][0], af[mt][1], af[mt][2], af[mt][3]);
#pragma unroll
                for (int np = 0; np < 2; np++)
                    ldsm4(sb + bOff + np * 16 * RPH * 2 + ks * 32, bf[np][0], bf[np][1], bf[np][2], bf[np][3]);
#pragma unroll
                for (int mt = 0; mt < 4; mt++)
#pragma unroll
                    for (int np = 0; np < 2; np++) {
                        uint32_t b0[2] = { bf[np][0], bf[np][2] };
                        uint32_t b1[2] = { bf[np][1], bf[np][3] };
                        mma_f16(acc[mt][np * 2 + 0], af[mt], b0);
                        mma_f16(acc[mt][np * 2 + 1], af[mt], b1);
                    }
            }
        }
        if (c + 2 < nc) issue(c + 2);
        asm volatile("cp.async.commit_group;");
    }

    int g = lane >> 2, q2 = (lane & 3) << 1;
#pragma unroll
    for (int mt = 0; mt < 4; mt++) {
        int row0 = m0 + wm * 64 + mt * 16 + g;
#pragma unroll
        for (int e2 = 0; e2 < 2; e2++) {
            int row = row0 + e2 * 8;
            float bia = __ldg(&bo[row]);
#pragma unroll
            for (int nt = 0; nt < 4; nt++) {
                int col = n0 + wn * 32 + nt * 8 + q2;
                size_t adr = (((size_t)bidx * 256 + row) << 14) + col;
                *(float2*)&out[adr] = make_float2(acc[mt][nt][e2 * 2 + 0] + bia,
                                                  acc[mt][nt][e2 * 2 + 1] + bia);
            }
        }
    }
}

// ---------------- prep ----------------
__global__ void k_prepW(const float* __restrict__ wq, const float* __restrict__ wk, const float* __restrict__ wv,
                        const float* __restrict__ wo,
                        __half* __restrict__ dq, __half* __restrict__ dk, __half* __restrict__ dv,
                        __half* __restrict__ dwo)
{
    int i = blockIdx.x * 256 + threadIdx.x;
    if (i < 65536) dq[i] = __float2half_rn(wq[i]);
    else if (i < 131072) dk[i - 65536] = __float2half_rn(wk[i - 65536]);
    else if (i < 196608) dv[i - 131072] = __float2half_rn(wv[i - 131072]);
    else {
        int j = i - 196608;
        if (j < 589824) {
            int o = j / 2304, r = j - o * 2304;
            int tap = r >> 8, c = r & 255;
            dwo[j] = __float2half_rn(wo[((size_t)o * 256 + c) * 9 + tap]);
        }
    }
}

__global__ void k_transpose2(const float* __restrict__ xs, const float* __restrict__ ys,
                             __half* __restrict__ xd, __half* __restrict__ yd)
{
    __shared__ float t[32][33];
    int zz = blockIdx.z;
    int b = zz & 3;
    const float* s = ((zz >> 2) ? ys : xs) + (size_t)b * CHW;
    __half* d = ((zz >> 2) ? yd : xd) + (size_t)b * CHW;
    int x = blockIdx.x * 32 + threadIdx.x;
    int yc = blockIdx.y * 32 + threadIdx.y;
#pragma unroll
    for (int j = 0; j < 4; j++)
        t[threadIdx.y + j * 8][threadIdx.x] = s[(size_t)(yc + j * 8) * HWP + x];
    __syncthreads();
    int x2 = blockIdx.y * 32 + threadIdx.x;
    int y2 = blockIdx.x * 32 + threadIdx.y;
#pragma unroll
    for (int j = 0; j < 4; j++)
        d[(size_t)(y2 + j * 8) * 256 + x2] = __float2half_rn(t[threadIdx.x][threadIdx.y + j * 8]);
}

// ---------------- batchnorm stats ----------------
__global__ void k_stats(const float* __restrict__ z, float* __restrict__ meanv, float* __restrict__ rstdv)
{
    __shared__ float rs[256], rs2[256];
    int c = blockIdx.x;
    int tid = threadIdx.x;
    float s = 0.f, s2 = 0.f;
    for (int i = tid * 4; i < 65536; i += 1024) {
        int b = i >> 14, p = i & 16383;
        float4 v = *(const float4*)&z[(((size_t)b * 256 + c) << 14) + p];
        s += v.x + v.y + v.z + v.w;
        s2 += v.x * v.x + v.y * v.y + v.z * v.z + v.w * v.w;
    }
    rs[tid] = s; rs2[tid] = s2; __syncthreads();
    for (int st = 128; st; st >>= 1) {
        if (tid < st) { rs[tid] += rs[tid + st]; rs2[tid] += rs2[tid + st]; }
        __syncthreads();
    }
    if (tid == 0) {
        float m = rs[0] * (1.0f / 65536.0f);
        float var = rs2[0] * (1.0f / 65536.0f) - m * m;
        meanv[c] = m;
        rstdv[c] = rsqrtf(var + 1e-5f);
    }
}

// ---------------- normalize + affine + LeakyReLU ----------------
__global__ void k_final(float* __restrict__ z, const float* __restrict__ meanv, const float* __restrict__ rstdv,
                        const float* __restrict__ gamma, const float* __restrict__ beta)
{
    size_t idx = ((size_t)blockIdx.x * 1024 + threadIdx.x) * 4;
    int c = (int)((idx >> 14) & 255);
    float m = __ldg(&meanv[c]);
    float sc = __ldg(&rstdv[c]) * __ldg(&gamma[c]);
    float bt = __ldg(&beta[c]);
    float4 v = *(float4*)&z[idx];
    v.x = (v.x - m) * sc + bt; v.y = (v.y - m) * sc + bt;
    v.z = (v.z - m) * sc + bt; v.w = (v.w - m) * sc + bt;
    v.x = v.x >= 0.f ? v.x : 0.2f * v.x;
    v.y = v.y >= 0.f ? v.y : 0.2f * v.y;
    v.z = v.z >= 0.f ? v.z : 0.2f * v.z;
    v.w = v.w >= 0.f ? v.w : 0.2f * v.w;
    *(float4*)&z[idx] = v;
}

// ---------------- host launch ----------------
extern "C" void kernel_launch(void* const* d_in, const int* in_sizes, int n_in,
                              void* d_out, int out_size)
{
    (void)in_sizes; (void)n_in; (void)out_size;
    const float* x     = (const float*)d_in[0];
    const float* y     = (const float*)d_in[1];
    const float* Wq    = (const float*)d_in[2];
    const float* bq    = (const float*)d_in[3];
    const float* Wk    = (const float*)d_in[4];
    const float* bk    = (const float*)d_in[5];
    const float* Wv    = (const float*)d_in[6];
    const float* bv    = (const float*)d_in[7];
    const float* Wo    = (const float*)d_in[8];
    const float* bo    = (const float*)d_in[9];
    const float* gamma = (const float*)d_in[10];
    const float* beta  = (const float*)d_in[11];
    float* out = (float*)d_out;

    __half *qt, *kt, *vt, *P, *attnT, *xT, *yT, *WqH, *WkH, *WvH, *WoH;
    float *S3, *invZ, *meanv, *rstdv;
    cudaGetSymbolAddress((void**)&qt,    g_qt);
    cudaGetSymbolAddress((void**)&kt,    g_kt);
    cudaGetSymbolAddress((void**)&vt,    g_vt);
    cudaGetSymbolAddress((void**)&S3,    g_S3);
    cudaGetSymbolAddress((void**)&P,     g_P);
    cudaGetSymbolAddress((void**)&invZ,  g_invZ);
    cudaGetSymbolAddress((void**)&attnT, g_attnT);
    cudaGetSymbolAddress((void**)&xT,    g_xT);
    cudaGetSymbolAddress((void**)&yT,    g_yT);
    cudaGetSymbolAddress((void**)&WqH,   g_WqH);
    cudaGetSymbolAddress((void**)&WkH,   g_WkH);
    cudaGetSymbolAddress((void**)&WvH,   g_WvH);
    cudaGetSymbolAddress((void**)&WoH,   g_WoH);
    cudaGetSymbolAddress((void**)&meanv, g_mean);
    cudaGetSymbolAddress((void**)&rstdv, g_rstd);

    const int shm = ST * (128 + 128) * RPH * 2;   // 110592
    cudaFuncSetAttribute(k_proj,   cudaFuncAttributeMaxDynamicSharedMemorySize, shm);
    cudaFuncSetAttribute(k_scores, cudaFuncAttributeMaxDynamicSharedMemorySize, shm);
    cudaFuncSetAttribute(k_pv,     cudaFuncAttributeMaxDynamicSharedMemorySize, shm);
    cudaFuncSetAttribute(k_conv,   cudaFuncAttributeMaxDynamicSharedMemorySize, shm);

    // prep
    k_prepW<<<3072, 256>>>(Wq, Wk, Wv, Wo, WqH, WkH, WvH, WoH);
    k_transpose2<<<dim3(512, 8, 8), dim3(32, 8)>>>(x, y, xT, yT);

    // merged stages
    k_proj<<<dim3(2, 128, 12), 256, shm>>>(WqH, WkH, WvH, xT, yT, bq, bk, bv, qt, kt, vt);
    k_scores<<<4624, 256, shm>>>(qt, kt, P, S3);
    k_norm<<<dim3(5440, 4), 256>>>(P, S3, P, invZ);
    k_pv<<<1280, 256, shm>>>(P, vt, invZ, attnT);
    k_conv<<<dim3(128, 2, 4), 256, shm>>>(WoH, attnT, bo, out);
    k_stats<<<256, 256>>>(out, meanv, rstdv);
    k_final<<<4096, 1024>>>(out, meanv, rstdv, gamma, beta);
}

// round 14
// speedup vs baseline: 8.5108x; 1.0157x over previous
#include <cuda_runtime.h>
#include <cuda_fp16.h>
#include <math.h>
#include <stdint.h>

#define BATCH 4
#define HWP 16384
#define CHW 4194304
#define TOKB 4194304
#define KC 64
#define RPH 72
#define ST 3

// ---------------- scratch ----------------
__device__ __half g_qt[BATCH * TOKB];      // tokens [scale][n][d_new]
__device__ __half g_kt[BATCH * TOKB];
__device__ __half g_vt[BATCH * TOKB];      // V transposed [scale][d_new][n]
__device__ float  g_S3[1048576];           // scale-3 split-K partials
__device__ __half g_P[71581696];           // unnormalized exp(scores)
__device__ float  g_invZ[4 * 5440];        // per-row 1/sum
__device__ float  g_rps[4 * 139776];       // per-block partial row sums (s0-2)
__device__ float  g_cs[131072];            // conv per-channel partial sums  [256][512]
__device__ float  g_cs2[131072];           // conv per-channel partial sumsq [256][512]
__device__ __half g_attnT[BATCH * CHW];    // [b][pixel][channel]
__device__ __half g_xT[BATCH * CHW];
__device__ __half g_yT[BATCH * CHW];
__device__ __half g_WqH[65536];
__device__ __half g_WkH[65536];
__device__ __half g_WvH[65536];
__device__ __half g_WoH[589824];
__device__ float  g_mean[256];
__device__ float  g_rstd[256];

#define SOFF1 67108864ull
#define SOFF2 71303168ull
#define SOFF3 71565312ull
#define RPSB  139776      // per-batch stride of g_rps

__device__ __forceinline__ int nssF(int s) { return 16384 >> (2 * (s + 1)); }
__device__ __forceinline__ int dssF(int s) { return 64 << (2 * (s + 1)); }
__device__ __forceinline__ size_t soffF(int s) { return s == 0 ? 0ull : (s == 1 ? SOFF1 : (s == 2 ? SOFF2 : SOFF3)); }

// ---------------- helpers ----------------
__device__ __forceinline__ void cpasync16(uint32_t dst, const void* src) {
    asm volatile("cp.async.cg.shared.global [%0], [%1], 16;" :: "r"(dst), "l"(src));
}
__device__ __forceinline__ void cpasync16z(uint32_t dst, const void* src, int srcsz) {
    asm volatile("cp.async.cg.shared.global [%0], [%1], 16, %2;" :: "r"(dst), "l"(src), "r"(srcsz));
}
__device__ __forceinline__ void ldsm4(uint32_t a, uint32_t& r0, uint32_t& r1, uint32_t& r2, uint32_t& r3) {
    asm volatile("ldmatrix.sync.aligned.m8n8.x4.shared.b16 {%0,%1,%2,%3}, [%4];"
                 : "=r"(r0), "=r"(r1), "=r"(r2), "=r"(r3) : "r"(a));
}
__device__ __forceinline__ void mma_f16(float* c, const uint32_t* a, const uint32_t* b) {
    asm volatile("mma.sync.aligned.m16n8k16.row.col.f32.f16.f16.f32 "
                 "{%0,%1,%2,%3}, {%4,%5,%6,%7}, {%8,%9}, {%0,%1,%2,%3};"
                 : "+f"(c[0]), "+f"(c[1]), "+f"(c[2]), "+f"(c[3])
                 : "r"(a[0]), "r"(a[1]), "r"(a[2]), "r"(a[3]), "r"(b[0]), "r"(b[1]));
}

// ---------------- shared 128x128 fp16 mainloop (row-clamped loaders) ----------------
__device__ __forceinline__ void mainloop128(
    const __half* __restrict__ Ab, const __half* __restrict__ Bb,
    int lda, int ldb, int nc, int rmaxA, int rmaxB, int m0, int n0,
    __half* Asm, __half* Bsm, float (&acc)[4][4][4])
{
    int tid = threadIdx.x;
    int lane = tid & 31, wid = tid >> 5;
    int wm = wid >> 2, wn = wid & 3;
    uint32_t sA = (uint32_t)__cvta_generic_to_shared(Asm);
    uint32_t sB = (uint32_t)__cvta_generic_to_shared(Bsm);
    const uint32_t ASTR = 128 * RPH * 2, BSTR = 128 * RPH * 2;

    auto issue = [&](int c) {
        int st = c % ST;
        int k0 = c * KC;
#pragma unroll
        for (int j = 0; j < 4; j++) {
            int i = tid + j * 256;
            int row = i >> 3, seg = (i & 7) << 3;
            int ar = min(m0 + row, rmaxA);
            cpasync16(sA + st * ASTR + (uint32_t)(row * RPH + seg) * 2,
                      Ab + (size_t)ar * lda + k0 + seg);
        }
#pragma unroll
        for (int j = 0; j < 4; j++) {
            int i = tid + j * 256;
            int row = i >> 3, seg = (i & 7) << 3;
            int br = min(n0 + row, rmaxB);
            cpasync16(sB + st * BSTR + (uint32_t)(row * RPH + seg) * 2,
                      Bb + (size_t)br * ldb + k0 + seg);
        }
    };

#pragma unroll
    for (int i = 0; i < 4; i++)
#pragma unroll
        for (int j = 0; j < 4; j++)
#pragma unroll
            for (int e = 0; e < 4; e++) acc[i][j][e] = 0.f;

    int r8 = lane & 7, hi8 = (lane >> 3) & 1, hi16 = (lane >> 4) & 1;
    uint32_t aOff = (uint32_t)((wm * 64 + r8 + hi8 * 8) * RPH * 2 + hi16 * 16);
    uint32_t bOff = (uint32_t)((wn * 32 + r8 + hi8 * 8) * RPH * 2 + hi16 * 16);

    if (0 < nc) issue(0);
    asm volatile("cp.async.commit_group;");
    if (1 < nc) issue(1);
    asm volatile("cp.async.commit_group;");

    for (int c = 0; c < nc; c++) {
        asm volatile("cp.async.wait_group 1;");
        __syncthreads();
        {
            int st = c % ST;
            uint32_t sa = sA + st * ASTR, sb = sB + st * BSTR;
#pragma unroll
            for (int ks = 0; ks < 4; ks++) {
                uint32_t af[4][4], bf[2][4];
#pragma unroll
                for (int mt = 0; mt < 4; mt++)
                    ldsm4(sa + aOff + mt * 16 * RPH * 2 + ks * 32, af[mt][0], af[mt][1], af[mt][2], af[mt][3]);
#pragma unroll
                for (int np = 0; np < 2; np++)
                    ldsm4(sb + bOff + np * 16 * RPH * 2 + ks * 32, bf[np][0], bf[np][1], bf[np][2], bf[np][3]);
#pragma unroll
                for (int mt = 0; mt < 4; mt++)
#pragma unroll
                    for (int np = 0; np < 2; np++) {
                        uint32_t b0[2] = { bf[np][0], bf[np][2] };
                        uint32_t b1[2] = { bf[np][1], bf[np][3] };
                        mma_f16(acc[mt][np * 2 + 0], af[mt], b0);
                        mma_f16(acc[mt][np * 2 + 1], af[mt], b1);
                    }
            }
        }
        if (c + 2 < nc) issue(c + 2);
        asm volatile("cp.async.commit_group;");
    }
}

// ---------------- merged projections ----------------
#define TRP 132
__global__ __launch_bounds__(256) void k_proj(
    const __half* __restrict__ Wq, const __half* __restrict__ Wk, const __half* __restrict__ Wv,
    const __half* __restrict__ xT, const __half* __restrict__ yT,
    const float* __restrict__ bq, const float* __restrict__ bk, const float* __restrict__ bv,
    __half* __restrict__ qt, __half* __restrict__ kt, __half* __restrict__ vt)
{
    extern __shared__ __half dynsmem[];
    int which = blockIdx.z >> 2, b = blockIdx.z & 3;
    const __half* A = (which == 0 ? xT : yT) + (size_t)b * CHW;
    const __half* Bw = which == 0 ? Wq : (which == 1 ? Wk : Wv);
    const float* bias = which == 0 ? bq : (which == 1 ? bk : bv);
    __half* outp = (which == 0 ? qt : (which == 1 ? kt : vt)) + (size_t)b * TOKB;

    int m0 = blockIdx.y * 128, n0 = blockIdx.x * 128;
    float acc[4][4][4];
    mainloop128(A, Bw, 256, 256, 4, 16383, 255, m0, n0, dynsmem, dynsmem + ST * 128 * RPH, acc);

    int tid = threadIdx.x, lane = tid & 31, wid = tid >> 5;
    int wm = wid >> 2, wn = wid & 3;
    int g = lane >> 2, q2 = (lane & 3) << 1;
    int colb = n0 + wn * 32;

    float bia0[4], bia1[4];
#pragma unroll
    for (int nt = 0; nt < 4; nt++) {
        bia0[nt] = __ldg(&bias[colb + nt * 8 + q2]);
        bia1[nt] = __ldg(&bias[colb + nt * 8 + q2 + 1]);
    }

    if (which < 2) {
        int scl = colb >> 6;
        int l = scl + 1, msk = (1 << l) - 1, owlog = 7 - l;
        int dsz = 64 << (2 * l);
        size_t sbase = (size_t)scl << 20;
#pragma unroll
        for (int mt = 0; mt < 4; mt++) {
#pragma unroll
            for (int e2 = 0; e2 < 2; e2++) {
                int p = m0 + wm * 64 + mt * 16 + g + e2 * 8;
                int yy = p >> 7, xx = p & 127;
                int wy = yy >> l, py = yy & msk, wx = xx >> l, px = xx & msk;
                int n = (wy << owlog) | wx;
                int pix = (py << l) | px;
#pragma unroll
                for (int nt = 0; nt < 4; nt++) {
                    int cl = (colb + nt * 8 + q2) & 63;
                    __half v0 = __float2half_rn(acc[mt][nt][e2 * 2 + 0] + bia0[nt]);
                    __half v1 = __float2half_rn(acc[mt][nt][e2 * 2 + 1] + bia1[nt]);
                    *(__half2*)&outp[sbase + (size_t)n * dsz + pix * 64 + cl] = __halves2half2(v0, v1);
                }
            }
        }
    } else {
        __syncthreads();
        __half* T = dynsmem;
#pragma unroll
        for (int mt = 0; mt < 4; mt++) {
#pragma unroll
            for (int e2 = 0; e2 < 2; e2++) {
                int row = wm * 64 + mt * 16 + g + e2 * 8;
#pragma unroll
                for (int nt = 0; nt < 4; nt++) {
                    int col = wn * 32 + nt * 8 + q2;
                    __half v0 = __float2half_rn(acc[mt][nt][e2 * 2 + 0] + bia0[nt]);
                    __half v1 = __float2half_rn(acc[mt][nt][e2 * 2 + 1] + bia1[nt]);
                    *(__half2*)&T[row * TRP + col] = __halves2half2(v0, v1);
                }
            }
        }
        __syncthreads();
        int yrow = blockIdx.y;
#pragma unroll
        for (int i = 0; i < 8; i++) {
            int t = tid * 8 + i;
            int h = t >> 10, ht = t & 1023;
            int cl = ht >> 4, sub = ht & 15;
            int scl = (n0 >> 6) + h;
            int l = scl + 1;
            int px = sub >> (4 - l);
            int chunk = sub & ((16 >> l) - 1);
            int nTokS = 16384 >> (2 * l);
            int py = yrow & ((1 << l) - 1);
            int wy = yrow >> l;
            int d = ((py << l) | px) * 64 + cl;
            int nst = (wy << (7 - l)) + chunk * 8;
            uint4 u;
            __half* tp = (__half*)&u;
#pragma unroll
            for (int r = 0; r < 8; r++) {
                int xx = ((chunk * 8 + r) << l) | px;
                tp[r] = T[xx * TRP + h * 64 + cl];
            }
            *(uint4*)&outp[((size_t)scl << 20) + (size_t)d * nTokS + nst] = u;
        }
    }
}

// ---------------- merged scores: fused exp -> P fp16; per-block partial row sums ----
__global__ __launch_bounds__(256) void k_scores(
    const __half* __restrict__ qt, const __half* __restrict__ kt,
    __half* __restrict__ P, float* __restrict__ S3, float* __restrict__ rps)
{
    extern __shared__ __half dynsmem[];
    int f = blockIdx.x;
    int s, b, zS, sp = 0, bx, by;
    if (f < 4096)      { s = 0; zS = f >> 10; b = zS; int t = f & 1023; by = t >> 5; bx = t & 31; }
    else if (f < 4352) { s = 1; int r = f - 4096; zS = r >> 6; b = zS; int t = r & 63; by = t >> 3; bx = t & 7; }
    else if (f < 4368) { s = 2; int r = f - 4352; zS = r >> 2; b = zS; int t = r & 3; by = t >> 1; bx = t & 1; }
    else               { s = 3; int zz = f - 4368; zS = zz; b = zz >> 6; sp = zz & 63; bx = 0; by = 0; }

    int nTok = nssF(s), d = dssF(s);
    int Kl = (s == 3) ? 256 : d;
    const __half* Ab = qt + (size_t)b * TOKB + ((size_t)s << 20) + (size_t)sp * 256;
    const __half* Bb = kt + (size_t)b * TOKB + ((size_t)s << 20) + (size_t)sp * 256;
    int m0 = by * 128, n0 = bx * 128;

    float acc[4][4][4];
    mainloop128(Ab, Bb, d, d, Kl / KC, nTok - 1, nTok - 1, m0, n0,
                dynsmem, dynsmem + ST * 128 * RPH, acc);

    int tid = threadIdx.x, lane = tid & 31, wid = tid >> 5;
    int wm = wid >> 2, wn = wid & 3;
    int g = lane >> 2, q2 = (lane & 3) << 1;

    if (s < 3) {
        __syncthreads();                       // mainloop smem no longer needed
        float* sred = (float*)dynsmem;         // [128 rows][4 wn]
        float alpha = rsqrtf((float)d);
        __half* Pb = P + soffF(s) + (size_t)zS * nTok * nTok;
#pragma unroll
        for (int mt = 0; mt < 4; mt++) {
            int row0 = m0 + wm * 64 + mt * 16 + g;
#pragma unroll
            for (int e2 = 0; e2 < 2; e2++) {
                int row = row0 + e2 * 8;
                float rs = 0.f;
#pragma unroll
                for (int nt = 0; nt < 4; nt++) {
                    int col = n0 + wn * 32 + nt * 8 + q2;
                    float e0 = __expf(acc[mt][nt][e2 * 2 + 0] * alpha);
                    float e1 = __expf(acc[mt][nt][e2 * 2 + 1] * alpha);
                    rs += e0 + e1;
                    *(__half2*)&Pb[(size_t)row * nTok + col] = __floats2half2_rn(e0, e1);
                }
                rs += __shfl_xor_sync(0xffffffff, rs, 1);
                rs += __shfl_xor_sync(0xffffffff, rs, 2);
                if ((lane & 3) == 0)
                    sred[(wm * 64 + mt * 16 + g + e2 * 8) * 4 + wn] = rs;
            }
        }
        __syncthreads();
        if (tid < 128) {
            float tot = sred[tid * 4] + sred[tid * 4 + 1] + sred[tid * 4 + 2] + sred[tid * 4 + 3];
            int nb = nTok >> 7;   // 32 / 8 / 2
            int base = (s == 0) ? 0 : (s == 1 ? 131072 : 139264);
            rps[b * RPSB + base + (m0 + tid) * nb + bx] = tot;
        }
    } else {
        float* Sb = S3 + (size_t)zS * 4096;
#pragma unroll
        for (int mt = 0; mt < 4; mt++) {
            int row0 = m0 + wm * 64 + mt * 16 + g;
#pragma unroll
            for (int e2 = 0; e2 < 2; e2++) {
                int row = row0 + e2 * 8;
                if (row >= 64) continue;
#pragma unroll
                for (int nt = 0; nt < 4; nt++) {
                    int col = n0 + wn * 32 + nt * 8 + q2;
                    if (col >= 64) continue;
                    *(float2*)&Sb[(size_t)row * 64 + col] =
                        make_float2(acc[mt][nt][e2 * 2 + 0], acc[mt][nt][e2 * 2 + 1]);
                }
            }
        }
    }
}

// ---------------- norm: reduce partials -> invZ; s3 split-reduce + exp + Z ----------
__global__ void k_norm(const float* __restrict__ rps, const float* __restrict__ S3,
                       __half* __restrict__ P3out, float* __restrict__ invZ)
{
    __shared__ float red[128];
    int f = blockIdx.x;
    int b = blockIdx.y;
    int tid = threadIdx.x;

    if (f < 5376) {
        int s, row;
        if (f < 4096)      { s = 0; row = f; }
        else if (f < 5120) { s = 1; row = f - 4096; }
        else               { s = 2; row = f - 5120; }
        int nb = nssF(s) >> 7;
        int base = (s == 0) ? 0 : (s == 1 ? 131072 : 139264);
        if (tid < 32) {
            float v = (tid < nb) ? rps[b * RPSB + base + row * nb + tid] : 0.f;
            v += __shfl_xor_sync(0xffffffff, v, 16);
            v += __shfl_xor_sync(0xffffffff, v, 8);
            v += __shfl_xor_sync(0xffffffff, v, 4);
            v += __shfl_xor_sync(0xffffffff, v, 2);
            v += __shfl_xor_sync(0xffffffff, v, 1);
            if (tid == 0) invZ[b * 5440 + f] = 1.0f / v;
        }
    } else {
        int row = f - 5376;   // 0..63
        float e = 0.f;
        if (tid < 64) {
            float sv = 0.f;
            for (int sp = 0; sp < 64; sp++)
                sv += S3[(size_t)((b << 6) + sp) * 4096 + row * 64 + tid];
            e = __expf(sv * 0.0078125f);   // alpha = 1/128
            P3out[SOFF3 + (size_t)b * 4096 + row * 64 + tid] = __float2half_rn(e);
        }
        red[tid] = e; __syncthreads();
        for (int st = 64; st; st >>= 1) { if (tid < st) red[tid] += red[tid + st]; __syncthreads(); }
        if (tid == 0) invZ[b * 5440 + f] = 1.0f / red[0];
    }
}

// ---------------- merged P@V: normalize-by-invZ epilogue ----------------
__global__ __launch_bounds__(256) void k_pv(
    const __half* __restrict__ P, const __half* __restrict__ vt,
    const float* __restrict__ invZ, __half* __restrict__ attnT)
{
    extern __shared__ __half dynsmem[];
    int f = blockIdx.x;
    int s, b, bx, by;
    if (f < 256)      { s = 0; b = f >> 6; int t = f & 63; by = t >> 1; bx = t & 1; }
    else if (f < 512) { s = 1; int r = f - 256; b = r >> 6; int t = r & 63; by = t >> 3; bx = t & 7; }
    else if (f < 768) { s = 2; int r = f - 512; b = r >> 6; int t = r & 63; bx = t >> 1; by = t & 1; }
    else              { s = 3; int r = f - 768; b = r >> 7; bx = r & 127; by = 0; }

    int nTok = nssF(s), d = dssF(s);
    const __half* Ab = P + soffF(s) + (size_t)b * nTok * nTok;
    const __half* Bb = vt + (size_t)b * TOKB + ((size_t)s << 20);
    int m0 = by * 128, n0 = bx * 128;

    float acc[4][4][4];
    mainloop128(Ab, Bb, nTok, nTok, nTok / KC, nTok - 1, d - 1, m0, n0,
                dynsmem, dynsmem + ST * 128 * RPH, acc);

    int tid = threadIdx.x, lane = tid & 31, wid = tid >> 5;
    int wm = wid >> 2, wn = wid & 3;
    int g = lane >> 2, q2 = (lane & 3) << 1;

    int l = s + 1, msk = (1 << l) - 1, owlog = 7 - l;
    int colb = n0 + wn * 32;
    int pix = colb >> 6;
    int py = pix >> l, px = pix & msk;
    int rowbase = (s == 0) ? 0 : (s == 1 ? 4096 : (s == 2 ? 5120 : 5376));

#pragma unroll
    for (int mt = 0; mt < 4; mt++) {
        int row0 = m0 + wm * 64 + mt * 16 + g;
#pragma unroll
        for (int e2 = 0; e2 < 2; e2++) {
            int row = row0 + e2 * 8;
            if (row >= nTok) continue;
            float iz = __ldg(&invZ[b * 5440 + rowbase + row]);
            int wy = row >> owlog, wx = row & ((1 << owlog) - 1);
            int y = (wy << l) | py, x = (wx << l) | px;
            size_t pbase = ((((size_t)b << 14) + (y << 7) + x) << 8) + (s << 6);
#pragma unroll
            for (int nt = 0; nt < 4; nt++) {
                int cl = (colb + nt * 8 + q2) & 63;
                __half v0 = __float2half_rn(acc[mt][nt][e2 * 2 + 0] * iz);
                __half v1 = __float2half_rn(acc[mt][nt][e2 * 2 + 1] * iz);
                *(__half2*)&attnT[pbase + cl] = __halves2half2(v0, v1);
            }
        }
    }
}

// ---------------- conv3x3 tap-GEMM + per-block channel stats partials ----------------
__global__ __launch_bounds__(256) void k_conv(
    const __half* __restrict__ Wo, const __half* __restrict__ attnT,
    const float* __restrict__ bo, float* __restrict__ out,
    float* __restrict__ cs, float* __restrict__ cs2)
{
    extern __shared__ __half dynsmem[];
    __half* Asm = dynsmem;
    __half* Bsm = dynsmem + ST * 128 * RPH;
    int tid = threadIdx.x;
    int lane = tid & 31, wid = tid >> 5;
    int wm = wid >> 2, wn = wid & 3;
    int m0 = blockIdx.y * 128, n0 = blockIdx.x * 128;
    int bidx = blockIdx.z;
    const __half* Ab = Wo;
    const __half* Bb = attnT + (size_t)bidx * CHW;

    uint32_t sA = (uint32_t)__cvta_generic_to_shared(Asm);
    uint32_t sB = (uint32_t)__cvta_generic_to_shared(Bsm);
    const uint32_t ASTR = 128 * RPH * 2, BSTR = 128 * RPH * 2;
    const int nc = 36;

    auto issue = [&](int c) {
        int st = c % ST;
        int k0 = c * KC;
#pragma unroll
        for (int j = 0; j < 4; j++) {
            int i = tid + j * 256;
            int row = i >> 3, seg = (i & 7) << 3;
            cpasync16(sA + st * ASTR + (uint32_t)(row * RPH + seg) * 2,
                      Ab + (size_t)(m0 + row) * 2304 + k0 + seg);
        }
        int tap = k0 >> 8;
        int dy = tap / 3, dx = tap - dy * 3;
        int gy = (int)blockIdx.x + dy - 1;
        bool okY = (unsigned)gy < 128u;
#pragma unroll
        for (int j = 0; j < 4; j++) {
            int i = tid + j * 256;
            int xrow = i >> 3, seg = (i & 7) << 3;
            int ch = (k0 & 255) + seg;
            int gx = xrow + dx - 1;
            int sz = (okY && (unsigned)gx < 128u) ? 16 : 0;
            const __half* src = Bb + ((size_t)(gy << 7) + gx) * 256 + ch;
            cpasync16z(sB + st * BSTR + (uint32_t)(xrow * RPH + seg) * 2, src, sz);
        }
    };

    float acc[4][4][4];
#pragma unroll
    for (int i = 0; i < 4; i++)
#pragma unroll
        for (int j = 0; j < 4; j++)
#pragma unroll
            for (int e = 0; e < 4; e++) acc[i][j][e] = 0.f;

    int r8 = lane & 7, hi8 = (lane >> 3) & 1, hi16 = (lane >> 4) & 1;
    uint32_t aOff = (uint32_t)((wm * 64 + r8 + hi8 * 8) * RPH * 2 + hi16 * 16);
    uint32_t bOff = (uint32_t)((wn * 32 + r8 + hi8 * 8) * RPH * 2 + hi16 * 16);

    issue(0);
    asm volatile("cp.async.commit_group;");
    issue(1);
    asm volatile("cp.async.commit_group;");

    for (int c = 0; c < nc; c++) {
        asm volatile("cp.async.wait_group 1;");
        __syncthreads();
        {
            int st = c % ST;
            uint32_t sa = sA + st * ASTR, sb = sB + st * BSTR;
#pragma unroll
            for (int ks = 0; ks < 4; ks++) {
                uint32_t af[4][4], bf[2][4];
#pragma unroll
                for (int mt = 0; mt < 4; mt++)
                    ldsm4(sa + aOff + mt * 16 * RPH * 2 + ks * 32, af[mt][0], af[mt][1], af[mt][2], af[mt][3]);
#pragma unroll
                for (int np = 0; np < 2; np++)
                    ldsm4(sb + bOff + np * 16 * RPH * 2 + ks * 32, bf[np][0], bf[np][1], bf[np][2], bf[np][3]);
#pragma unroll
                for (int mt = 0; mt < 4; mt++)
#pragma unroll
                    for (int np = 0; np < 2; np++) {
                        uint32_t b0[2] = { bf[np][0], bf[np][2] };
                        uint32_t b1[2] = { bf[np][1], bf[np][3] };
                        mma_f16(acc[mt][np * 2 + 0], af[mt], b0);
                        mma_f16(acc[mt][np * 2 + 1], af[mt], b1);
                    }
            }
        }
        if (c + 2 < nc) issue(c + 2);
        asm volatile("cp.async.commit_group;");
    }

    __syncthreads();                       // smem free for reductions
    float* sred  = (float*)dynsmem;        // [128][4]
    float* sred2 = sred + 512;             // [128][4]
    int g = lane >> 2, q2 = (lane & 3) << 1;
#pragma unroll
    for (int mt = 0; mt < 4; mt++) {
        int row0 = m0 + wm * 64 + mt * 16 + g;
#pragma unroll
        for (int e2 = 0; e2 < 2; e2++) {
            int row = row0 + e2 * 8;
            float bia = __ldg(&bo[row]);
            float rs = 0.f, rs2 = 0.f;
#pragma unroll
            for (int nt = 0; nt < 4; nt++) {
                int col = n0 + wn * 32 + nt * 8 + q2;
                float v0 = acc[mt][nt][e2 * 2 + 0] + bia;
                float v1 = acc[mt][nt][e2 * 2 + 1] + bia;
                rs += v0 + v1;
                rs2 += v0 * v0 + v1 * v1;
                size_t adr = (((size_t)bidx * 256 + row) << 14) + col;
                *(float2*)&out[adr] = make_float2(v0, v1);
            }
            rs  += __shfl_xor_sync(0xffffffff, rs, 1);
            rs  += __shfl_xor_sync(0xffffffff, rs, 2);
            rs2 += __shfl_xor_sync(0xffffffff, rs2, 1);
            rs2 += __shfl_xor_sync(0xffffffff, rs2, 2);
            if ((lane & 3) == 0) {
                int rl = wm * 64 + mt * 16 + g + e2 * 8;
                sred[rl * 4 + wn]  = rs;
                sred2[rl * 4 + wn] = rs2;
            }
        }
    }
    __syncthreads();
    if (tid < 128) {
        float s1 = sred[tid * 4] + sred[tid * 4 + 1] + sred[tid * 4 + 2] + sred[tid * 4 + 3];
        float s2 = sred2[tid * 4] + sred2[tid * 4 + 1] + sred2[tid * 4 + 2] + sred2[tid * 4 + 3];
        int ch = m0 + tid;
        int slot = bidx * 128 + blockIdx.x;
        cs[ch * 512 + slot]  = s1;
        cs2[ch * 512 + slot] = s2;
    }
}

// ---------------- prep ----------------
__global__ void k_prepW(const float* __restrict__ wq, const float* __restrict__ wk, const float* __restrict__ wv,
                        const float* __restrict__ wo,
                        __half* __restrict__ dq, __half* __restrict__ dk, __half* __restrict__ dv,
                        __half* __restrict__ dwo)
{
    int i = blockIdx.x * 256 + threadIdx.x;
    if (i < 65536) dq[i] = __float2half_rn(wq[i]);
    else if (i < 131072) dk[i - 65536] = __float2half_rn(wk[i - 65536]);
    else if (i < 196608) dv[i - 131072] = __float2half_rn(wv[i - 131072]);
    else {
        int j = i - 196608;
        if (j < 589824) {
            int o = j / 2304, r = j - o * 2304;
            int tap = r >> 8, c = r & 255;
            dwo[j] = __float2half_rn(wo[((size_t)o * 256 + c) * 9 + tap]);
        }
    }
}

__global__ void k_transpose2(const float* __restrict__ xs, const float* __restrict__ ys,
                             __half* __restrict__ xd, __half* __restrict__ yd)
{
    __shared__ float t[32][33];
    int zz = blockIdx.z;
    int b = zz & 3;
    const float* s = ((zz >> 2) ? ys : xs) + (size_t)b * CHW;
    __half* d = ((zz >> 2) ? yd : xd) + (size_t)b * CHW;
    int x = blockIdx.x * 32 + threadIdx.x;
    int yc = blockIdx.y * 32 + threadIdx.y;
#pragma unroll
    for (int j = 0; j < 4; j++)
        t[threadIdx.y + j * 8][threadIdx.x] = s[(size_t)(yc + j * 8) * HWP + x];
    __syncthreads();
    int x2 = blockIdx.y * 32 + threadIdx.x;
    int y2 = blockIdx.x * 32 + threadIdx.y;
#pragma unroll
    for (int j = 0; j < 4; j++)
        d[(size_t)(y2 + j * 8) * 256 + x2] = __float2half_rn(t[threadIdx.x][threadIdx.y + j * 8]);
}

// ---------------- batchnorm stats from conv partials ----------------
__global__ void k_stats(const float* __restrict__ cs, const float* __restrict__ cs2,
                        float* __restrict__ meanv, float* __restrict__ rstdv)
{
    __shared__ float rs[256], rs2[256];
    int c = blockIdx.x;
    int tid = threadIdx.x;
    float s  = cs[c * 512 + tid]  + cs[c * 512 + 256 + tid];
    float s2 = cs2[c * 512 + tid] + cs2[c * 512 + 256 + tid];
    rs[tid] = s; rs2[tid] = s2; __syncthreads();
    for (int st = 128; st; st >>= 1) {
        if (tid < st) { rs[tid] += rs[tid + st]; rs2[tid] += rs2[tid + st]; }
        __syncthreads();
    }
    if (tid == 0) {
        float m = rs[0] * (1.0f / 65536.0f);
        float var = rs2[0] * (1.0f / 65536.0f) - m * m;
        meanv[c] = m;
        rstdv[c] = rsqrtf(var + 1e-5f);
    }
}

// ---------------- normalize + affine + LeakyReLU ----------------
__global__ void k_final(float* __restrict__ z, const float* __restrict__ meanv, const float* __restrict__ rstdv,
                        const float* __restrict__ gamma, const float* __restrict__ beta)
{
    size_t idx = ((size_t)blockIdx.x * 1024 + threadIdx.x) * 4;
    int c = (int)((idx >> 14) & 255);
    float m = __ldg(&meanv[c]);
    float sc = __ldg(&rstdv[c]) * __ldg(&gamma[c]);
    float bt = __ldg(&beta[c]);
    float4 v = *(float4*)&z[idx];
    v.x = (v.x - m) * sc + bt; v.y = (v.y - m) * sc + bt;
    v.z = (v.z - m) * sc + bt; v.w = (v.w - m) * sc + bt;
    v.x = v.x >= 0.f ? v.x : 0.2f * v.x;
    v.y = v.y >= 0.f ? v.y : 0.2f * v.y;
    v.z = v.z >= 0.f ? v.z : 0.2f * v.z;
    v.w = v.w >= 0.f ? v.w : 0.2f * v.w;
    *(float4*)&z[idx] = v;
}

// ---------------- host launch ----------------
extern "C" void kernel_launch(void* const* d_in, const int* in_sizes, int n_in,
                              void* d_out, int out_size)
{
    (void)in_sizes; (void)n_in; (void)out_size;
    const float* x     = (const float*)d_in[0];
    const float* y     = (const float*)d_in[1];
    const float* Wq    = (const float*)d_in[2];
    const float* bq    = (const float*)d_in[3];
    const float* Wk    = (const float*)d_in[4];
    const float* bk    = (const float*)d_in[5];
    const float* Wv    = (const float*)d_in[6];
    const float* bv    = (const float*)d_in[7];
    const float* Wo    = (const float*)d_in[8];
    const float* bo    = (const float*)d_in[9];
    const float* gamma = (const float*)d_in[10];
    const float* beta  = (const float*)d_in[11];
    float* out = (float*)d_out;

    __half *qt, *kt, *vt, *P, *attnT, *xT, *yT, *WqH, *WkH, *WvH, *WoH;
    float *S3, *invZ, *rps, *cs, *cs2, *meanv, *rstdv;
    cudaGetSymbolAddress((void**)&qt,    g_qt);
    cudaGetSymbolAddress((void**)&kt,    g_kt);
    cudaGetSymbolAddress((void**)&vt,    g_vt);
    cudaGetSymbolAddress((void**)&S3,    g_S3);
    cudaGetSymbolAddress((void**)&P,     g_P);
    cudaGetSymbolAddress((void**)&invZ,  g_invZ);
    cudaGetSymbolAddress((void**)&rps,   g_rps);
    cudaGetSymbolAddress((void**)&cs,    g_cs);
    cudaGetSymbolAddress((void**)&cs2,   g_cs2);
    cudaGetSymbolAddress((void**)&attnT, g_attnT);
    cudaGetSymbolAddress((void**)&xT,    g_xT);
    cudaGetSymbolAddress((void**)&yT,    g_yT);
    cudaGetSymbolAddress((void**)&WqH,   g_WqH);
    cudaGetSymbolAddress((void**)&WkH,   g_WkH);
    cudaGetSymbolAddress((void**)&WvH,   g_WvH);
    cudaGetSymbolAddress((void**)&WoH,   g_WoH);
    cudaGetSymbolAddress((void**)&meanv, g_mean);
    cudaGetSymbolAddress((void**)&rstdv, g_rstd);

    const int shm = ST * (128 + 128) * RPH * 2;   // 110592
    cudaFuncSetAttribute(k_proj,   cudaFuncAttributeMaxDynamicSharedMemorySize, shm);
    cudaFuncSetAttribute(k_scores, cudaFuncAttributeMaxDynamicSharedMemorySize, shm);
    cudaFuncSetAttribute(k_pv,     cudaFuncAttributeMaxDynamicSharedMemorySize, shm);
    cudaFuncSetAttribute(k_conv,   cudaFuncAttributeMaxDynamicSharedMemorySize, shm);

    // prep
    k_prepW<<<3072, 256>>>(Wq, Wk, Wv, Wo, WqH, WkH, WvH, WoH);
    k_transpose2<<<dim3(512, 8, 8), dim3(32, 8)>>>(x, y, xT, yT);

    // merged stages
    k_proj<<<dim3(2, 128, 12), 256, shm>>>(WqH, WkH, WvH, xT, yT, bq, bk, bv, qt, kt, vt);
    k_scores<<<4624, 256, shm>>>(qt, kt, P, S3, rps);
    k_norm<<<dim3(5440, 4), 128>>>(rps, S3, P, invZ);
    k_pv<<<1280, 256, shm>>>(P, vt, invZ, attnT);
    k_conv<<<dim3(128, 2, 4), 256, shm>>>(WoH, attnT, bo, out, cs, cs2);
    k_stats<<<256, 256>>>(cs, cs2, meanv, rstdv);
    k_final<<<4096, 1024>>>(out, meanv, rstdv, gamma, beta);
}